// round 1
// baseline (speedup 1.0000x reference)
#include <cuda_runtime.h>
#include <math.h>

// Problem constants
#define B_   4
#define S_   2048
#define DM   1024
#define NH   16
#define DK   64
#define MTOT (B_ * S_)   // 8192

// Scratch (static __device__ arrays: allowed; no runtime allocation)
__device__ float g_Q[B_ * NH * S_ * DK];   // (b,h,s,d)
__device__ float g_K[B_ * NH * S_ * DK];
__device__ float g_V[B_ * NH * S_ * DK];
__device__ float g_AO[MTOT * DM];          // attention output, (b,s,e)

// ---------------------------------------------------------------------------
// SGEMM: C[m,n] = sum_k A[m,k] * W[n,k] + bias[n]
// M=8192, N=1024, K=1024. Block tile 128x128x8, 256 threads, 8x8 per thread.
// QKV=1: scatter output into (b,h,s,d) head-major layout.
// QKV=0: plain row-major [M,N] output.
// ---------------------------------------------------------------------------
template <int QKV>
__global__ __launch_bounds__(256)
void sgemm_kernel(const float* __restrict__ A, const float* __restrict__ W,
                  const float* __restrict__ bias, float* __restrict__ C)
{
    const int K = 1024;
    const int N = 1024;

    __shared__ float As[8][128];
    __shared__ float Bs[8][128];

    const int t  = threadIdx.x;
    const int m0 = blockIdx.y * 128;
    const int n0 = blockIdx.x * 128;

    const int lr = t >> 1;          // 0..127 : row within tile
    const int lc = (t & 1) * 4;     // 0 or 4 : k-offset (float4)

    const float* Ag = A + (size_t)(m0 + lr) * K + lc;
    const float* Wg = W + (size_t)(n0 + lr) * K + lc;

    const int ty = t >> 4;          // 0..15
    const int tx = t & 15;          // 0..15

    float acc[8][8];
#pragma unroll
    for (int i = 0; i < 8; i++)
#pragma unroll
        for (int j = 0; j < 8; j++) acc[i][j] = 0.f;

    for (int k0 = 0; k0 < K; k0 += 8) {
        float4 av = *(const float4*)(Ag + k0);
        float4 wv = *(const float4*)(Wg + k0);

        __syncthreads();   // previous tile fully consumed
        As[lc + 0][lr] = av.x; As[lc + 1][lr] = av.y;
        As[lc + 2][lr] = av.z; As[lc + 3][lr] = av.w;
        Bs[lc + 0][lr] = wv.x; Bs[lc + 1][lr] = wv.y;
        Bs[lc + 2][lr] = wv.z; Bs[lc + 3][lr] = wv.w;
        __syncthreads();

#pragma unroll
        for (int kk = 0; kk < 8; kk++) {
            float4 a0 = *(const float4*)&As[kk][ty * 8];
            float4 a1 = *(const float4*)&As[kk][ty * 8 + 4];
            float4 b0 = *(const float4*)&Bs[kk][tx * 8];
            float4 b1 = *(const float4*)&Bs[kk][tx * 8 + 4];
            float af[8] = {a0.x, a0.y, a0.z, a0.w, a1.x, a1.y, a1.z, a1.w};
            float bf[8] = {b0.x, b0.y, b0.z, b0.w, b1.x, b1.y, b1.z, b1.w};
#pragma unroll
            for (int i = 0; i < 8; i++)
#pragma unroll
                for (int j = 0; j < 8; j++)
                    acc[i][j] = fmaf(af[i], bf[j], acc[i][j]);
        }
    }

    // Epilogue
    const int nbase = n0 + tx * 8;
    float bv[8];
#pragma unroll
    for (int j = 0; j < 8; j++) bv[j] = bias[nbase + j];

#pragma unroll
    for (int i = 0; i < 8; i++) {
        const int m = m0 + ty * 8 + i;
        float4 v0, v1;
        v0.x = acc[i][0] + bv[0]; v0.y = acc[i][1] + bv[1];
        v0.z = acc[i][2] + bv[2]; v0.w = acc[i][3] + bv[3];
        v1.x = acc[i][4] + bv[4]; v1.y = acc[i][5] + bv[5];
        v1.z = acc[i][6] + bv[6]; v1.w = acc[i][7] + bv[7];
        if (QKV) {
            // m = b*S + s ; n = h*64 + d (8 consecutive d within one head)
            const int b = m >> 11;
            const int s = m & (S_ - 1);
            const int h = nbase >> 6;
            const int d = nbase & (DK - 1);
            float* dst = C + ((((size_t)b * NH + h) * S_ + s) * DK + d);
            *(float4*)(dst)     = v0;
            *(float4*)(dst + 4) = v1;
        } else {
            float* dst = C + (size_t)m * N + nbase;
            *(float4*)(dst)     = v0;
            *(float4*)(dst + 4) = v1;
        }
    }
}

// ---------------------------------------------------------------------------
// Flash attention, fp32. One thread per query row, 128 rows per block.
// K/V staged in smem in 64-row chunks; online softmax with deferred rescale.
// ---------------------------------------------------------------------------
__global__ __launch_bounds__(128)
void attn_kernel(const float* __restrict__ Q, const float* __restrict__ Kg,
                 const float* __restrict__ Vg, const int* __restrict__ mask,
                 float* __restrict__ Out)
{
    __shared__ float Ks[64 * 64];
    __shared__ float Vs[64 * 64];
    __shared__ int   msk[64];

    const int tid = threadIdx.x;
    const int bh  = blockIdx.y;              // b*NH + h
    const int b   = bh >> 4;
    const int h   = bh & 15;
    const int m   = blockIdx.x * 128 + tid;  // query row within (b,h)

    const float* qptr = Q + ((size_t)bh * S_ + m) * DK;
    float q[DK];
#pragma unroll
    for (int d4 = 0; d4 < 16; d4++) {
        float4 v = ((const float4*)qptr)[d4];
        q[d4 * 4 + 0] = v.x; q[d4 * 4 + 1] = v.y;
        q[d4 * 4 + 2] = v.z; q[d4 * 4 + 3] = v.w;
    }

    float o[DK];
#pragma unroll
    for (int d = 0; d < DK; d++) o[d] = 0.f;
    float mi = -1e30f;
    float li = 0.f;

    const float* kbase = Kg + (size_t)bh * S_ * DK;
    const float* vbase = Vg + (size_t)bh * S_ * DK;
    const int*   mbase = mask + b * S_;

    for (int j0 = 0; j0 < S_; j0 += 64) {
        __syncthreads();  // previous chunk consumed
        // Load 64x64 K and V chunks (1024 float4 each; 8 per thread)
        const float4* kg4 = (const float4*)(kbase + (size_t)j0 * DK);
        const float4* vg4 = (const float4*)(vbase + (size_t)j0 * DK);
#pragma unroll
        for (int r = 0; r < 8; r++) {
            int idx = tid + r * 128;
            ((float4*)Ks)[idx] = kg4[idx];
            ((float4*)Vs)[idx] = vg4[idx];
        }
        if (tid < 64) msk[tid] = mbase[j0 + tid];
        __syncthreads();

        for (int j = 0; j < 64; j++) {
            const float4* krow = (const float4*)(Ks + j * DK);
            float s0 = 0.f, s1 = 0.f, s2 = 0.f, s3 = 0.f;
#pragma unroll
            for (int d4 = 0; d4 < 16; d4++) {
                float4 kv = krow[d4];
                s0 = fmaf(q[d4 * 4 + 0], kv.x, s0);
                s1 = fmaf(q[d4 * 4 + 1], kv.y, s1);
                s2 = fmaf(q[d4 * 4 + 2], kv.z, s2);
                s3 = fmaf(q[d4 * 4 + 3], kv.w, s3);
            }
            float s = ((s0 + s1) + (s2 + s3)) * 0.125f;  // 1/sqrt(64)
            if (msk[j] == 0) s = -1e9f;

            if (s > mi) {               // rare rescale path
                float c = __expf(mi - s);
                mi = s;
                li *= c;
#pragma unroll
                for (int d = 0; d < DK; d++) o[d] *= c;
            }
            float p = __expf(s - mi);
            li += p;
            const float4* vrow = (const float4*)(Vs + j * DK);
#pragma unroll
            for (int d4 = 0; d4 < 16; d4++) {
                float4 vv = vrow[d4];
                o[d4 * 4 + 0] = fmaf(p, vv.x, o[d4 * 4 + 0]);
                o[d4 * 4 + 1] = fmaf(p, vv.y, o[d4 * 4 + 1]);
                o[d4 * 4 + 2] = fmaf(p, vv.z, o[d4 * 4 + 2]);
                o[d4 * 4 + 3] = fmaf(p, vv.w, o[d4 * 4 + 3]);
            }
        }
    }

    const float inv = 1.f / li;
    float* optr = Out + ((size_t)(b * S_ + m) * DM) + h * DK;
#pragma unroll
    for (int d4 = 0; d4 < 16; d4++) {
        float4 v;
        v.x = o[d4 * 4 + 0] * inv; v.y = o[d4 * 4 + 1] * inv;
        v.z = o[d4 * 4 + 2] * inv; v.w = o[d4 * 4 + 3] * inv;
        ((float4*)optr)[d4] = v;
    }
}

// ---------------------------------------------------------------------------
// Launch
// ---------------------------------------------------------------------------
extern "C" void kernel_launch(void* const* d_in, const int* in_sizes, int n_in,
                              void* d_out, int out_size)
{
    (void)in_sizes; (void)n_in; (void)out_size;
    const float* x    = (const float*)d_in[0];
    const int*   mask = (const int*)  d_in[1];
    const float* Wq   = (const float*)d_in[2];
    const float* bq   = (const float*)d_in[3];
    const float* Wk   = (const float*)d_in[4];
    const float* bk   = (const float*)d_in[5];
    const float* Wv   = (const float*)d_in[6];
    const float* bv   = (const float*)d_in[7];
    const float* Wo   = (const float*)d_in[8];
    const float* bo   = (const float*)d_in[9];
    float* out = (float*)d_out;

    float *Qd, *Kd, *Vd, *AOd;
    cudaGetSymbolAddress((void**)&Qd,  g_Q);
    cudaGetSymbolAddress((void**)&Kd,  g_K);
    cudaGetSymbolAddress((void**)&Vd,  g_V);
    cudaGetSymbolAddress((void**)&AOd, g_AO);

    dim3 gproj(DM / 128, MTOT / 128);   // (8, 64)
    sgemm_kernel<1><<<gproj, 256>>>(x,   Wq, bq, Qd);
    sgemm_kernel<1><<<gproj, 256>>>(x,   Wk, bk, Kd);
    sgemm_kernel<1><<<gproj, 256>>>(x,   Wv, bv, Vd);

    attn_kernel<<<dim3(S_ / 128, B_ * NH), 128>>>(Qd, Kd, Vd, mask, AOd);

    sgemm_kernel<0><<<gproj, 256>>>(AOd, Wo, bo, out);
}

// round 5
// speedup vs baseline: 3.5698x; 3.5698x over previous
#include <cuda_runtime.h>
#include <cuda_bf16.h>
#include <cstdint>
#include <math.h>

#define B_   4
#define S_   2048
#define DM   1024
#define NH   16
#define DK   64
#define MTOT (B_ * S_)   // 8192

typedef __nv_bfloat16 bf16;
typedef __nv_bfloat162 bf162;

// ---------------------------------------------------------------------------
// Scratch
// ---------------------------------------------------------------------------
__device__ bf16 g_xhi[MTOT * DM];
__device__ bf16 g_xlo[MTOT * DM];
__device__ bf16 g_whi[4][DM * DM];
__device__ bf16 g_wlo[4][DM * DM];
__device__ bf16 g_qhi[MTOT * DM];
__device__ bf16 g_qlo[MTOT * DM];
__device__ bf16 g_khi[MTOT * DM];
__device__ bf16 g_klo[MTOT * DM];
__device__ bf16 g_vhi[MTOT * DM];
__device__ bf16 g_vlo[MTOT * DM];
__device__ bf16 g_aohi[MTOT * DM];
__device__ bf16 g_aolo[MTOT * DM];

// ---------------------------------------------------------------------------
// helpers
// ---------------------------------------------------------------------------
__device__ __forceinline__ uint32_t s2u(const void* p) {
    uint32_t a;
    asm("{ .reg .u64 t; cvta.to.shared.u64 t, %1; cvt.u32.u64 %0, t; }"
        : "=r"(a) : "l"(p));
    return a;
}

#define SWZ(x) ((x) ^ (((x) >> 3) & 0x70))

__device__ __forceinline__ void ldsm4(uint32_t* r, uint32_t addr) {
    asm volatile("ldmatrix.sync.aligned.m8n8.x4.shared.b16 {%0,%1,%2,%3}, [%4];"
        : "=r"(r[0]), "=r"(r[1]), "=r"(r[2]), "=r"(r[3]) : "r"(addr));
}
__device__ __forceinline__ void ldsm4t(uint32_t* r, uint32_t addr) {
    asm volatile("ldmatrix.sync.aligned.m8n8.x4.trans.shared.b16 {%0,%1,%2,%3}, [%4];"
        : "=r"(r[0]), "=r"(r[1]), "=r"(r[2]), "=r"(r[3]) : "r"(addr));
}
__device__ __forceinline__ void mma16816(float* c, const uint32_t* a, const uint32_t* b) {
    asm volatile(
        "mma.sync.aligned.m16n8k16.row.col.f32.bf16.bf16.f32 "
        "{%0,%1,%2,%3}, {%4,%5,%6,%7}, {%8,%9}, {%0,%1,%2,%3};"
        : "+f"(c[0]), "+f"(c[1]), "+f"(c[2]), "+f"(c[3])
        : "r"(a[0]), "r"(a[1]), "r"(a[2]), "r"(a[3]), "r"(b[0]), "r"(b[1]));
}

// split v into hi/lo bf16 parts
__device__ __forceinline__ void split2(float v0, float v1, uint32_t& h, uint32_t& l) {
    bf16 h0 = __float2bfloat16(v0), h1 = __float2bfloat16(v1);
    bf16 l0 = __float2bfloat16(v0 - __bfloat162float(h0));
    bf16 l1 = __float2bfloat16(v1 - __bfloat162float(h1));
    bf162 hv = __halves2bfloat162(h0, h1);
    bf162 lv = __halves2bfloat162(l0, l1);
    h = *(uint32_t*)&hv; l = *(uint32_t*)&lv;
}

#define CP16(dst, src) \
    asm volatile("cp.async.cg.shared.global [%0], [%1], 16;" :: "r"(dst), "l"(src))
#define CP_COMMIT() asm volatile("cp.async.commit_group;")
#define CP_WAIT1()  asm volatile("cp.async.wait_group 1;")

// ---------------------------------------------------------------------------
// fp32 -> bf16 hi/lo split
// ---------------------------------------------------------------------------
__global__ __launch_bounds__(256)
void cvt_kernel(const float* __restrict__ in, bf16* __restrict__ hi, bf16* __restrict__ lo)
{
    int i = (blockIdx.x * 256 + threadIdx.x) * 4;
    float4 v = *(const float4*)(in + i);
    uint32_t h0, l0, h1, l1;
    split2(v.x, v.y, h0, l0);
    split2(v.z, v.w, h1, l1);
    ((uint32_t*)(hi + i))[0] = h0; ((uint32_t*)(hi + i))[1] = h1;
    ((uint32_t*)(lo + i))[0] = l0; ((uint32_t*)(lo + i))[1] = l1;
}

// ---------------------------------------------------------------------------
// Split-bf16 GEMM via mma.sync. C[m,n] = sum_k A[m,k]*W[n,k] + bias[n]
// Block 128x128, warp 64x32 (8 warps as 2x4), Kc=64, cp.async double buffer.
// OUT=0: fp32 row-major.  OUT=1: bf16 hi/lo scattered to (b,h,s,d).
// ---------------------------------------------------------------------------
static const int GEMM_SMEM = 2 * 4 * 16384;  // 128KB

template <int OUT>
__global__ __launch_bounds__(256)
void gemm_mma(const bf16* __restrict__ Ahi, const bf16* __restrict__ Alo,
              const bf16* __restrict__ Whi, const bf16* __restrict__ Wlo,
              const float* __restrict__ bias,
              float* __restrict__ Cf, bf16* __restrict__ Chi, bf16* __restrict__ Clo)
{
    extern __shared__ __align__(1024) char smem[];
    const int K = 1024;
    const int tid = threadIdx.x;
    const int wid = tid >> 5;
    const int lid = tid & 31;
    const int m0 = blockIdx.y * 128;
    const int n0 = blockIdx.x * 128;
    const int wm = wid & 1;        // 0..1 (64-row slice)
    const int wn = wid >> 1;       // 0..3 (32-col slice)

    const uint32_t sb = s2u(smem);

    // stage fill: 4 tiles x 1024 16B units; per thread 16 units
    auto load_stage = [&](int kc, int buf) {
        const bf16* srcs[4] = {Ahi + (size_t)m0 * K + kc * 64,
                               Alo + (size_t)m0 * K + kc * 64,
                               Whi + (size_t)n0 * K + kc * 64,
                               Wlo + (size_t)n0 * K + kc * 64};
        const uint32_t bufo = buf * 65536;
#pragma unroll
        for (int t = 0; t < 4; t++) {
#pragma unroll
            for (int it = 0; it < 4; it++) {
                const int idx = tid + it * 256;         // 0..1023
                const int row = idx >> 3;
                const int u = idx & 7;
                const uint32_t dst = sb + bufo + t * 16384 + SWZ(idx * 16);
                const bf16* src = srcs[t] + (size_t)row * K + u * 8;
                CP16(dst, src);
            }
        }
    };

    float acc[4][4][4];
#pragma unroll
    for (int a = 0; a < 4; a++)
#pragma unroll
        for (int b = 0; b < 4; b++)
#pragma unroll
            for (int c = 0; c < 4; c++) acc[a][b][c] = 0.f;

    load_stage(0, 0); CP_COMMIT();
    load_stage(1, 1); CP_COMMIT();

    for (int kc = 0; kc < 16; kc++) {
        CP_WAIT1();
        __syncthreads();
        const uint32_t bufo = sb + (kc & 1) * 65536;

#pragma unroll
        for (int ks = 0; ks < 4; ks++) {
            uint32_t ah[4][4], al[4][4];
#pragma unroll
            for (int mf = 0; mf < 4; mf++) {
                const int row = wm * 64 + mf * 16 + (lid & 15);
                const int u = ks * 2 + (lid >> 4);
                const uint32_t off = SWZ(row * 128 + u * 16);
                ldsm4(ah[mf], bufo + off);
                ldsm4(al[mf], bufo + 16384 + off);
            }
#pragma unroll
            for (int nf2 = 0; nf2 < 2; nf2++) {
                const int row = wn * 32 + nf2 * 16 + ((lid >> 4) << 3) + (lid & 7);
                const int u = ks * 2 + ((lid >> 3) & 1);
                const uint32_t off = SWZ(row * 128 + u * 16);
                uint32_t bh[4], bl[4];
                ldsm4(bh, bufo + 32768 + off);
                ldsm4(bl, bufo + 49152 + off);
#pragma unroll
                for (int mf = 0; mf < 4; mf++) {
                    mma16816(acc[mf][nf2 * 2],     ah[mf], bh);
                    mma16816(acc[mf][nf2 * 2],     ah[mf], bl);
                    mma16816(acc[mf][nf2 * 2],     al[mf], bh);
                    mma16816(acc[mf][nf2 * 2 + 1], ah[mf], bh + 2);
                    mma16816(acc[mf][nf2 * 2 + 1], ah[mf], bl + 2);
                    mma16816(acc[mf][nf2 * 2 + 1], al[mf], bh + 2);
                }
            }
        }
        __syncthreads();
        if (kc + 2 < 16) load_stage(kc + 2, kc & 1);
        CP_COMMIT();
    }

    // epilogue
#pragma unroll
    for (int mf = 0; mf < 4; mf++) {
#pragma unroll
        for (int nf = 0; nf < 4; nf++) {
            const int n = n0 + wn * 32 + nf * 8 + (lid & 3) * 2;
            const int r0 = m0 + wm * 64 + mf * 16 + (lid >> 2);
            const int r1 = r0 + 8;
            const float b0 = bias[n], b1 = bias[n + 1];
            float v00 = acc[mf][nf][0] + b0, v01 = acc[mf][nf][1] + b1;
            float v10 = acc[mf][nf][2] + b0, v11 = acc[mf][nf][3] + b1;
            if (OUT == 0) {
                float2* p0 = (float2*)(Cf + (size_t)r0 * 1024 + n);
                float2* p1 = (float2*)(Cf + (size_t)r1 * 1024 + n);
                *p0 = make_float2(v00, v01);
                *p1 = make_float2(v10, v11);
            } else {
                const int h = n >> 6, d = n & 63;
#pragma unroll
                for (int rr = 0; rr < 2; rr++) {
                    const int r = rr ? r1 : r0;
                    const int b = r >> 11, s = r & (S_ - 1);
                    const size_t idx = ((((size_t)b * NH + h) * S_ + s) * DK) + d;
                    uint32_t hv, lv;
                    split2(rr ? v10 : v00, rr ? v11 : v01, hv, lv);
                    *(uint32_t*)(Chi + idx) = hv;
                    *(uint32_t*)(Clo + idx) = lv;
                }
            }
        }
    }
}

// ---------------------------------------------------------------------------
// Flash attention with mma.sync split-bf16.
// Block: 256 thr (8 warps), 128 queries (16/warp). Key chunks of 128,
// scored in two 64-key halves. Q pre-scaled by 1/8 (exact).
// ---------------------------------------------------------------------------
static const int ATTN_SMEM = 4 * 16384 + 512;

__global__ __launch_bounds__(256)
void attn_mma(const bf16* __restrict__ Qhi, const bf16* __restrict__ Qlo,
              const bf16* __restrict__ Khi, const bf16* __restrict__ Klo,
              const bf16* __restrict__ Vhi, const bf16* __restrict__ Vlo,
              const int* __restrict__ mask,
              bf16* __restrict__ AOhi, bf16* __restrict__ AOlo)
{
    extern __shared__ __align__(1024) char smem[];
    const uint32_t sb = s2u(smem);
    const uint32_t sK = sb, sKl = sb + 16384, sV = sb + 32768, sVl = sb + 49152;
    float* maskadd = (float*)(smem + 65536);

    const int tid = threadIdx.x;
    const int wid = tid >> 5;
    const int lid = tid & 31;
    const int bh = blockIdx.y;
    const int b = bh >> 4, h = bh & 15;
    const int q0 = blockIdx.x * 128 + wid * 16;

    const size_t bho = (size_t)bh * S_ * DK;

    // Q fragments (pre-scaled by 0.125 via bf16x2 multiply: exact)
    uint32_t qh[4][4], ql[4][4];
    const uint32_t eighth = 0x3E003E00u;  // bf16 0.125 x2
#pragma unroll
    for (int ks = 0; ks < 4; ks++) {
        const int c2 = ks * 16 + (lid & 3) * 2;
        const int r0 = q0 + (lid >> 2), r1 = r0 + 8;
        const uint32_t* qhp = (const uint32_t*)(Qhi + bho);
        const uint32_t* qlp = (const uint32_t*)(Qlo + bho);
        uint32_t a0 = qhp[(r0 * DK + c2) >> 1];
        uint32_t a1 = qhp[(r1 * DK + c2) >> 1];
        uint32_t a2 = qhp[(r0 * DK + c2 + 8) >> 1];
        uint32_t a3 = qhp[(r1 * DK + c2 + 8) >> 1];
        uint32_t b0 = qlp[(r0 * DK + c2) >> 1];
        uint32_t b1 = qlp[(r1 * DK + c2) >> 1];
        uint32_t b2 = qlp[(r0 * DK + c2 + 8) >> 1];
        uint32_t b3 = qlp[(r1 * DK + c2 + 8) >> 1];
        asm("mul.rn.bf16x2 %0, %1, %2;" : "=r"(qh[ks][0]) : "r"(a0), "r"(eighth));
        asm("mul.rn.bf16x2 %0, %1, %2;" : "=r"(qh[ks][1]) : "r"(a1), "r"(eighth));
        asm("mul.rn.bf16x2 %0, %1, %2;" : "=r"(qh[ks][2]) : "r"(a2), "r"(eighth));
        asm("mul.rn.bf16x2 %0, %1, %2;" : "=r"(qh[ks][3]) : "r"(a3), "r"(eighth));
        asm("mul.rn.bf16x2 %0, %1, %2;" : "=r"(ql[ks][0]) : "r"(b0), "r"(eighth));
        asm("mul.rn.bf16x2 %0, %1, %2;" : "=r"(ql[ks][1]) : "r"(b1), "r"(eighth));
        asm("mul.rn.bf16x2 %0, %1, %2;" : "=r"(ql[ks][2]) : "r"(b2), "r"(eighth));
        asm("mul.rn.bf16x2 %0, %1, %2;" : "=r"(ql[ks][3]) : "r"(b3), "r"(eighth));
    }

    float o[8][4];
#pragma unroll
    for (int j = 0; j < 8; j++)
#pragma unroll
        for (int c = 0; c < 4; c++) o[j][c] = 0.f;
    float mA = -1e30f, mB = -1e30f, lA = 0.f, lB = 0.f;

    for (int ch = 0; ch < 16; ch++) {
        __syncthreads();
        {
            const uint4* k4h = (const uint4*)(Khi + bho + ch * 128 * DK);
            const uint4* k4l = (const uint4*)(Klo + bho + ch * 128 * DK);
            const uint4* v4h = (const uint4*)(Vhi + bho + ch * 128 * DK);
            const uint4* v4l = (const uint4*)(Vlo + bho + ch * 128 * DK);
#pragma unroll
            for (int it = 0; it < 4; it++) {
                const int idx = tid + it * 256;
                const uint32_t sw = SWZ(idx * 16);
                *(uint4*)(smem + (sK - sb) + sw)  = k4h[idx];
                *(uint4*)(smem + (sKl - sb) + sw) = k4l[idx];
                *(uint4*)(smem + (sV - sb) + sw)  = v4h[idx];
                *(uint4*)(smem + (sVl - sb) + sw) = v4l[idx];
            }
            if (tid < 128)
                maskadd[tid] = mask[b * S_ + ch * 128 + tid] ? 0.f : -1e9f;
        }
        __syncthreads();

#pragma unroll
        for (int sub = 0; sub < 2; sub++) {
            float sc[8][4];
#pragma unroll
            for (int nf = 0; nf < 8; nf++)
#pragma unroll
                for (int c = 0; c < 4; c++) sc[nf][c] = 0.f;

            // scores: Q (16xk64) . K^T
#pragma unroll
            for (int nf2 = 0; nf2 < 4; nf2++) {
                const int row = sub * 64 + nf2 * 16 + ((lid >> 4) << 3) + (lid & 7);
#pragma unroll
                for (int ks = 0; ks < 4; ks++) {
                    const int u = ks * 2 + ((lid >> 3) & 1);
                    const uint32_t off = SWZ(row * 128 + u * 16);
                    uint32_t kb[4], kl[4];
                    ldsm4(kb, sK + off);
                    ldsm4(kl, sKl + off);
                    mma16816(sc[nf2 * 2],     qh[ks], kb);
                    mma16816(sc[nf2 * 2],     qh[ks], kl);
                    mma16816(sc[nf2 * 2],     ql[ks], kb);
                    mma16816(sc[nf2 * 2 + 1], qh[ks], kb + 2);
                    mma16816(sc[nf2 * 2 + 1], qh[ks], kl + 2);
                    mma16816(sc[nf2 * 2 + 1], ql[ks], kb + 2);
                }
            }

            // mask
#pragma unroll
            for (int nf = 0; nf < 8; nf++) {
                const int k0 = sub * 64 + nf * 8 + (lid & 3) * 2;
                const float ma0 = maskadd[k0], ma1 = maskadd[k0 + 1];
                sc[nf][0] += ma0; sc[nf][1] += ma1;
                sc[nf][2] += ma0; sc[nf][3] += ma1;
            }

            // online softmax
            float mxA = -1e30f, mxB = -1e30f;
#pragma unroll
            for (int nf = 0; nf < 8; nf++) {
                mxA = fmaxf(mxA, fmaxf(sc[nf][0], sc[nf][1]));
                mxB = fmaxf(mxB, fmaxf(sc[nf][2], sc[nf][3]));
            }
            mxA = fmaxf(mxA, __shfl_xor_sync(0xffffffffu, mxA, 1));
            mxA = fmaxf(mxA, __shfl_xor_sync(0xffffffffu, mxA, 2));
            mxB = fmaxf(mxB, __shfl_xor_sync(0xffffffffu, mxB, 1));
            mxB = fmaxf(mxB, __shfl_xor_sync(0xffffffffu, mxB, 2));
            const float mAn = fmaxf(mA, mxA), mBn = fmaxf(mB, mxB);
            const float fA = __expf(mA - mAn), fB = __expf(mB - mBn);
            mA = mAn; mB = mBn;
            lA *= fA; lB *= fB;
#pragma unroll
            for (int j = 0; j < 8; j++) {
                o[j][0] *= fA; o[j][1] *= fA;
                o[j][2] *= fB; o[j][3] *= fB;
            }
#pragma unroll
            for (int nf = 0; nf < 8; nf++) {
                sc[nf][0] = __expf(sc[nf][0] - mA);
                sc[nf][1] = __expf(sc[nf][1] - mA);
                sc[nf][2] = __expf(sc[nf][2] - mB);
                sc[nf][3] = __expf(sc[nf][3] - mB);
                lA += sc[nf][0] + sc[nf][1];
                lB += sc[nf][2] + sc[nf][3];
            }

            // P·V  (P frags built in-register from score frags)
#pragma unroll
            for (int kk = 0; kk < 4; kk++) {
                uint32_t ph[4], pl[4];
                split2(sc[2 * kk][0],     sc[2 * kk][1],     ph[0], pl[0]);
                split2(sc[2 * kk][2],     sc[2 * kk][3],     ph[1], pl[1]);
                split2(sc[2 * kk + 1][0], sc[2 * kk + 1][1], ph[2], pl[2]);
                split2(sc[2 * kk + 1][2], sc[2 * kk + 1][3], ph[3], pl[3]);
                const int row = sub * 64 + kk * 16 + (((lid >> 3) & 1) << 3) + (lid & 7);
#pragma unroll
                for (int j2 = 0; j2 < 4; j2++) {
                    const int u = 2 * j2 + (lid >> 4);
                    const uint32_t off = SWZ(row * 128 + u * 16);
                    uint32_t vb[4], vl[4];
                    ldsm4t(vb, sV + off);
                    ldsm4t(vl, sVl + off);
                    mma16816(o[j2 * 2],     ph, vb);
                    mma16816(o[j2 * 2],     ph, vl);
                    mma16816(o[j2 * 2],     pl, vb);
                    mma16816(o[j2 * 2 + 1], ph, vb + 2);
                    mma16816(o[j2 * 2 + 1], ph, vl + 2);
                    mma16816(o[j2 * 2 + 1], pl, vb + 2);
                }
            }
        }
    }

    // final row sums and store
    lA += __shfl_xor_sync(0xffffffffu, lA, 1);
    lA += __shfl_xor_sync(0xffffffffu, lA, 2);
    lB += __shfl_xor_sync(0xffffffffu, lB, 1);
    lB += __shfl_xor_sync(0xffffffffu, lB, 2);
    const float invA = 1.f / lA, invB = 1.f / lB;

    const int s0 = q0 + (lid >> 2), s1 = s0 + 8;
#pragma unroll
    for (int j = 0; j < 8; j++) {
        const int col = h * DK + j * 8 + (lid & 3) * 2;
        const size_t i0 = ((size_t)(b * S_ + s0)) * DM + col;
        const size_t i1 = ((size_t)(b * S_ + s1)) * DM + col;
        uint32_t hv, lv;
        split2(o[j][0] * invA, o[j][1] * invA, hv, lv);
        *(uint32_t*)(AOhi + i0) = hv;
        *(uint32_t*)(AOlo + i0) = lv;
        split2(o[j][2] * invB, o[j][3] * invB, hv, lv);
        *(uint32_t*)(AOhi + i1) = hv;
        *(uint32_t*)(AOlo + i1) = lv;
    }
}

// ---------------------------------------------------------------------------
// Launch
// ---------------------------------------------------------------------------
extern "C" void kernel_launch(void* const* d_in, const int* in_sizes, int n_in,
                              void* d_out, int out_size)
{
    (void)in_sizes; (void)n_in; (void)out_size;
    const float* x    = (const float*)d_in[0];
    const int*   mask = (const int*)  d_in[1];
    const float* Wq   = (const float*)d_in[2];
    const float* bq   = (const float*)d_in[3];
    const float* Wk   = (const float*)d_in[4];
    const float* bk   = (const float*)d_in[5];
    const float* Wv   = (const float*)d_in[6];
    const float* bv   = (const float*)d_in[7];
    const float* Wo   = (const float*)d_in[8];
    const float* bo   = (const float*)d_in[9];
    float* out = (float*)d_out;

    bf16 *xhi, *xlo, *whi, *wlo, *qhi, *qlo, *khi, *klo, *vhi, *vlo, *aohi, *aolo;
    cudaGetSymbolAddress((void**)&xhi,  g_xhi);
    cudaGetSymbolAddress((void**)&xlo,  g_xlo);
    cudaGetSymbolAddress((void**)&whi,  g_whi);
    cudaGetSymbolAddress((void**)&wlo,  g_wlo);
    cudaGetSymbolAddress((void**)&qhi,  g_qhi);
    cudaGetSymbolAddress((void**)&qlo,  g_qlo);
    cudaGetSymbolAddress((void**)&khi,  g_khi);
    cudaGetSymbolAddress((void**)&klo,  g_klo);
    cudaGetSymbolAddress((void**)&vhi,  g_vhi);
    cudaGetSymbolAddress((void**)&vlo,  g_vlo);
    cudaGetSymbolAddress((void**)&aohi, g_aohi);
    cudaGetSymbolAddress((void**)&aolo, g_aolo);

    cudaFuncSetAttribute(gemm_mma<0>, cudaFuncAttributeMaxDynamicSharedMemorySize, GEMM_SMEM);
    cudaFuncSetAttribute(gemm_mma<1>, cudaFuncAttributeMaxDynamicSharedMemorySize, GEMM_SMEM);
    cudaFuncSetAttribute(attn_mma,    cudaFuncAttributeMaxDynamicSharedMemorySize, ATTN_SMEM);

    cvt_kernel<<<MTOT * DM / 1024, 256>>>(x, xhi, xlo);
    cvt_kernel<<<DM * DM / 1024, 256>>>(Wq, whi + 0 * DM * DM, wlo + 0 * DM * DM);
    cvt_kernel<<<DM * DM / 1024, 256>>>(Wk, whi + 1 * DM * DM, wlo + 1 * DM * DM);
    cvt_kernel<<<DM * DM / 1024, 256>>>(Wv, whi + 2 * DM * DM, wlo + 2 * DM * DM);
    cvt_kernel<<<DM * DM / 1024, 256>>>(Wo, whi + 3 * DM * DM, wlo + 3 * DM * DM);

    dim3 g(DM / 128, MTOT / 128);   // (8, 64)
    gemm_mma<1><<<g, 256, GEMM_SMEM>>>(xhi, xlo, whi + 0 * DM * DM, wlo + 0 * DM * DM, bq, nullptr, qhi, qlo);
    gemm_mma<1><<<g, 256, GEMM_SMEM>>>(xhi, xlo, whi + 1 * DM * DM, wlo + 1 * DM * DM, bk, nullptr, khi, klo);
    gemm_mma<1><<<g, 256, GEMM_SMEM>>>(xhi, xlo, whi + 2 * DM * DM, wlo + 2 * DM * DM, bv, nullptr, vhi, vlo);

    attn_mma<<<dim3(S_ / 128, B_ * NH), 256, ATTN_SMEM>>>(qhi, qlo, khi, klo, vhi, vlo,
                                                          mask, aohi, aolo);

    gemm_mma<0><<<g, 256, GEMM_SMEM>>>(aohi, aolo, whi + 3 * DM * DM, wlo + 3 * DM * DM, bo, out, nullptr, nullptr);
}

// round 6
// speedup vs baseline: 3.6581x; 1.0247x over previous
#include <cuda_runtime.h>
#include <cuda_bf16.h>
#include <cstdint>
#include <math.h>

#define B_   4
#define S_   2048
#define DM   1024
#define NH   16
#define DK   64
#define MTOT (B_ * S_)   // 8192

#define LOG2E 1.4426950408889634f

typedef __nv_bfloat16 bf16;
typedef __nv_bfloat162 bf162;

// ---------------------------------------------------------------------------
// Scratch
// ---------------------------------------------------------------------------
__device__ bf16 g_xhi[MTOT * DM];
__device__ bf16 g_xlo[MTOT * DM];
__device__ bf16 g_whi[4][DM * DM];
__device__ bf16 g_wlo[4][DM * DM];
__device__ bf16 g_qhi[MTOT * DM];
__device__ bf16 g_qlo[MTOT * DM];
__device__ bf16 g_khi[MTOT * DM];
__device__ bf16 g_klo[MTOT * DM];
__device__ bf16 g_vhi[MTOT * DM];
__device__ bf16 g_vlo[MTOT * DM];
__device__ bf16 g_aohi[MTOT * DM];
__device__ bf16 g_aolo[MTOT * DM];

// ---------------------------------------------------------------------------
// helpers
// ---------------------------------------------------------------------------
__device__ __forceinline__ uint32_t s2u(const void* p) {
    uint32_t a;
    asm("{ .reg .u64 t; cvta.to.shared.u64 t, %1; cvt.u32.u64 %0, t; }"
        : "=r"(a) : "l"(p));
    return a;
}

#define SWZ(x) ((x) ^ (((x) >> 3) & 0x70))

__device__ __forceinline__ void ldsm4(uint32_t* r, uint32_t addr) {
    asm volatile("ldmatrix.sync.aligned.m8n8.x4.shared.b16 {%0,%1,%2,%3}, [%4];"
        : "=r"(r[0]), "=r"(r[1]), "=r"(r[2]), "=r"(r[3]) : "r"(addr));
}
__device__ __forceinline__ void ldsm4t(uint32_t* r, uint32_t addr) {
    asm volatile("ldmatrix.sync.aligned.m8n8.x4.trans.shared.b16 {%0,%1,%2,%3}, [%4];"
        : "=r"(r[0]), "=r"(r[1]), "=r"(r[2]), "=r"(r[3]) : "r"(addr));
}
__device__ __forceinline__ void mma16816(float* c, const uint32_t* a, const uint32_t* b) {
    asm volatile(
        "mma.sync.aligned.m16n8k16.row.col.f32.bf16.bf16.f32 "
        "{%0,%1,%2,%3}, {%4,%5,%6,%7}, {%8,%9}, {%0,%1,%2,%3};"
        : "+f"(c[0]), "+f"(c[1]), "+f"(c[2]), "+f"(c[3])
        : "r"(a[0]), "r"(a[1]), "r"(a[2]), "r"(a[3]), "r"(b[0]), "r"(b[1]));
}

// split v into hi/lo bf16 parts
__device__ __forceinline__ void split2(float v0, float v1, uint32_t& h, uint32_t& l) {
    bf16 h0 = __float2bfloat16(v0), h1 = __float2bfloat16(v1);
    bf16 l0 = __float2bfloat16(v0 - __bfloat162float(h0));
    bf16 l1 = __float2bfloat16(v1 - __bfloat162float(h1));
    bf162 hv = __halves2bfloat162(h0, h1);
    bf162 lv = __halves2bfloat162(l0, l1);
    h = *(uint32_t*)&hv; l = *(uint32_t*)&lv;
}

#define CP16(dst, src) \
    asm volatile("cp.async.cg.shared.global [%0], [%1], 16;" :: "r"(dst), "l"(src))
#define CP4(dst, src) \
    asm volatile("cp.async.ca.shared.global [%0], [%1], 4;" :: "r"(dst), "l"(src))
#define CP_COMMIT() asm volatile("cp.async.commit_group;")
#define CP_WAIT1()  asm volatile("cp.async.wait_group 1;")
#define CP_WAIT2()  asm volatile("cp.async.wait_group 2;")

// ---------------------------------------------------------------------------
// fp32 -> bf16 hi/lo split
// ---------------------------------------------------------------------------
__global__ __launch_bounds__(256)
void cvt_kernel(const float* __restrict__ in, bf16* __restrict__ hi, bf16* __restrict__ lo)
{
    int i = (blockIdx.x * 256 + threadIdx.x) * 4;
    float4 v = *(const float4*)(in + i);
    uint32_t h0, l0, h1, l1;
    split2(v.x, v.y, h0, l0);
    split2(v.z, v.w, h1, l1);
    ((uint32_t*)(hi + i))[0] = h0; ((uint32_t*)(hi + i))[1] = h1;
    ((uint32_t*)(lo + i))[0] = l0; ((uint32_t*)(lo + i))[1] = l1;
}

// ---------------------------------------------------------------------------
// Split-bf16 GEMM via mma.sync. C[m,n] = sum_k A[m,k]*W[n,k] + bias[n]
// Block 128x128, warp 64x32 (8 warps as 2x4), Kc=64, 3-stage cp.async.
// OUT=0: fp32 row-major.  OUT=1: bf16 hi/lo scattered to (b,h,s,d).
// ---------------------------------------------------------------------------
static const int GEMM_SMEM = 3 * 4 * 16384;  // 192KB

template <int OUT>
__global__ __launch_bounds__(256)
void gemm_mma(const bf16* __restrict__ Ahi, const bf16* __restrict__ Alo,
              const bf16* __restrict__ Whi, const bf16* __restrict__ Wlo,
              const float* __restrict__ bias,
              float* __restrict__ Cf, bf16* __restrict__ Chi, bf16* __restrict__ Clo)
{
    extern __shared__ __align__(1024) char smem[];
    const int K = 1024;
    const int tid = threadIdx.x;
    const int wid = tid >> 5;
    const int lid = tid & 31;
    const int m0 = blockIdx.y * 128;
    const int n0 = blockIdx.x * 128;
    const int wm = wid & 1;        // 0..1 (64-row slice)
    const int wn = wid >> 1;       // 0..3 (32-col slice)

    const uint32_t sb = s2u(smem);

    // stage fill: 4 tiles x 1024 16B units; per thread 16 units
    auto load_stage = [&](int kc, int buf) {
        const bf16* srcs[4] = {Ahi + (size_t)m0 * K + kc * 64,
                               Alo + (size_t)m0 * K + kc * 64,
                               Whi + (size_t)n0 * K + kc * 64,
                               Wlo + (size_t)n0 * K + kc * 64};
        const uint32_t bufo = buf * 65536;
#pragma unroll
        for (int t = 0; t < 4; t++) {
#pragma unroll
            for (int it = 0; it < 4; it++) {
                const int idx = tid + it * 256;         // 0..1023
                const int row = idx >> 3;
                const int u = idx & 7;
                const uint32_t dst = sb + bufo + t * 16384 + SWZ(idx * 16);
                const bf16* src = srcs[t] + (size_t)row * K + u * 8;
                CP16(dst, src);
            }
        }
    };

    float acc[4][4][4];
#pragma unroll
    for (int a = 0; a < 4; a++)
#pragma unroll
        for (int b = 0; b < 4; b++)
#pragma unroll
            for (int c = 0; c < 4; c++) acc[a][b][c] = 0.f;

    load_stage(0, 0); CP_COMMIT();
    load_stage(1, 1); CP_COMMIT();
    load_stage(2, 2); CP_COMMIT();

    for (int kc = 0; kc < 16; kc++) {
        CP_WAIT2();
        __syncthreads();
        const int bi = kc % 3;
        const uint32_t bufo = sb + bi * 65536;

#pragma unroll
        for (int ks = 0; ks < 4; ks++) {
            uint32_t ah[4][4], al[4][4];
#pragma unroll
            for (int mf = 0; mf < 4; mf++) {
                const int row = wm * 64 + mf * 16 + (lid & 15);
                const int u = ks * 2 + (lid >> 4);
                const uint32_t off = SWZ(row * 128 + u * 16);
                ldsm4(ah[mf], bufo + off);
                ldsm4(al[mf], bufo + 16384 + off);
            }
#pragma unroll
            for (int nf2 = 0; nf2 < 2; nf2++) {
                const int row = wn * 32 + nf2 * 16 + ((lid >> 4) << 3) + (lid & 7);
                const int u = ks * 2 + ((lid >> 3) & 1);
                const uint32_t off = SWZ(row * 128 + u * 16);
                uint32_t bh[4], bl[4];
                ldsm4(bh, bufo + 32768 + off);
                ldsm4(bl, bufo + 49152 + off);
#pragma unroll
                for (int mf = 0; mf < 4; mf++) {
                    mma16816(acc[mf][nf2 * 2],     ah[mf], bh);
                    mma16816(acc[mf][nf2 * 2],     ah[mf], bl);
                    mma16816(acc[mf][nf2 * 2],     al[mf], bh);
                    mma16816(acc[mf][nf2 * 2 + 1], ah[mf], bh + 2);
                    mma16816(acc[mf][nf2 * 2 + 1], ah[mf], bl + 2);
                    mma16816(acc[mf][nf2 * 2 + 1], al[mf], bh + 2);
                }
            }
        }
        __syncthreads();
        if (kc + 3 < 16) load_stage(kc + 3, bi);
        CP_COMMIT();
    }

    // epilogue
#pragma unroll
    for (int mf = 0; mf < 4; mf++) {
#pragma unroll
        for (int nf = 0; nf < 4; nf++) {
            const int n = n0 + wn * 32 + nf * 8 + (lid & 3) * 2;
            const int r0 = m0 + wm * 64 + mf * 16 + (lid >> 2);
            const int r1 = r0 + 8;
            const float b0 = bias[n], b1 = bias[n + 1];
            float v00 = acc[mf][nf][0] + b0, v01 = acc[mf][nf][1] + b1;
            float v10 = acc[mf][nf][2] + b0, v11 = acc[mf][nf][3] + b1;
            if (OUT == 0) {
                float2* p0 = (float2*)(Cf + (size_t)r0 * 1024 + n);
                float2* p1 = (float2*)(Cf + (size_t)r1 * 1024 + n);
                *p0 = make_float2(v00, v01);
                *p1 = make_float2(v10, v11);
            } else {
                const int h = n >> 6, d = n & 63;
#pragma unroll
                for (int rr = 0; rr < 2; rr++) {
                    const int r = rr ? r1 : r0;
                    const int b = r >> 11, s = r & (S_ - 1);
                    const size_t idx = ((((size_t)b * NH + h) * S_ + s) * DK) + d;
                    uint32_t hv, lv;
                    split2(rr ? v10 : v00, rr ? v11 : v01, hv, lv);
                    *(uint32_t*)(Chi + idx) = hv;
                    *(uint32_t*)(Clo + idx) = lv;
                }
            }
        }
    }
}

// ---------------------------------------------------------------------------
// Flash attention with mma.sync split-bf16, cp.async double-buffered KV.
// Block: 256 thr (8 warps), 128 queries (16/warp). Key chunks of 128,
// scored in two 64-key halves. Q pre-scaled by 1/8 (exact); softmax in
// log2 domain (log2e folded into the mask FMA, exp2f for probabilities).
// ---------------------------------------------------------------------------
// Per-buffer layout: K(16K) Kl(16K) V(16K) Vl(16K) msk(512B) = 66048 B
static const int ATTN_BUF  = 66048;
static const int ATTN_SMEM = 2 * ATTN_BUF;

__global__ __launch_bounds__(256)
void attn_mma(const bf16* __restrict__ Qhi, const bf16* __restrict__ Qlo,
              const bf16* __restrict__ Khi, const bf16* __restrict__ Klo,
              const bf16* __restrict__ Vhi, const bf16* __restrict__ Vlo,
              const int* __restrict__ mask,
              bf16* __restrict__ AOhi, bf16* __restrict__ AOlo)
{
    extern __shared__ __align__(1024) char smem[];
    const uint32_t sb = s2u(smem);

    const int tid = threadIdx.x;
    const int wid = tid >> 5;
    const int lid = tid & 31;
    const int bh = blockIdx.y;
    const int b = bh >> 4, h = bh & 15;
    const int q0 = blockIdx.x * 128 + wid * 16;

    const size_t bho = (size_t)bh * S_ * DK;

    auto load_chunk = [&](int ch, int buf) {
        const uint32_t bo = sb + buf * ATTN_BUF;
        const char* kh = (const char*)(Khi + bho + (size_t)ch * 128 * DK);
        const char* kl = (const char*)(Klo + bho + (size_t)ch * 128 * DK);
        const char* vh = (const char*)(Vhi + bho + (size_t)ch * 128 * DK);
        const char* vl = (const char*)(Vlo + bho + (size_t)ch * 128 * DK);
#pragma unroll
        for (int it = 0; it < 4; it++) {
            const int idx = tid + it * 256;
            const uint32_t sw = SWZ(idx * 16);
            CP16(bo + sw,         kh + idx * 16);
            CP16(bo + 16384 + sw, kl + idx * 16);
            CP16(bo + 32768 + sw, vh + idx * 16);
            CP16(bo + 49152 + sw, vl + idx * 16);
        }
        if (tid < 128)
            CP4(bo + 65536 + tid * 4, mask + b * S_ + ch * 128 + tid);
    };

    // Q fragments (pre-scaled by 0.125 via bf16x2 multiply: exact)
    uint32_t qh[4][4], ql[4][4];
    const uint32_t eighth = 0x3E003E00u;  // bf16 0.125 x2
#pragma unroll
    for (int ks = 0; ks < 4; ks++) {
        const int c2 = ks * 16 + (lid & 3) * 2;
        const int r0 = q0 + (lid >> 2), r1 = r0 + 8;
        const uint32_t* qhp = (const uint32_t*)(Qhi + bho);
        const uint32_t* qlp = (const uint32_t*)(Qlo + bho);
        uint32_t a0 = qhp[(r0 * DK + c2) >> 1];
        uint32_t a1 = qhp[(r1 * DK + c2) >> 1];
        uint32_t a2 = qhp[(r0 * DK + c2 + 8) >> 1];
        uint32_t a3 = qhp[(r1 * DK + c2 + 8) >> 1];
        uint32_t b0 = qlp[(r0 * DK + c2) >> 1];
        uint32_t b1 = qlp[(r1 * DK + c2) >> 1];
        uint32_t b2 = qlp[(r0 * DK + c2 + 8) >> 1];
        uint32_t b3 = qlp[(r1 * DK + c2 + 8) >> 1];
        asm("mul.rn.bf16x2 %0, %1, %2;" : "=r"(qh[ks][0]) : "r"(a0), "r"(eighth));
        asm("mul.rn.bf16x2 %0, %1, %2;" : "=r"(qh[ks][1]) : "r"(a1), "r"(eighth));
        asm("mul.rn.bf16x2 %0, %1, %2;" : "=r"(qh[ks][2]) : "r"(a2), "r"(eighth));
        asm("mul.rn.bf16x2 %0, %1, %2;" : "=r"(qh[ks][3]) : "r"(a3), "r"(eighth));
        asm("mul.rn.bf16x2 %0, %1, %2;" : "=r"(ql[ks][0]) : "r"(b0), "r"(eighth));
        asm("mul.rn.bf16x2 %0, %1, %2;" : "=r"(ql[ks][1]) : "r"(b1), "r"(eighth));
        asm("mul.rn.bf16x2 %0, %1, %2;" : "=r"(ql[ks][2]) : "r"(b2), "r"(eighth));
        asm("mul.rn.bf16x2 %0, %1, %2;" : "=r"(ql[ks][3]) : "r"(b3), "r"(eighth));
    }

    float o[8][4];
#pragma unroll
    for (int j = 0; j < 8; j++)
#pragma unroll
        for (int c = 0; c < 4; c++) o[j][c] = 0.f;
    float mA = -1e30f, mB = -1e30f, lA = 0.f, lB = 0.f;

    load_chunk(0, 0); CP_COMMIT();
    load_chunk(1, 1); CP_COMMIT();

    for (int ch = 0; ch < 16; ch++) {
        CP_WAIT1();
        __syncthreads();
        const int bi = ch & 1;
        const uint32_t sK  = sb + bi * ATTN_BUF;
        const uint32_t sKl = sK + 16384;
        const uint32_t sV  = sK + 32768;
        const uint32_t sVl = sK + 49152;
        const int* msk = (const int*)(smem + bi * ATTN_BUF + 65536);

#pragma unroll
        for (int sub = 0; sub < 2; sub++) {
            float sc[8][4];
#pragma unroll
            for (int nf = 0; nf < 8; nf++)
#pragma unroll
                for (int c = 0; c < 4; c++) sc[nf][c] = 0.f;

            // scores: Q (16xk64) . K^T
#pragma unroll
            for (int nf2 = 0; nf2 < 4; nf2++) {
                const int row = sub * 64 + nf2 * 16 + ((lid >> 4) << 3) + (lid & 7);
#pragma unroll
                for (int ks = 0; ks < 4; ks++) {
                    const int u = ks * 2 + ((lid >> 3) & 1);
                    const uint32_t off = SWZ(row * 128 + u * 16);
                    uint32_t kb[4], kl[4];
                    ldsm4(kb, sK + off);
                    ldsm4(kl, sKl + off);
                    mma16816(sc[nf2 * 2],     qh[ks], kb);
                    mma16816(sc[nf2 * 2],     qh[ks], kl);
                    mma16816(sc[nf2 * 2],     ql[ks], kb);
                    mma16816(sc[nf2 * 2 + 1], qh[ks], kb + 2);
                    mma16816(sc[nf2 * 2 + 1], qh[ks], kl + 2);
                    mma16816(sc[nf2 * 2 + 1], ql[ks], kb + 2);
                }
            }

            // mask + convert to log2 domain: s' = s*log2e + maskadd
#pragma unroll
            for (int nf = 0; nf < 8; nf++) {
                const int k0 = sub * 64 + nf * 8 + (lid & 3) * 2;
                const float ma0 = msk[k0]     ? 0.f : -1e9f;
                const float ma1 = msk[k0 + 1] ? 0.f : -1e9f;
                sc[nf][0] = fmaf(sc[nf][0], LOG2E, ma0);
                sc[nf][1] = fmaf(sc[nf][1], LOG2E, ma1);
                sc[nf][2] = fmaf(sc[nf][2], LOG2E, ma0);
                sc[nf][3] = fmaf(sc[nf][3], LOG2E, ma1);
            }

            // online softmax (log2 domain)
            float mxA = -1e30f, mxB = -1e30f;
#pragma unroll
            for (int nf = 0; nf < 8; nf++) {
                mxA = fmaxf(mxA, fmaxf(sc[nf][0], sc[nf][1]));
                mxB = fmaxf(mxB, fmaxf(sc[nf][2], sc[nf][3]));
            }
            mxA = fmaxf(mxA, __shfl_xor_sync(0xffffffffu, mxA, 1));
            mxA = fmaxf(mxA, __shfl_xor_sync(0xffffffffu, mxA, 2));
            mxB = fmaxf(mxB, __shfl_xor_sync(0xffffffffu, mxB, 1));
            mxB = fmaxf(mxB, __shfl_xor_sync(0xffffffffu, mxB, 2));
            const float mAn = fmaxf(mA, mxA), mBn = fmaxf(mB, mxB);
            const float fA = exp2f(mA - mAn), fB = exp2f(mB - mBn);
            mA = mAn; mB = mBn;
            lA *= fA; lB *= fB;
#pragma unroll
            for (int j = 0; j < 8; j++) {
                o[j][0] *= fA; o[j][1] *= fA;
                o[j][2] *= fB; o[j][3] *= fB;
            }
#pragma unroll
            for (int nf = 0; nf < 8; nf++) {
                sc[nf][0] = exp2f(sc[nf][0] - mA);
                sc[nf][1] = exp2f(sc[nf][1] - mA);
                sc[nf][2] = exp2f(sc[nf][2] - mB);
                sc[nf][3] = exp2f(sc[nf][3] - mB);
                lA += sc[nf][0] + sc[nf][1];
                lB += sc[nf][2] + sc[nf][3];
            }

            // P·V  (P frags built in-register from score frags)
#pragma unroll
            for (int kk = 0; kk < 4; kk++) {
                uint32_t ph[4], pl[4];
                split2(sc[2 * kk][0],     sc[2 * kk][1],     ph[0], pl[0]);
                split2(sc[2 * kk][2],     sc[2 * kk][3],     ph[1], pl[1]);
                split2(sc[2 * kk + 1][0], sc[2 * kk + 1][1], ph[2], pl[2]);
                split2(sc[2 * kk + 1][2], sc[2 * kk + 1][3], ph[3], pl[3]);
                const int row = sub * 64 + kk * 16 + (((lid >> 3) & 1) << 3) + (lid & 7);
#pragma unroll
                for (int j2 = 0; j2 < 4; j2++) {
                    const int u = 2 * j2 + (lid >> 4);
                    const uint32_t off = SWZ(row * 128 + u * 16);
                    uint32_t vb[4], vl[4];
                    ldsm4t(vb, sV + off);
                    ldsm4t(vl, sVl + off);
                    mma16816(o[j2 * 2],     ph, vb);
                    mma16816(o[j2 * 2],     ph, vl);
                    mma16816(o[j2 * 2],     pl, vb);
                    mma16816(o[j2 * 2 + 1], ph, vb + 2);
                    mma16816(o[j2 * 2 + 1], ph, vl + 2);
                    mma16816(o[j2 * 2 + 1], pl, vb + 2);
                }
            }
        }

        __syncthreads();
        if (ch + 2 < 16) load_chunk(ch + 2, bi);
        CP_COMMIT();
    }

    // final row sums and store
    lA += __shfl_xor_sync(0xffffffffu, lA, 1);
    lA += __shfl_xor_sync(0xffffffffu, lA, 2);
    lB += __shfl_xor_sync(0xffffffffu, lB, 1);
    lB += __shfl_xor_sync(0xffffffffu, lB, 2);
    const float invA = 1.f / lA, invB = 1.f / lB;

    const int s0 = q0 + (lid >> 2), s1 = s0 + 8;
#pragma unroll
    for (int j = 0; j < 8; j++) {
        const int col = h * DK + j * 8 + (lid & 3) * 2;
        const size_t i0 = ((size_t)(b * S_ + s0)) * DM + col;
        const size_t i1 = ((size_t)(b * S_ + s1)) * DM + col;
        uint32_t hv, lv;
        split2(o[j][0] * invA, o[j][1] * invA, hv, lv);
        *(uint32_t*)(AOhi + i0) = hv;
        *(uint32_t*)(AOlo + i0) = lv;
        split2(o[j][2] * invB, o[j][3] * invB, hv, lv);
        *(uint32_t*)(AOhi + i1) = hv;
        *(uint32_t*)(AOlo + i1) = lv;
    }
}

// ---------------------------------------------------------------------------
// Launch
// ---------------------------------------------------------------------------
extern "C" void kernel_launch(void* const* d_in, const int* in_sizes, int n_in,
                              void* d_out, int out_size)
{
    (void)in_sizes; (void)n_in; (void)out_size;
    const float* x    = (const float*)d_in[0];
    const int*   mask = (const int*)  d_in[1];
    const float* Wq   = (const float*)d_in[2];
    const float* bq   = (const float*)d_in[3];
    const float* Wk   = (const float*)d_in[4];
    const float* bk   = (const float*)d_in[5];
    const float* Wv   = (const float*)d_in[6];
    const float* bv   = (const float*)d_in[7];
    const float* Wo   = (const float*)d_in[8];
    const float* bo   = (const float*)d_in[9];
    float* out = (float*)d_out;

    bf16 *xhi, *xlo, *whi, *wlo, *qhi, *qlo, *khi, *klo, *vhi, *vlo, *aohi, *aolo;
    cudaGetSymbolAddress((void**)&xhi,  g_xhi);
    cudaGetSymbolAddress((void**)&xlo,  g_xlo);
    cudaGetSymbolAddress((void**)&whi,  g_whi);
    cudaGetSymbolAddress((void**)&wlo,  g_wlo);
    cudaGetSymbolAddress((void**)&qhi,  g_qhi);
    cudaGetSymbolAddress((void**)&qlo,  g_qlo);
    cudaGetSymbolAddress((void**)&khi,  g_khi);
    cudaGetSymbolAddress((void**)&klo,  g_klo);
    cudaGetSymbolAddress((void**)&vhi,  g_vhi);
    cudaGetSymbolAddress((void**)&vlo,  g_vlo);
    cudaGetSymbolAddress((void**)&aohi, g_aohi);
    cudaGetSymbolAddress((void**)&aolo, g_aolo);

    cudaFuncSetAttribute(gemm_mma<0>, cudaFuncAttributeMaxDynamicSharedMemorySize, GEMM_SMEM);
    cudaFuncSetAttribute(gemm_mma<1>, cudaFuncAttributeMaxDynamicSharedMemorySize, GEMM_SMEM);
    cudaFuncSetAttribute(attn_mma,    cudaFuncAttributeMaxDynamicSharedMemorySize, ATTN_SMEM);

    cvt_kernel<<<MTOT * DM / 1024, 256>>>(x, xhi, xlo);
    cvt_kernel<<<DM * DM / 1024, 256>>>(Wq, whi + 0 * DM * DM, wlo + 0 * DM * DM);
    cvt_kernel<<<DM * DM / 1024, 256>>>(Wk, whi + 1 * DM * DM, wlo + 1 * DM * DM);
    cvt_kernel<<<DM * DM / 1024, 256>>>(Wv, whi + 2 * DM * DM, wlo + 2 * DM * DM);
    cvt_kernel<<<DM * DM / 1024, 256>>>(Wo, whi + 3 * DM * DM, wlo + 3 * DM * DM);

    dim3 g(DM / 128, MTOT / 128);   // (8, 64)
    gemm_mma<1><<<g, 256, GEMM_SMEM>>>(xhi, xlo, whi + 0 * DM * DM, wlo + 0 * DM * DM, bq, nullptr, qhi, qlo);
    gemm_mma<1><<<g, 256, GEMM_SMEM>>>(xhi, xlo, whi + 1 * DM * DM, wlo + 1 * DM * DM, bk, nullptr, khi, klo);
    gemm_mma<1><<<g, 256, GEMM_SMEM>>>(xhi, xlo, whi + 2 * DM * DM, wlo + 2 * DM * DM, bv, nullptr, vhi, vlo);

    attn_mma<<<dim3(S_ / 128, B_ * NH), 256, ATTN_SMEM>>>(qhi, qlo, khi, klo, vhi, vlo,
                                                          mask, aohi, aolo);

    gemm_mma<0><<<g, 256, GEMM_SMEM>>>(aohi, aolo, whi + 3 * DM * DM, wlo + 3 * DM * DM, bo, out, nullptr, nullptr);
}

// round 9
// speedup vs baseline: 4.1650x; 1.1386x over previous
#include <cuda_runtime.h>
#include <cuda_fp16.h>
#include <cstdint>
#include <math.h>

#define B_   4
#define S_   2048
#define DM   1024
#define NH   16
#define DK   64
#define MTOT (B_ * S_)   // 8192

#define LOG2E 1.4426950408889634f

typedef __half  f16;

// ---------------------------------------------------------------------------
// Scratch
// ---------------------------------------------------------------------------
__device__ f16 g_xhi[MTOT * DM];
__device__ f16 g_xlo[MTOT * DM];
__device__ f16 g_whi[4][DM * DM];
__device__ f16 g_wlo[4][DM * DM];
__device__ f16 g_qhi[MTOT * DM];
__device__ f16 g_qlo[MTOT * DM];
__device__ f16 g_k[MTOT * DM];
__device__ f16 g_v[MTOT * DM];
__device__ f16 g_aohi[MTOT * DM];
__device__ f16 g_aolo[MTOT * DM];

// ---------------------------------------------------------------------------
// helpers
// ---------------------------------------------------------------------------
__device__ __forceinline__ uint32_t s2u(const void* p) {
    uint32_t a;
    asm("{ .reg .u64 t; cvta.to.shared.u64 t, %1; cvt.u32.u64 %0, t; }"
        : "=r"(a) : "l"(p));
    return a;
}

#define SWZ(x) ((x) ^ (((x) >> 3) & 0x70))

__device__ __forceinline__ void ldsm4(uint32_t* r, uint32_t addr) {
    asm volatile("ldmatrix.sync.aligned.m8n8.x4.shared.b16 {%0,%1,%2,%3}, [%4];"
        : "=r"(r[0]), "=r"(r[1]), "=r"(r[2]), "=r"(r[3]) : "r"(addr));
}
__device__ __forceinline__ void ldsm4t(uint32_t* r, uint32_t addr) {
    asm volatile("ldmatrix.sync.aligned.m8n8.x4.trans.shared.b16 {%0,%1,%2,%3}, [%4];"
        : "=r"(r[0]), "=r"(r[1]), "=r"(r[2]), "=r"(r[3]) : "r"(addr));
}
__device__ __forceinline__ void mma16816(float* c, const uint32_t* a, const uint32_t* b) {
    asm volatile(
        "mma.sync.aligned.m16n8k16.row.col.f32.f16.f16.f32 "
        "{%0,%1,%2,%3}, {%4,%5,%6,%7}, {%8,%9}, {%0,%1,%2,%3};"
        : "+f"(c[0]), "+f"(c[1]), "+f"(c[2]), "+f"(c[3])
        : "r"(a[0]), "r"(a[1]), "r"(a[2]), "r"(a[3]), "r"(b[0]), "r"(b[1]));
}

// split (v0,v1) into packed fp16 hi and lo parts
__device__ __forceinline__ void split2(float v0, float v1, uint32_t& h, uint32_t& l) {
    f16 h0 = __float2half_rn(v0), h1 = __float2half_rn(v1);
    f16 l0 = __float2half_rn(v0 - __half2float(h0));
    f16 l1 = __float2half_rn(v1 - __half2float(h1));
    __half2 hv = __halves2half2(h0, h1);
    __half2 lv = __halves2half2(l0, l1);
    h = *(uint32_t*)&hv; l = *(uint32_t*)&lv;
}
__device__ __forceinline__ uint32_t pack2h(float v0, float v1) {
    __half2 hv = __floats2half2_rn(v0, v1);
    return *(uint32_t*)&hv;
}

#define CP16(dst, src) \
    asm volatile("cp.async.cg.shared.global [%0], [%1], 16;" :: "r"(dst), "l"(src))
#define CP4(dst, src) \
    asm volatile("cp.async.ca.shared.global [%0], [%1], 4;" :: "r"(dst), "l"(src))
#define CP_COMMIT() asm volatile("cp.async.commit_group;")
#define CP_WAIT1()  asm volatile("cp.async.wait_group 1;")
#define CP_WAIT2()  asm volatile("cp.async.wait_group 2;")

// ---------------------------------------------------------------------------
// fp32 -> fp16 hi/lo split
// ---------------------------------------------------------------------------
__global__ __launch_bounds__(256)
void cvt_kernel(const float* __restrict__ in, f16* __restrict__ hi, f16* __restrict__ lo)
{
    int i = (blockIdx.x * 256 + threadIdx.x) * 4;
    float4 v = *(const float4*)(in + i);
    uint32_t h0, l0, h1, l1;
    split2(v.x, v.y, h0, l0);
    split2(v.z, v.w, h1, l1);
    ((uint32_t*)(hi + i))[0] = h0; ((uint32_t*)(hi + i))[1] = h1;
    ((uint32_t*)(lo + i))[0] = l0; ((uint32_t*)(lo + i))[1] = l1;
}

// ---------------------------------------------------------------------------
// Split-fp16 GEMM via mma.sync. C[m,n] = sum_k A[m,k]*W[n,k] + bias[n]
// Block 128x128, warp 64x32 (8 warps as 2x4), Kc=64, 3-stage cp.async.
// OUT=0: fp32 row-major.  OUT=1: fp16 hi/lo scatter (Q).  OUT=2: single fp16
// scatter (K, V).
// ---------------------------------------------------------------------------
static const int GEMM_SMEM = 3 * 4 * 16384;  // 192KB

template <int OUT>
__global__ __launch_bounds__(256)
void gemm_mma(const f16* __restrict__ Ahi, const f16* __restrict__ Alo,
              const f16* __restrict__ Whi, const f16* __restrict__ Wlo,
              const float* __restrict__ bias,
              float* __restrict__ Cf, f16* __restrict__ Chi, f16* __restrict__ Clo)
{
    extern __shared__ __align__(1024) char smem[];
    const int K = 1024;
    const int tid = threadIdx.x;
    const int wid = tid >> 5;
    const int lid = tid & 31;
    const int m0 = blockIdx.y * 128;
    const int n0 = blockIdx.x * 128;
    const int wm = wid & 1;        // 0..1 (64-row slice)
    const int wn = wid >> 1;       // 0..3 (32-col slice)

    const uint32_t sb = s2u(smem);

    auto load_stage = [&](int kc, int buf) {
        const f16* srcs[4] = {Ahi + (size_t)m0 * K + kc * 64,
                              Alo + (size_t)m0 * K + kc * 64,
                              Whi + (size_t)n0 * K + kc * 64,
                              Wlo + (size_t)n0 * K + kc * 64};
        const uint32_t bufo = buf * 65536;
#pragma unroll
        for (int t = 0; t < 4; t++) {
#pragma unroll
            for (int it = 0; it < 4; it++) {
                const int idx = tid + it * 256;         // 0..1023
                const int row = idx >> 3;
                const int u = idx & 7;
                const uint32_t dst = sb + bufo + t * 16384 + SWZ(idx * 16);
                const f16* src = srcs[t] + (size_t)row * K + u * 8;
                CP16(dst, src);
            }
        }
    };

    float acc[4][4][4];
#pragma unroll
    for (int a = 0; a < 4; a++)
#pragma unroll
        for (int b = 0; b < 4; b++)
#pragma unroll
            for (int c = 0; c < 4; c++) acc[a][b][c] = 0.f;

    load_stage(0, 0); CP_COMMIT();
    load_stage(1, 1); CP_COMMIT();
    load_stage(2, 2); CP_COMMIT();

    for (int kc = 0; kc < 16; kc++) {
        CP_WAIT2();
        __syncthreads();
        const int bi = kc % 3;
        const uint32_t bufo = sb + bi * 65536;

#pragma unroll
        for (int ks = 0; ks < 4; ks++) {
            uint32_t ah[4][4], al[4][4];
#pragma unroll
            for (int mf = 0; mf < 4; mf++) {
                const int row = wm * 64 + mf * 16 + (lid & 15);
                const int u = ks * 2 + (lid >> 4);
                const uint32_t off = SWZ(row * 128 + u * 16);
                ldsm4(ah[mf], bufo + off);
                ldsm4(al[mf], bufo + 16384 + off);
            }
#pragma unroll
            for (int nf2 = 0; nf2 < 2; nf2++) {
                const int row = wn * 32 + nf2 * 16 + ((lid >> 4) << 3) + (lid & 7);
                const int u = ks * 2 + ((lid >> 3) & 1);
                const uint32_t off = SWZ(row * 128 + u * 16);
                uint32_t bh[4], bl[4];
                ldsm4(bh, bufo + 32768 + off);
                ldsm4(bl, bufo + 49152 + off);
#pragma unroll
                for (int mf = 0; mf < 4; mf++) {
                    mma16816(acc[mf][nf2 * 2],     ah[mf], bh);
                    mma16816(acc[mf][nf2 * 2],     ah[mf], bl);
                    mma16816(acc[mf][nf2 * 2],     al[mf], bh);
                    mma16816(acc[mf][nf2 * 2 + 1], ah[mf], bh + 2);
                    mma16816(acc[mf][nf2 * 2 + 1], ah[mf], bl + 2);
                    mma16816(acc[mf][nf2 * 2 + 1], al[mf], bh + 2);
                }
            }
        }
        __syncthreads();
        if (kc + 3 < 16) load_stage(kc + 3, bi);
        CP_COMMIT();
    }

    // epilogue
#pragma unroll
    for (int mf = 0; mf < 4; mf++) {
#pragma unroll
        for (int nf = 0; nf < 4; nf++) {
            const int n = n0 + wn * 32 + nf * 8 + (lid & 3) * 2;
            const int r0 = m0 + wm * 64 + mf * 16 + (lid >> 2);
            const int r1 = r0 + 8;
            const float b0 = bias[n], b1 = bias[n + 1];
            float v00 = acc[mf][nf][0] + b0, v01 = acc[mf][nf][1] + b1;
            float v10 = acc[mf][nf][2] + b0, v11 = acc[mf][nf][3] + b1;
            if (OUT == 0) {
                float2* p0 = (float2*)(Cf + (size_t)r0 * 1024 + n);
                float2* p1 = (float2*)(Cf + (size_t)r1 * 1024 + n);
                *p0 = make_float2(v00, v01);
                *p1 = make_float2(v10, v11);
            } else {
                const int h = n >> 6, d = n & 63;
#pragma unroll
                for (int rr = 0; rr < 2; rr++) {
                    const int r = rr ? r1 : r0;
                    const int b = r >> 11, s = r & (S_ - 1);
                    const size_t idx = ((((size_t)b * NH + h) * S_ + s) * DK) + d;
                    const float va = rr ? v10 : v00, vb = rr ? v11 : v01;
                    if (OUT == 1) {
                        uint32_t hv, lv;
                        split2(va, vb, hv, lv);
                        *(uint32_t*)(Chi + idx) = hv;
                        *(uint32_t*)(Clo + idx) = lv;
                    } else {
                        *(uint32_t*)(Chi + idx) = pack2h(va, vb);
                    }
                }
            }
        }
    }
}

// ---------------------------------------------------------------------------
// Flash attention, fp16 mma. Q split hi/lo (2-pass QK vs single-fp16 K),
// P split hi/lo (2-pass PV vs single-fp16 V). cp.async double-buffered KV,
// log2-domain softmax.
// ---------------------------------------------------------------------------
// Per-buffer layout: K(16K) V(16K) msk(512B) = 33280 B
static const int ATTN_BUF  = 33280;
static const int ATTN_SMEM = 2 * ATTN_BUF;

__global__ __launch_bounds__(256)
void attn_mma(const f16* __restrict__ Qhi, const f16* __restrict__ Qlo,
              const f16* __restrict__ Kg,  const f16* __restrict__ Vg,
              const int* __restrict__ mask,
              f16* __restrict__ AOhi, f16* __restrict__ AOlo)
{
    extern __shared__ __align__(1024) char smem[];
    const uint32_t sb = s2u(smem);

    const int tid = threadIdx.x;
    const int wid = tid >> 5;
    const int lid = tid & 31;
    const int bh = blockIdx.y;
    const int b = bh >> 4, h = bh & 15;
    const int q0 = blockIdx.x * 128 + wid * 16;

    const size_t bho = (size_t)bh * S_ * DK;

    auto load_chunk = [&](int ch, int buf) {
        const uint32_t bo = sb + buf * ATTN_BUF;
        const char* kh = (const char*)(Kg + bho + (size_t)ch * 128 * DK);
        const char* vh = (const char*)(Vg + bho + (size_t)ch * 128 * DK);
#pragma unroll
        for (int it = 0; it < 4; it++) {
            const int idx = tid + it * 256;
            const uint32_t sw = SWZ(idx * 16);
            CP16(bo + sw,         kh + idx * 16);
            CP16(bo + 16384 + sw, vh + idx * 16);
        }
        if (tid < 128)
            CP4(bo + 32768 + tid * 4, mask + b * S_ + ch * 128 + tid);
    };

    // Q fragments (pre-scaled by 0.125 via f16x2 multiply: exact)
    uint32_t qh[4][4], ql[4][4];
    const uint32_t eighth = 0x30003000u;  // fp16 0.125 x2
#pragma unroll
    for (int ks = 0; ks < 4; ks++) {
        const int c2 = ks * 16 + (lid & 3) * 2;
        const int r0 = q0 + (lid >> 2), r1 = r0 + 8;
        const uint32_t* qhp = (const uint32_t*)(Qhi + bho);
        const uint32_t* qlp = (const uint32_t*)(Qlo + bho);
        uint32_t a0 = qhp[(r0 * DK + c2) >> 1];
        uint32_t a1 = qhp[(r1 * DK + c2) >> 1];
        uint32_t a2 = qhp[(r0 * DK + c2 + 8) >> 1];
        uint32_t a3 = qhp[(r1 * DK + c2 + 8) >> 1];
        uint32_t b0 = qlp[(r0 * DK + c2) >> 1];
        uint32_t b1 = qlp[(r1 * DK + c2) >> 1];
        uint32_t b2 = qlp[(r0 * DK + c2 + 8) >> 1];
        uint32_t b3 = qlp[(r1 * DK + c2 + 8) >> 1];
        asm("mul.rn.f16x2 %0, %1, %2;" : "=r"(qh[ks][0]) : "r"(a0), "r"(eighth));
        asm("mul.rn.f16x2 %0, %1, %2;" : "=r"(qh[ks][1]) : "r"(a1), "r"(eighth));
        asm("mul.rn.f16x2 %0, %1, %2;" : "=r"(qh[ks][2]) : "r"(a2), "r"(eighth));
        asm("mul.rn.f16x2 %0, %1, %2;" : "=r"(qh[ks][3]) : "r"(a3), "r"(eighth));
        asm("mul.rn.f16x2 %0, %1, %2;" : "=r"(ql[ks][0]) : "r"(b0), "r"(eighth));
        asm("mul.rn.f16x2 %0, %1, %2;" : "=r"(ql[ks][1]) : "r"(b1), "r"(eighth));
        asm("mul.rn.f16x2 %0, %1, %2;" : "=r"(ql[ks][2]) : "r"(b2), "r"(eighth));
        asm("mul.rn.f16x2 %0, %1, %2;" : "=r"(ql[ks][3]) : "r"(b3), "r"(eighth));
    }

    float o[8][4];
#pragma unroll
    for (int j = 0; j < 8; j++)
#pragma unroll
        for (int c = 0; c < 4; c++) o[j][c] = 0.f;
    float mA = -1e30f, mB = -1e30f, lA = 0.f, lB = 0.f;

    load_chunk(0, 0); CP_COMMIT();
    load_chunk(1, 1); CP_COMMIT();

    for (int ch = 0; ch < 16; ch++) {
        CP_WAIT1();
        __syncthreads();
        const int bi = ch & 1;
        const uint32_t sK  = sb + bi * ATTN_BUF;
        const uint32_t sV  = sK + 16384;
        const int* msk = (const int*)(smem + bi * ATTN_BUF + 32768);

#pragma unroll
        for (int sub = 0; sub < 2; sub++) {
            float sc[8][4];
#pragma unroll
            for (int nf = 0; nf < 8; nf++)
#pragma unroll
                for (int c = 0; c < 4; c++) sc[nf][c] = 0.f;

            // scores: Q (16xk64) . K^T  (2-pass: qh, ql vs single-fp16 K)
#pragma unroll
            for (int nf2 = 0; nf2 < 4; nf2++) {
                const int row = sub * 64 + nf2 * 16 + ((lid >> 4) << 3) + (lid & 7);
#pragma unroll
                for (int ks = 0; ks < 4; ks++) {
                    const int u = ks * 2 + ((lid >> 3) & 1);
                    const uint32_t off = SWZ(row * 128 + u * 16);
                    uint32_t kb[4];
                    ldsm4(kb, sK + off);
                    mma16816(sc[nf2 * 2],     qh[ks], kb);
                    mma16816(sc[nf2 * 2],     ql[ks], kb);
                    mma16816(sc[nf2 * 2 + 1], qh[ks], kb + 2);
                    mma16816(sc[nf2 * 2 + 1], ql[ks], kb + 2);
                }
            }

            // mask + convert to log2 domain: s' = s*log2e + maskadd
#pragma unroll
            for (int nf = 0; nf < 8; nf++) {
                const int k0 = sub * 64 + nf * 8 + (lid & 3) * 2;
                const float ma0 = msk[k0]     ? 0.f : -1e9f;
                const float ma1 = msk[k0 + 1] ? 0.f : -1e9f;
                sc[nf][0] = fmaf(sc[nf][0], LOG2E, ma0);
                sc[nf][1] = fmaf(sc[nf][1], LOG2E, ma1);
                sc[nf][2] = fmaf(sc[nf][2], LOG2E, ma0);
                sc[nf][3] = fmaf(sc[nf][3], LOG2E, ma1);
            }

            // online softmax (log2 domain)
            float mxA = -1e30f, mxB = -1e30f;
#pragma unroll
            for (int nf = 0; nf < 8; nf++) {
                mxA = fmaxf(mxA, fmaxf(sc[nf][0], sc[nf][1]));
                mxB = fmaxf(mxB, fmaxf(sc[nf][2], sc[nf][3]));
            }
            mxA = fmaxf(mxA, __shfl_xor_sync(0xffffffffu, mxA, 1));
            mxA = fmaxf(mxA, __shfl_xor_sync(0xffffffffu, mxA, 2));
            mxB = fmaxf(mxB, __shfl_xor_sync(0xffffffffu, mxB, 1));
            mxB = fmaxf(mxB, __shfl_xor_sync(0xffffffffu, mxB, 2));
            const float mAn = fmaxf(mA, mxA), mBn = fmaxf(mB, mxB);
            const float fA = exp2f(mA - mAn), fB = exp2f(mB - mBn);
            mA = mAn; mB = mBn;
            lA *= fA; lB *= fB;
#pragma unroll
            for (int j = 0; j < 8; j++) {
                o[j][0] *= fA; o[j][1] *= fA;
                o[j][2] *= fB; o[j][3] *= fB;
            }
#pragma unroll
            for (int nf = 0; nf < 8; nf++) {
                sc[nf][0] = exp2f(sc[nf][0] - mA);
                sc[nf][1] = exp2f(sc[nf][1] - mA);
                sc[nf][2] = exp2f(sc[nf][2] - mB);
                sc[nf][3] = exp2f(sc[nf][3] - mB);
                lA += sc[nf][0] + sc[nf][1];
                lB += sc[nf][2] + sc[nf][3];
            }

            // P·V (P split hi/lo in-register; single-fp16 V)
#pragma unroll
            for (int kk = 0; kk < 4; kk++) {
                uint32_t ph[4], pl[4];
                split2(sc[2 * kk][0],     sc[2 * kk][1],     ph[0], pl[0]);
                split2(sc[2 * kk][2],     sc[2 * kk][3],     ph[1], pl[1]);
                split2(sc[2 * kk + 1][0], sc[2 * kk + 1][1], ph[2], pl[2]);
                split2(sc[2 * kk + 1][2], sc[2 * kk + 1][3], ph[3], pl[3]);
                const int row = sub * 64 + kk * 16 + (((lid >> 3) & 1) << 3) + (lid & 7);
#pragma unroll
                for (int j2 = 0; j2 < 4; j2++) {
                    const int u = 2 * j2 + (lid >> 4);
                    const uint32_t off = SWZ(row * 128 + u * 16);
                    uint32_t vb[4];
                    ldsm4t(vb, sV + off);
                    mma16816(o[j2 * 2],     ph, vb);
                    mma16816(o[j2 * 2],     pl, vb);
                    mma16816(o[j2 * 2 + 1], ph, vb + 2);
                    mma16816(o[j2 * 2 + 1], pl, vb + 2);
                }
            }
        }

        __syncthreads();
        if (ch + 2 < 16) load_chunk(ch + 2, bi);
        CP_COMMIT();
    }

    // final row sums and store
    lA += __shfl_xor_sync(0xffffffffu, lA, 1);
    lA += __shfl_xor_sync(0xffffffffu, lA, 2);
    lB += __shfl_xor_sync(0xffffffffu, lB, 1);
    lB += __shfl_xor_sync(0xffffffffu, lB, 2);
    const float invA = 1.f / lA, invB = 1.f / lB;

    const int s0 = q0 + (lid >> 2), s1 = s0 + 8;
#pragma unroll
    for (int j = 0; j < 8; j++) {
        const int col = h * DK + j * 8 + (lid & 3) * 2;
        const size_t i0 = ((size_t)(b * S_ + s0)) * DM + col;
        const size_t i1 = ((size_t)(b * S_ + s1)) * DM + col;
        uint32_t hv, lv;
        split2(o[j][0] * invA, o[j][1] * invA, hv, lv);
        *(uint32_t*)(AOhi + i0) = hv;
        *(uint32_t*)(AOlo + i0) = lv;
        split2(o[j][2] * invB, o[j][3] * invB, hv, lv);
        *(uint32_t*)(AOhi + i1) = hv;
        *(uint32_t*)(AOlo + i1) = lv;
    }
}

// ---------------------------------------------------------------------------
// Launch
// ---------------------------------------------------------------------------
extern "C" void kernel_launch(void* const* d_in, const int* in_sizes, int n_in,
                              void* d_out, int out_size)
{
    (void)in_sizes; (void)n_in; (void)out_size;
    const float* x    = (const float*)d_in[0];
    const int*   mask = (const int*)  d_in[1];
    const float* Wq   = (const float*)d_in[2];
    const float* bq   = (const float*)d_in[3];
    const float* Wk   = (const float*)d_in[4];
    const float* bk   = (const float*)d_in[5];
    const float* Wv   = (const float*)d_in[6];
    const float* bv   = (const float*)d_in[7];
    const float* Wo   = (const float*)d_in[8];
    const float* bo   = (const float*)d_in[9];
    float* out = (float*)d_out;

    f16 *xhi, *xlo, *whi, *wlo, *qhi, *qlo, *kd, *vd, *aohi, *aolo;
    cudaGetSymbolAddress((void**)&xhi,  g_xhi);
    cudaGetSymbolAddress((void**)&xlo,  g_xlo);
    cudaGetSymbolAddress((void**)&whi,  g_whi);
    cudaGetSymbolAddress((void**)&wlo,  g_wlo);
    cudaGetSymbolAddress((void**)&qhi,  g_qhi);
    cudaGetSymbolAddress((void**)&qlo,  g_qlo);
    cudaGetSymbolAddress((void**)&kd,   g_k);
    cudaGetSymbolAddress((void**)&vd,   g_v);
    cudaGetSymbolAddress((void**)&aohi, g_aohi);
    cudaGetSymbolAddress((void**)&aolo, g_aolo);

    cudaFuncSetAttribute(gemm_mma<0>, cudaFuncAttributeMaxDynamicSharedMemorySize, GEMM_SMEM);
    cudaFuncSetAttribute(gemm_mma<1>, cudaFuncAttributeMaxDynamicSharedMemorySize, GEMM_SMEM);
    cudaFuncSetAttribute(gemm_mma<2>, cudaFuncAttributeMaxDynamicSharedMemorySize, GEMM_SMEM);
    cudaFuncSetAttribute(attn_mma,    cudaFuncAttributeMaxDynamicSharedMemorySize, ATTN_SMEM);

    cvt_kernel<<<MTOT * DM / 1024, 256>>>(x, xhi, xlo);
    cvt_kernel<<<DM * DM / 1024, 256>>>(Wq, whi + 0 * DM * DM, wlo + 0 * DM * DM);
    cvt_kernel<<<DM * DM / 1024, 256>>>(Wk, whi + 1 * DM * DM, wlo + 1 * DM * DM);
    cvt_kernel<<<DM * DM / 1024, 256>>>(Wv, whi + 2 * DM * DM, wlo + 2 * DM * DM);
    cvt_kernel<<<DM * DM / 1024, 256>>>(Wo, whi + 3 * DM * DM, wlo + 3 * DM * DM);

    dim3 g(DM / 128, MTOT / 128);   // (8, 64)
    gemm_mma<1><<<g, 256, GEMM_SMEM>>>(xhi, xlo, whi + 0 * DM * DM, wlo + 0 * DM * DM, bq, nullptr, qhi, qlo);
    gemm_mma<2><<<g, 256, GEMM_SMEM>>>(xhi, xlo, whi + 1 * DM * DM, wlo + 1 * DM * DM, bk, nullptr, kd, nullptr);
    gemm_mma<2><<<g, 256, GEMM_SMEM>>>(xhi, xlo, whi + 2 * DM * DM, wlo + 2 * DM * DM, bv, nullptr, vd, nullptr);

    attn_mma<<<dim3(S_ / 128, B_ * NH), 256, ATTN_SMEM>>>(qhi, qlo, kd, vd,
                                                          mask, aohi, aolo);

    gemm_mma<0><<<g, 256, GEMM_SMEM>>>(aohi, aolo, whi + 3 * DM * DM, wlo + 3 * DM * DM, bo, out, nullptr, nullptr);
}

// round 11
// speedup vs baseline: 4.6465x; 1.1156x over previous
#include <cuda_runtime.h>
#include <cuda_fp16.h>
#include <cstdint>
#include <math.h>

#define B_   4
#define S_   2048
#define DM   1024
#define NH   16
#define DK   64
#define MTOT (B_ * S_)   // 8192

#define LOG2E 1.4426950408889634f

typedef __half  f16;

// ---------------------------------------------------------------------------
// Scratch
// ---------------------------------------------------------------------------
__device__ f16 g_xhi[MTOT * DM];
__device__ f16 g_xlo[MTOT * DM];
__device__ f16 g_whi[4][DM * DM];
__device__ f16 g_wlo[4][DM * DM];
__device__ f16 g_qhi[MTOT * DM];
__device__ f16 g_qlo[MTOT * DM];
__device__ f16 g_k[MTOT * DM];
__device__ f16 g_v[MTOT * DM];
__device__ f16 g_aohi[MTOT * DM];
__device__ f16 g_aolo[MTOT * DM];
__device__ float g_maskf[MTOT];

// ---------------------------------------------------------------------------
// helpers
// ---------------------------------------------------------------------------
__device__ __forceinline__ uint32_t s2u(const void* p) {
    uint32_t a;
    asm("{ .reg .u64 t; cvta.to.shared.u64 t, %1; cvt.u32.u64 %0, t; }"
        : "=r"(a) : "l"(p));
    return a;
}

#define SWZ(x) ((x) ^ (((x) >> 3) & 0x70))

__device__ __forceinline__ void ldsm4(uint32_t* r, uint32_t addr) {
    asm volatile("ldmatrix.sync.aligned.m8n8.x4.shared.b16 {%0,%1,%2,%3}, [%4];"
        : "=r"(r[0]), "=r"(r[1]), "=r"(r[2]), "=r"(r[3]) : "r"(addr));
}
__device__ __forceinline__ void ldsm4t(uint32_t* r, uint32_t addr) {
    asm volatile("ldmatrix.sync.aligned.m8n8.x4.trans.shared.b16 {%0,%1,%2,%3}, [%4];"
        : "=r"(r[0]), "=r"(r[1]), "=r"(r[2]), "=r"(r[3]) : "r"(addr));
}
__device__ __forceinline__ void mma16816(float* c, const uint32_t* a, const uint32_t* b) {
    asm volatile(
        "mma.sync.aligned.m16n8k16.row.col.f32.f16.f16.f32 "
        "{%0,%1,%2,%3}, {%4,%5,%6,%7}, {%8,%9}, {%0,%1,%2,%3};"
        : "+f"(c[0]), "+f"(c[1]), "+f"(c[2]), "+f"(c[3])
        : "r"(a[0]), "r"(a[1]), "r"(a[2]), "r"(a[3]), "r"(b[0]), "r"(b[1]));
}

// split (v0,v1) into packed fp16 hi and lo parts
__device__ __forceinline__ void split2(float v0, float v1, uint32_t& h, uint32_t& l) {
    f16 h0 = __float2half_rn(v0), h1 = __float2half_rn(v1);
    f16 l0 = __float2half_rn(v0 - __half2float(h0));
    f16 l1 = __float2half_rn(v1 - __half2float(h1));
    __half2 hv = __halves2half2(h0, h1);
    __half2 lv = __halves2half2(l0, l1);
    h = *(uint32_t*)&hv; l = *(uint32_t*)&lv;
}
__device__ __forceinline__ uint32_t pack2h(float v0, float v1) {
    __half2 hv = __floats2half2_rn(v0, v1);
    return *(uint32_t*)&hv;
}

#define CP16(dst, src) \
    asm volatile("cp.async.cg.shared.global [%0], [%1], 16;" :: "r"(dst), "l"(src))
#define CP4(dst, src) \
    asm volatile("cp.async.ca.shared.global [%0], [%1], 4;" :: "r"(dst), "l"(src))
#define CP_COMMIT() asm volatile("cp.async.commit_group;")
#define CP_WAIT1()  asm volatile("cp.async.wait_group 1;")
#define CP_WAIT2()  asm volatile("cp.async.wait_group 2;")

// ---------------------------------------------------------------------------
// fp32 -> fp16 hi/lo split
// ---------------------------------------------------------------------------
__global__ __launch_bounds__(256)
void cvt_kernel(const float* __restrict__ in, f16* __restrict__ hi, f16* __restrict__ lo)
{
    int i = (blockIdx.x * 256 + threadIdx.x) * 4;
    float4 v = *(const float4*)(in + i);
    uint32_t h0, l0, h1, l1;
    split2(v.x, v.y, h0, l0);
    split2(v.z, v.w, h1, l1);
    ((uint32_t*)(hi + i))[0] = h0; ((uint32_t*)(hi + i))[1] = h1;
    ((uint32_t*)(lo + i))[0] = l0; ((uint32_t*)(lo + i))[1] = l1;
}

// mask(int) -> float addend (0 or -1e9)
__global__ __launch_bounds__(256)
void maskcvt_kernel(const int* __restrict__ mask, float* __restrict__ mf)
{
    int i = (blockIdx.x * 256 + threadIdx.x) * 4;
    int4 m = *(const int4*)(mask + i);
    float4 v;
    v.x = m.x ? 0.f : -1e9f;
    v.y = m.y ? 0.f : -1e9f;
    v.z = m.z ? 0.f : -1e9f;
    v.w = m.w ? 0.f : -1e9f;
    *(float4*)(mf + i) = v;
}

// ---------------------------------------------------------------------------
// Fused QKV projection GEMM. grid (24, 64): blockIdx.x selects weight
// (wsel = x>>3) and n-block within it. Q: 3-pass split-fp16, hi/lo output.
// K/V: 2-pass (Wlo dropped — output rounds to fp16 anyway), single output.
// ---------------------------------------------------------------------------
static const int GEMM_SMEM = 3 * 4 * 16384;  // 192KB

__global__ __launch_bounds__(256)
void gemm_qkv(const f16* __restrict__ Ahi, const f16* __restrict__ Alo,
              const f16* __restrict__ Wh_base, const f16* __restrict__ Wl_base,
              const float* __restrict__ bq, const float* __restrict__ bk,
              const float* __restrict__ bv,
              f16* __restrict__ Qhi, f16* __restrict__ Qlo,
              f16* __restrict__ Kd, f16* __restrict__ Vd)
{
    extern __shared__ __align__(1024) char smem[];
    const int K = 1024;
    const int tid = threadIdx.x;
    const int wid = tid >> 5;
    const int lid = tid & 31;
    const int m0 = blockIdx.y * 128;
    const int wsel = blockIdx.x >> 3;            // 0=Q 1=K 2=V
    const int n0 = (blockIdx.x & 7) * 128;
    const bool isQ = (wsel == 0);
    const int wm = wid & 1;
    const int wn = wid >> 1;

    const f16* Whi = Wh_base + (size_t)wsel * DM * DM;
    const f16* Wlo = Wl_base + (size_t)wsel * DM * DM;
    const float* bias = (wsel == 0) ? bq : (wsel == 1) ? bk : bv;

    const uint32_t sb = s2u(smem);

    auto load_stage = [&](int kc, int buf) {
        const f16* srcs[3] = {Ahi + (size_t)m0 * K + kc * 64,
                              Alo + (size_t)m0 * K + kc * 64,
                              Whi + (size_t)n0 * K + kc * 64};
        const uint32_t bufo = buf * 65536;
#pragma unroll
        for (int t = 0; t < 3; t++) {
#pragma unroll
            for (int it = 0; it < 4; it++) {
                const int idx = tid + it * 256;
                const int row = idx >> 3;
                const int u = idx & 7;
                const uint32_t dst = sb + bufo + t * 16384 + SWZ(idx * 16);
                CP16(dst, srcs[t] + (size_t)row * K + u * 8);
            }
        }
        if (isQ) {
            const f16* wl = Wlo + (size_t)n0 * K + kc * 64;
#pragma unroll
            for (int it = 0; it < 4; it++) {
                const int idx = tid + it * 256;
                const int row = idx >> 3;
                const int u = idx & 7;
                const uint32_t dst = sb + bufo + 49152 + SWZ(idx * 16);
                CP16(dst, wl + (size_t)row * K + u * 8);
            }
        }
    };

    float acc[4][4][4];
#pragma unroll
    for (int a = 0; a < 4; a++)
#pragma unroll
        for (int b = 0; b < 4; b++)
#pragma unroll
            for (int c = 0; c < 4; c++) acc[a][b][c] = 0.f;

    load_stage(0, 0); CP_COMMIT();
    load_stage(1, 1); CP_COMMIT();
    load_stage(2, 2); CP_COMMIT();

    for (int kc = 0; kc < 16; kc++) {
        CP_WAIT2();
        __syncthreads();
        const int bi = kc % 3;
        const uint32_t bufo = sb + bi * 65536;

#pragma unroll
        for (int ks = 0; ks < 4; ks++) {
            uint32_t ah[4][4], al[4][4];
#pragma unroll
            for (int mf = 0; mf < 4; mf++) {
                const int row = wm * 64 + mf * 16 + (lid & 15);
                const int u = ks * 2 + (lid >> 4);
                const uint32_t off = SWZ(row * 128 + u * 16);
                ldsm4(ah[mf], bufo + off);
                ldsm4(al[mf], bufo + 16384 + off);
            }
#pragma unroll
            for (int nf2 = 0; nf2 < 2; nf2++) {
                const int row = wn * 32 + nf2 * 16 + ((lid >> 4) << 3) + (lid & 7);
                const int u = ks * 2 + ((lid >> 3) & 1);
                const uint32_t off = SWZ(row * 128 + u * 16);
                uint32_t bh[4];
                ldsm4(bh, bufo + 32768 + off);
#pragma unroll
                for (int mf = 0; mf < 4; mf++) {
                    mma16816(acc[mf][nf2 * 2],     ah[mf], bh);
                    mma16816(acc[mf][nf2 * 2],     al[mf], bh);
                    mma16816(acc[mf][nf2 * 2 + 1], ah[mf], bh + 2);
                    mma16816(acc[mf][nf2 * 2 + 1], al[mf], bh + 2);
                }
                if (isQ) {
                    uint32_t bl[4];
                    ldsm4(bl, bufo + 49152 + off);
#pragma unroll
                    for (int mf = 0; mf < 4; mf++) {
                        mma16816(acc[mf][nf2 * 2],     ah[mf], bl);
                        mma16816(acc[mf][nf2 * 2 + 1], ah[mf], bl + 2);
                    }
                }
            }
        }
        __syncthreads();
        if (kc + 3 < 16) load_stage(kc + 3, bi);
        CP_COMMIT();
    }

    // epilogue: scatter to (b,h,s,d)
    f16* KVd = (wsel == 1) ? Kd : Vd;
#pragma unroll
    for (int mf = 0; mf < 4; mf++) {
#pragma unroll
        for (int nf = 0; nf < 4; nf++) {
            const int n = n0 + wn * 32 + nf * 8 + (lid & 3) * 2;
            const int r0 = m0 + wm * 64 + mf * 16 + (lid >> 2);
            const float b0 = bias[n], b1 = bias[n + 1];
            const int h = n >> 6, d = n & 63;
#pragma unroll
            for (int rr = 0; rr < 2; rr++) {
                const int r = r0 + rr * 8;
                const int b = r >> 11, s = r & (S_ - 1);
                const size_t idx = ((((size_t)b * NH + h) * S_ + s) * DK) + d;
                const float va = acc[mf][nf][rr * 2] + b0;
                const float vb = acc[mf][nf][rr * 2 + 1] + b1;
                if (isQ) {
                    uint32_t hv, lv;
                    split2(va, vb, hv, lv);
                    *(uint32_t*)(Qhi + idx) = hv;
                    *(uint32_t*)(Qlo + idx) = lv;
                } else {
                    *(uint32_t*)(KVd + idx) = pack2h(va, vb);
                }
            }
        }
    }
}

// ---------------------------------------------------------------------------
// Output GEMM (3-pass split-fp16, fp32 row-major out).
// ---------------------------------------------------------------------------
__global__ __launch_bounds__(256)
void gemm_out(const f16* __restrict__ Ahi, const f16* __restrict__ Alo,
              const f16* __restrict__ Whi, const f16* __restrict__ Wlo,
              const float* __restrict__ bias, float* __restrict__ Cf)
{
    extern __shared__ __align__(1024) char smem[];
    const int K = 1024;
    const int tid = threadIdx.x;
    const int wid = tid >> 5;
    const int lid = tid & 31;
    const int m0 = blockIdx.y * 128;
    const int n0 = blockIdx.x * 128;
    const int wm = wid & 1;
    const int wn = wid >> 1;

    const uint32_t sb = s2u(smem);

    auto load_stage = [&](int kc, int buf) {
        const f16* srcs[4] = {Ahi + (size_t)m0 * K + kc * 64,
                              Alo + (size_t)m0 * K + kc * 64,
                              Whi + (size_t)n0 * K + kc * 64,
                              Wlo + (size_t)n0 * K + kc * 64};
        const uint32_t bufo = buf * 65536;
#pragma unroll
        for (int t = 0; t < 4; t++) {
#pragma unroll
            for (int it = 0; it < 4; it++) {
                const int idx = tid + it * 256;
                const int row = idx >> 3;
                const int u = idx & 7;
                const uint32_t dst = sb + bufo + t * 16384 + SWZ(idx * 16);
                CP16(dst, srcs[t] + (size_t)row * K + u * 8);
            }
        }
    };

    float acc[4][4][4];
#pragma unroll
    for (int a = 0; a < 4; a++)
#pragma unroll
        for (int b = 0; b < 4; b++)
#pragma unroll
            for (int c = 0; c < 4; c++) acc[a][b][c] = 0.f;

    load_stage(0, 0); CP_COMMIT();
    load_stage(1, 1); CP_COMMIT();
    load_stage(2, 2); CP_COMMIT();

    for (int kc = 0; kc < 16; kc++) {
        CP_WAIT2();
        __syncthreads();
        const int bi = kc % 3;
        const uint32_t bufo = sb + bi * 65536;

#pragma unroll
        for (int ks = 0; ks < 4; ks++) {
            uint32_t ah[4][4], al[4][4];
#pragma unroll
            for (int mf = 0; mf < 4; mf++) {
                const int row = wm * 64 + mf * 16 + (lid & 15);
                const int u = ks * 2 + (lid >> 4);
                const uint32_t off = SWZ(row * 128 + u * 16);
                ldsm4(ah[mf], bufo + off);
                ldsm4(al[mf], bufo + 16384 + off);
            }
#pragma unroll
            for (int nf2 = 0; nf2 < 2; nf2++) {
                const int row = wn * 32 + nf2 * 16 + ((lid >> 4) << 3) + (lid & 7);
                const int u = ks * 2 + ((lid >> 3) & 1);
                const uint32_t off = SWZ(row * 128 + u * 16);
                uint32_t bh[4], bl[4];
                ldsm4(bh, bufo + 32768 + off);
                ldsm4(bl, bufo + 49152 + off);
#pragma unroll
                for (int mf = 0; mf < 4; mf++) {
                    mma16816(acc[mf][nf2 * 2],     ah[mf], bh);
                    mma16816(acc[mf][nf2 * 2],     ah[mf], bl);
                    mma16816(acc[mf][nf2 * 2],     al[mf], bh);
                    mma16816(acc[mf][nf2 * 2 + 1], ah[mf], bh + 2);
                    mma16816(acc[mf][nf2 * 2 + 1], ah[mf], bl + 2);
                    mma16816(acc[mf][nf2 * 2 + 1], al[mf], bh + 2);
                }
            }
        }
        __syncthreads();
        if (kc + 3 < 16) load_stage(kc + 3, bi);
        CP_COMMIT();
    }

#pragma unroll
    for (int mf = 0; mf < 4; mf++) {
#pragma unroll
        for (int nf = 0; nf < 4; nf++) {
            const int n = n0 + wn * 32 + nf * 8 + (lid & 3) * 2;
            const int r0 = m0 + wm * 64 + mf * 16 + (lid >> 2);
            const int r1 = r0 + 8;
            const float b0 = bias[n], b1 = bias[n + 1];
            *(float2*)(Cf + (size_t)r0 * 1024 + n) =
                make_float2(acc[mf][nf][0] + b0, acc[mf][nf][1] + b1);
            *(float2*)(Cf + (size_t)r1 * 1024 + n) =
                make_float2(acc[mf][nf][2] + b0, acc[mf][nf][3] + b1);
        }
    }
}

// ---------------------------------------------------------------------------
// Flash attention, fp16 mma. Q split hi/lo (2-pass QK), P split hi/lo
// (2-pass PV), single-fp16 K/V. cp.async double-buffered, log2 softmax,
// precomputed float mask addend, rescale skipped when max unchanged.
// ---------------------------------------------------------------------------
// Per-buffer layout: K(16K) V(16K) maskf(512B) = 33280 B
static const int ATTN_BUF  = 33280;
static const int ATTN_SMEM = 2 * ATTN_BUF;

__global__ __launch_bounds__(256)
void attn_mma(const f16* __restrict__ Qhi, const f16* __restrict__ Qlo,
              const f16* __restrict__ Kg,  const f16* __restrict__ Vg,
              const float* __restrict__ maskf,
              f16* __restrict__ AOhi, f16* __restrict__ AOlo)
{
    extern __shared__ __align__(1024) char smem[];
    const uint32_t sb = s2u(smem);

    const int tid = threadIdx.x;
    const int wid = tid >> 5;
    const int lid = tid & 31;
    const int bh = blockIdx.y;
    const int b = bh >> 4, h = bh & 15;
    const int q0 = blockIdx.x * 128 + wid * 16;

    const size_t bho = (size_t)bh * S_ * DK;

    auto load_chunk = [&](int ch, int buf) {
        const uint32_t bo = sb + buf * ATTN_BUF;
        const char* kh = (const char*)(Kg + bho + (size_t)ch * 128 * DK);
        const char* vh = (const char*)(Vg + bho + (size_t)ch * 128 * DK);
#pragma unroll
        for (int it = 0; it < 4; it++) {
            const int idx = tid + it * 256;
            const uint32_t sw = SWZ(idx * 16);
            CP16(bo + sw,         kh + idx * 16);
            CP16(bo + 16384 + sw, vh + idx * 16);
        }
        if (tid < 128)
            CP4(bo + 32768 + tid * 4, maskf + b * S_ + ch * 128 + tid);
    };

    // Q fragments (pre-scaled by 0.125 via f16x2 multiply: exact)
    uint32_t qh[4][4], ql[4][4];
    const uint32_t eighth = 0x30003000u;  // fp16 0.125 x2
#pragma unroll
    for (int ks = 0; ks < 4; ks++) {
        const int c2 = ks * 16 + (lid & 3) * 2;
        const int r0 = q0 + (lid >> 2), r1 = r0 + 8;
        const uint32_t* qhp = (const uint32_t*)(Qhi + bho);
        const uint32_t* qlp = (const uint32_t*)(Qlo + bho);
        uint32_t a0 = qhp[(r0 * DK + c2) >> 1];
        uint32_t a1 = qhp[(r1 * DK + c2) >> 1];
        uint32_t a2 = qhp[(r0 * DK + c2 + 8) >> 1];
        uint32_t a3 = qhp[(r1 * DK + c2 + 8) >> 1];
        uint32_t b0 = qlp[(r0 * DK + c2) >> 1];
        uint32_t b1 = qlp[(r1 * DK + c2) >> 1];
        uint32_t b2 = qlp[(r0 * DK + c2 + 8) >> 1];
        uint32_t b3 = qlp[(r1 * DK + c2 + 8) >> 1];
        asm("mul.rn.f16x2 %0, %1, %2;" : "=r"(qh[ks][0]) : "r"(a0), "r"(eighth));
        asm("mul.rn.f16x2 %0, %1, %2;" : "=r"(qh[ks][1]) : "r"(a1), "r"(eighth));
        asm("mul.rn.f16x2 %0, %1, %2;" : "=r"(qh[ks][2]) : "r"(a2), "r"(eighth));
        asm("mul.rn.f16x2 %0, %1, %2;" : "=r"(qh[ks][3]) : "r"(a3), "r"(eighth));
        asm("mul.rn.f16x2 %0, %1, %2;" : "=r"(ql[ks][0]) : "r"(b0), "r"(eighth));
        asm("mul.rn.f16x2 %0, %1, %2;" : "=r"(ql[ks][1]) : "r"(b1), "r"(eighth));
        asm("mul.rn.f16x2 %0, %1, %2;" : "=r"(ql[ks][2]) : "r"(b2), "r"(eighth));
        asm("mul.rn.f16x2 %0, %1, %2;" : "=r"(ql[ks][3]) : "r"(b3), "r"(eighth));
    }

    float o[8][4];
#pragma unroll
    for (int j = 0; j < 8; j++)
#pragma unroll
        for (int c = 0; c < 4; c++) o[j][c] = 0.f;
    float mA = -1e30f, mB = -1e30f, lA = 0.f, lB = 0.f;

    load_chunk(0, 0); CP_COMMIT();
    load_chunk(1, 1); CP_COMMIT();

    for (int ch = 0; ch < 16; ch++) {
        CP_WAIT1();
        __syncthreads();
        const int bi = ch & 1;
        const uint32_t sK  = sb + bi * ATTN_BUF;
        const uint32_t sV  = sK + 16384;
        const float* mskf = (const float*)(smem + bi * ATTN_BUF + 32768);

#pragma unroll
        for (int sub = 0; sub < 2; sub++) {
            float sc[8][4];
#pragma unroll
            for (int nf = 0; nf < 8; nf++)
#pragma unroll
                for (int c = 0; c < 4; c++) sc[nf][c] = 0.f;

            // scores: Q (16xk64) . K^T  (2-pass: qh, ql vs single-fp16 K)
#pragma unroll
            for (int nf2 = 0; nf2 < 4; nf2++) {
                const int row = sub * 64 + nf2 * 16 + ((lid >> 4) << 3) + (lid & 7);
#pragma unroll
                for (int ks = 0; ks < 4; ks++) {
                    const int u = ks * 2 + ((lid >> 3) & 1);
                    const uint32_t off = SWZ(row * 128 + u * 16);
                    uint32_t kb[4];
                    ldsm4(kb, sK + off);
                    mma16816(sc[nf2 * 2],     qh[ks], kb);
                    mma16816(sc[nf2 * 2],     ql[ks], kb);
                    mma16816(sc[nf2 * 2 + 1], qh[ks], kb + 2);
                    mma16816(sc[nf2 * 2 + 1], ql[ks], kb + 2);
                }
            }

            // mask + convert to log2 domain: s' = s*log2e + maskadd
#pragma unroll
            for (int nf = 0; nf < 8; nf++) {
                const int k0 = sub * 64 + nf * 8 + (lid & 3) * 2;
                const float ma0 = mskf[k0], ma1 = mskf[k0 + 1];
                sc[nf][0] = fmaf(sc[nf][0], LOG2E, ma0);
                sc[nf][1] = fmaf(sc[nf][1], LOG2E, ma1);
                sc[nf][2] = fmaf(sc[nf][2], LOG2E, ma0);
                sc[nf][3] = fmaf(sc[nf][3], LOG2E, ma1);
            }

            // online softmax (log2 domain)
            float mxA = -1e30f, mxB = -1e30f;
#pragma unroll
            for (int nf = 0; nf < 8; nf++) {
                mxA = fmaxf(mxA, fmaxf(sc[nf][0], sc[nf][1]));
                mxB = fmaxf(mxB, fmaxf(sc[nf][2], sc[nf][3]));
            }
            mxA = fmaxf(mxA, __shfl_xor_sync(0xffffffffu, mxA, 1));
            mxA = fmaxf(mxA, __shfl_xor_sync(0xffffffffu, mxA, 2));
            mxB = fmaxf(mxB, __shfl_xor_sync(0xffffffffu, mxB, 1));
            mxB = fmaxf(mxB, __shfl_xor_sync(0xffffffffu, mxB, 2));
            const float mAn = fmaxf(mA, mxA), mBn = fmaxf(mB, mxB);
            if (!__all_sync(0xffffffffu, (mAn == mA) && (mBn == mB))) {
                const float fA = exp2f(mA - mAn), fB = exp2f(mB - mBn);
                lA *= fA; lB *= fB;
#pragma unroll
                for (int j = 0; j < 8; j++) {
                    o[j][0] *= fA; o[j][1] *= fA;
                    o[j][2] *= fB; o[j][3] *= fB;
                }
            }
            mA = mAn; mB = mBn;
#pragma unroll
            for (int nf = 0; nf < 8; nf++) {
                sc[nf][0] = exp2f(sc[nf][0] - mA);
                sc[nf][1] = exp2f(sc[nf][1] - mA);
                sc[nf][2] = exp2f(sc[nf][2] - mB);
                sc[nf][3] = exp2f(sc[nf][3] - mB);
                lA += sc[nf][0] + sc[nf][1];
                lB += sc[nf][2] + sc[nf][3];
            }

            // P·V (P split hi/lo in-register; single-fp16 V)
#pragma unroll
            for (int kk = 0; kk < 4; kk++) {
                uint32_t ph[4], pl[4];
                split2(sc[2 * kk][0],     sc[2 * kk][1],     ph[0], pl[0]);
                split2(sc[2 * kk][2],     sc[2 * kk][3],     ph[1], pl[1]);
                split2(sc[2 * kk + 1][0], sc[2 * kk + 1][1], ph[2], pl[2]);
                split2(sc[2 * kk + 1][2], sc[2 * kk + 1][3], ph[3], pl[3]);
                const int row = sub * 64 + kk * 16 + (((lid >> 3) & 1) << 3) + (lid & 7);
#pragma unroll
                for (int j2 = 0; j2 < 4; j2++) {
                    const int u = 2 * j2 + (lid >> 4);
                    const uint32_t off = SWZ(row * 128 + u * 16);
                    uint32_t vb[4];
                    ldsm4t(vb, sV + off);
                    mma16816(o[j2 * 2],     ph, vb);
                    mma16816(o[j2 * 2],     pl, vb);
                    mma16816(o[j2 * 2 + 1], ph, vb + 2);
                    mma16816(o[j2 * 2 + 1], pl, vb + 2);
                }
            }
        }

        __syncthreads();
        if (ch + 2 < 16) load_chunk(ch + 2, bi);
        CP_COMMIT();
    }

    // final row sums and store
    lA += __shfl_xor_sync(0xffffffffu, lA, 1);
    lA += __shfl_xor_sync(0xffffffffu, lA, 2);
    lB += __shfl_xor_sync(0xffffffffu, lB, 1);
    lB += __shfl_xor_sync(0xffffffffu, lB, 2);
    const float invA = 1.f / lA, invB = 1.f / lB;

    const int s0 = q0 + (lid >> 2), s1 = s0 + 8;
#pragma unroll
    for (int j = 0; j < 8; j++) {
        const int col = h * DK + j * 8 + (lid & 3) * 2;
        const size_t i0 = ((size_t)(b * S_ + s0)) * DM + col;
        const size_t i1 = ((size_t)(b * S_ + s1)) * DM + col;
        uint32_t hv, lv;
        split2(o[j][0] * invA, o[j][1] * invA, hv, lv);
        *(uint32_t*)(AOhi + i0) = hv;
        *(uint32_t*)(AOlo + i0) = lv;
        split2(o[j][2] * invB, o[j][3] * invB, hv, lv);
        *(uint32_t*)(AOhi + i1) = hv;
        *(uint32_t*)(AOlo + i1) = lv;
    }
}

// ---------------------------------------------------------------------------
// Launch
// ---------------------------------------------------------------------------
extern "C" void kernel_launch(void* const* d_in, const int* in_sizes, int n_in,
                              void* d_out, int out_size)
{
    (void)in_sizes; (void)n_in; (void)out_size;
    const float* x    = (const float*)d_in[0];
    const int*   mask = (const int*)  d_in[1];
    const float* Wq   = (const float*)d_in[2];
    const float* bq   = (const float*)d_in[3];
    const float* Wk   = (const float*)d_in[4];
    const float* bk   = (const float*)d_in[5];
    const float* Wv   = (const float*)d_in[6];
    const float* bv   = (const float*)d_in[7];
    const float* Wo   = (const float*)d_in[8];
    const float* bo   = (const float*)d_in[9];
    float* out = (float*)d_out;

    f16 *xhi, *xlo, *whi, *wlo, *qhi, *qlo, *kd, *vd, *aohi, *aolo;
    float* maskf;
    cudaGetSymbolAddress((void**)&xhi,   g_xhi);
    cudaGetSymbolAddress((void**)&xlo,   g_xlo);
    cudaGetSymbolAddress((void**)&whi,   g_whi);
    cudaGetSymbolAddress((void**)&wlo,   g_wlo);
    cudaGetSymbolAddress((void**)&qhi,   g_qhi);
    cudaGetSymbolAddress((void**)&qlo,   g_qlo);
    cudaGetSymbolAddress((void**)&kd,    g_k);
    cudaGetSymbolAddress((void**)&vd,    g_v);
    cudaGetSymbolAddress((void**)&aohi,  g_aohi);
    cudaGetSymbolAddress((void**)&aolo,  g_aolo);
    cudaGetSymbolAddress((void**)&maskf, g_maskf);

    cudaFuncSetAttribute(gemm_qkv, cudaFuncAttributeMaxDynamicSharedMemorySize, GEMM_SMEM);
    cudaFuncSetAttribute(gemm_out, cudaFuncAttributeMaxDynamicSharedMemorySize, GEMM_SMEM);
    cudaFuncSetAttribute(attn_mma, cudaFuncAttributeMaxDynamicSharedMemorySize, ATTN_SMEM);

    cvt_kernel<<<MTOT * DM / 1024, 256>>>(x, xhi, xlo);
    cvt_kernel<<<DM * DM / 1024, 256>>>(Wq, whi + 0 * DM * DM, wlo + 0 * DM * DM);
    cvt_kernel<<<DM * DM / 1024, 256>>>(Wk, whi + 1 * DM * DM, wlo + 1 * DM * DM);
    cvt_kernel<<<DM * DM / 1024, 256>>>(Wv, whi + 2 * DM * DM, wlo + 2 * DM * DM);
    cvt_kernel<<<DM * DM / 1024, 256>>>(Wo, whi + 3 * DM * DM, wlo + 3 * DM * DM);
    maskcvt_kernel<<<MTOT / 1024, 256>>>(mask, maskf);

    gemm_qkv<<<dim3(24, MTOT / 128), 256, GEMM_SMEM>>>(
        xhi, xlo, whi, wlo, bq, bk, bv, qhi, qlo, kd, vd);

    attn_mma<<<dim3(S_ / 128, B_ * NH), 256, ATTN_SMEM>>>(qhi, qlo, kd, vd,
                                                          maskf, aohi, aolo);

    gemm_out<<<dim3(DM / 128, MTOT / 128), 256, GEMM_SMEM>>>(
        aohi, aolo, whi + 3 * DM * DM, wlo + 3 * DM * DM, bo, out);
}

// round 12
// speedup vs baseline: 6.2127x; 1.3371x over previous
#include <cuda_runtime.h>
#include <cuda_fp16.h>
#include <cstdint>
#include <math.h>

#define B_   4
#define S_   2048
#define DM   1024
#define NH   16
#define DK   64
#define MTOT (B_ * S_)   // 8192

#define LOG2E 1.4426950408889634f

typedef __half  f16;

// ---------------------------------------------------------------------------
// Scratch
// ---------------------------------------------------------------------------
__device__ f16 g_xhi[MTOT * DM];
__device__ f16 g_xlo[MTOT * DM];
__device__ f16 g_whi[4][DM * DM];
__device__ f16 g_wlo[4][DM * DM];
__device__ f16 g_q[MTOT * DM];
__device__ f16 g_k[MTOT * DM];
__device__ f16 g_v[MTOT * DM];
__device__ f16 g_aohi[MTOT * DM];
__device__ f16 g_aolo[MTOT * DM];
__device__ float g_maskf[MTOT];

// ---------------------------------------------------------------------------
// helpers
// ---------------------------------------------------------------------------
__device__ __forceinline__ uint32_t s2u(const void* p) {
    uint32_t a;
    asm("{ .reg .u64 t; cvta.to.shared.u64 t, %1; cvt.u32.u64 %0, t; }"
        : "=r"(a) : "l"(p));
    return a;
}

#define SWZ(x) ((x) ^ (((x) >> 3) & 0x70))

__device__ __forceinline__ void ldsm4(uint32_t* r, uint32_t addr) {
    asm volatile("ldmatrix.sync.aligned.m8n8.x4.shared.b16 {%0,%1,%2,%3}, [%4];"
        : "=r"(r[0]), "=r"(r[1]), "=r"(r[2]), "=r"(r[3]) : "r"(addr));
}
__device__ __forceinline__ void ldsm4t(uint32_t* r, uint32_t addr) {
    asm volatile("ldmatrix.sync.aligned.m8n8.x4.trans.shared.b16 {%0,%1,%2,%3}, [%4];"
        : "=r"(r[0]), "=r"(r[1]), "=r"(r[2]), "=r"(r[3]) : "r"(addr));
}
__device__ __forceinline__ void mma16816(float* c, const uint32_t* a, const uint32_t* b) {
    asm volatile(
        "mma.sync.aligned.m16n8k16.row.col.f32.f16.f16.f32 "
        "{%0,%1,%2,%3}, {%4,%5,%6,%7}, {%8,%9}, {%0,%1,%2,%3};"
        : "+f"(c[0]), "+f"(c[1]), "+f"(c[2]), "+f"(c[3])
        : "r"(a[0]), "r"(a[1]), "r"(a[2]), "r"(a[3]), "r"(b[0]), "r"(b[1]));
}

// split (v0,v1) into packed fp16 hi and lo parts
__device__ __forceinline__ void split2(float v0, float v1, uint32_t& h, uint32_t& l) {
    f16 h0 = __float2half_rn(v0), h1 = __float2half_rn(v1);
    f16 l0 = __float2half_rn(v0 - __half2float(h0));
    f16 l1 = __float2half_rn(v1 - __half2float(h1));
    __half2 hv = __halves2half2(h0, h1);
    __half2 lv = __halves2half2(l0, l1);
    h = *(uint32_t*)&hv; l = *(uint32_t*)&lv;
}
__device__ __forceinline__ uint32_t pack2h(float v0, float v1) {
    __half2 hv = __floats2half2_rn(v0, v1);
    return *(uint32_t*)&hv;
}

#define CP16(dst, src) \
    asm volatile("cp.async.cg.shared.global [%0], [%1], 16;" :: "r"(dst), "l"(src))
#define CP4(dst, src) \
    asm volatile("cp.async.ca.shared.global [%0], [%1], 4;" :: "r"(dst), "l"(src))
#define CP_COMMIT() asm volatile("cp.async.commit_group;")
#define CP_WAIT1()  asm volatile("cp.async.wait_group 1;")
#define CP_WAIT2()  asm volatile("cp.async.wait_group 2;")

// ---------------------------------------------------------------------------
// fp32 -> fp16 hi/lo split
// ---------------------------------------------------------------------------
__global__ __launch_bounds__(256)
void cvt_kernel(const float* __restrict__ in, f16* __restrict__ hi, f16* __restrict__ lo)
{
    int i = (blockIdx.x * 256 + threadIdx.x) * 4;
    float4 v = *(const float4*)(in + i);
    uint32_t h0, l0, h1, l1;
    split2(v.x, v.y, h0, l0);
    split2(v.z, v.w, h1, l1);
    ((uint32_t*)(hi + i))[0] = h0; ((uint32_t*)(hi + i))[1] = h1;
    ((uint32_t*)(lo + i))[0] = l0; ((uint32_t*)(lo + i))[1] = l1;
}

// mask(int) -> float addend (0 or -1e9)
__global__ __launch_bounds__(256)
void maskcvt_kernel(const int* __restrict__ mask, float* __restrict__ mf)
{
    int i = (blockIdx.x * 256 + threadIdx.x) * 4;
    int4 m = *(const int4*)(mask + i);
    float4 v;
    v.x = m.x ? 0.f : -1e9f;
    v.y = m.y ? 0.f : -1e9f;
    v.z = m.z ? 0.f : -1e9f;
    v.w = m.w ? 0.f : -1e9f;
    *(float4*)(mf + i) = v;
}

// ---------------------------------------------------------------------------
// Fused QKV projection GEMM. grid (24, 64): blockIdx.x selects weight
// (wsel = x>>3) and n-block. Uniform 2-pass (Ahi·Wh + Alo·Wh) — all three
// outputs round to single fp16, so the Wlo term is below output precision.
// ---------------------------------------------------------------------------
static const int GEMM_SMEM = 3 * 4 * 16384;  // 192KB (3 stages x 64KB; QKV uses 48KB/stage)

__global__ __launch_bounds__(256)
void gemm_qkv(const f16* __restrict__ Ahi, const f16* __restrict__ Alo,
              const f16* __restrict__ Wh_base,
              const float* __restrict__ bq, const float* __restrict__ bk,
              const float* __restrict__ bv,
              f16* __restrict__ Qd, f16* __restrict__ Kd, f16* __restrict__ Vd)
{
    extern __shared__ __align__(1024) char smem[];
    const int K = 1024;
    const int tid = threadIdx.x;
    const int wid = tid >> 5;
    const int lid = tid & 31;
    const int m0 = blockIdx.y * 128;
    const int wsel = blockIdx.x >> 3;            // 0=Q 1=K 2=V
    const int n0 = (blockIdx.x & 7) * 128;
    const int wm = wid & 1;
    const int wn = wid >> 1;

    const f16* Whi = Wh_base + (size_t)wsel * DM * DM;
    const float* bias = (wsel == 0) ? bq : (wsel == 1) ? bk : bv;

    const uint32_t sb = s2u(smem);

    auto load_stage = [&](int kc, int buf) {
        const f16* srcs[3] = {Ahi + (size_t)m0 * K + kc * 64,
                              Alo + (size_t)m0 * K + kc * 64,
                              Whi + (size_t)n0 * K + kc * 64};
        const uint32_t bufo = buf * 65536;
#pragma unroll
        for (int t = 0; t < 3; t++) {
#pragma unroll
            for (int it = 0; it < 4; it++) {
                const int idx = tid + it * 256;
                const int row = idx >> 3;
                const int u = idx & 7;
                const uint32_t dst = sb + bufo + t * 16384 + SWZ(idx * 16);
                CP16(dst, srcs[t] + (size_t)row * K + u * 8);
            }
        }
    };

    float acc[4][4][4];
#pragma unroll
    for (int a = 0; a < 4; a++)
#pragma unroll
        for (int b = 0; b < 4; b++)
#pragma unroll
            for (int c = 0; c < 4; c++) acc[a][b][c] = 0.f;

    load_stage(0, 0); CP_COMMIT();
    load_stage(1, 1); CP_COMMIT();
    load_stage(2, 2); CP_COMMIT();

    for (int kc = 0; kc < 16; kc++) {
        CP_WAIT2();
        __syncthreads();
        const int bi = kc % 3;
        const uint32_t bufo = sb + bi * 65536;

#pragma unroll
        for (int ks = 0; ks < 4; ks++) {
            uint32_t ah[4][4], al[4][4];
#pragma unroll
            for (int mf = 0; mf < 4; mf++) {
                const int row = wm * 64 + mf * 16 + (lid & 15);
                const int u = ks * 2 + (lid >> 4);
                const uint32_t off = SWZ(row * 128 + u * 16);
                ldsm4(ah[mf], bufo + off);
                ldsm4(al[mf], bufo + 16384 + off);
            }
#pragma unroll
            for (int nf2 = 0; nf2 < 2; nf2++) {
                const int row = wn * 32 + nf2 * 16 + ((lid >> 4) << 3) + (lid & 7);
                const int u = ks * 2 + ((lid >> 3) & 1);
                const uint32_t off = SWZ(row * 128 + u * 16);
                uint32_t bh[4];
                ldsm4(bh, bufo + 32768 + off);
#pragma unroll
                for (int mf = 0; mf < 4; mf++) {
                    mma16816(acc[mf][nf2 * 2],     ah[mf], bh);
                    mma16816(acc[mf][nf2 * 2],     al[mf], bh);
                    mma16816(acc[mf][nf2 * 2 + 1], ah[mf], bh + 2);
                    mma16816(acc[mf][nf2 * 2 + 1], al[mf], bh + 2);
                }
            }
        }
        __syncthreads();
        if (kc + 3 < 16) load_stage(kc + 3, bi);
        CP_COMMIT();
    }

    // epilogue: scatter single fp16 to (b,h,s,d)
    f16* Out = (wsel == 0) ? Qd : (wsel == 1) ? Kd : Vd;
#pragma unroll
    for (int mf = 0; mf < 4; mf++) {
#pragma unroll
        for (int nf = 0; nf < 4; nf++) {
            const int n = n0 + wn * 32 + nf * 8 + (lid & 3) * 2;
            const int r0 = m0 + wm * 64 + mf * 16 + (lid >> 2);
            const float b0 = bias[n], b1 = bias[n + 1];
            const int h = n >> 6, d = n & 63;
#pragma unroll
            for (int rr = 0; rr < 2; rr++) {
                const int r = r0 + rr * 8;
                const int b = r >> 11, s = r & (S_ - 1);
                const size_t idx = ((((size_t)b * NH + h) * S_ + s) * DK) + d;
                *(uint32_t*)(Out + idx) =
                    pack2h(acc[mf][nf][rr * 2] + b0, acc[mf][nf][rr * 2 + 1] + b1);
            }
        }
    }
}

// ---------------------------------------------------------------------------
// Output GEMM (3-pass split-fp16, fp32 row-major out).
// ---------------------------------------------------------------------------
__global__ __launch_bounds__(256)
void gemm_out(const f16* __restrict__ Ahi, const f16* __restrict__ Alo,
              const f16* __restrict__ Whi, const f16* __restrict__ Wlo,
              const float* __restrict__ bias, float* __restrict__ Cf)
{
    extern __shared__ __align__(1024) char smem[];
    const int K = 1024;
    const int tid = threadIdx.x;
    const int wid = tid >> 5;
    const int lid = tid & 31;
    const int m0 = blockIdx.y * 128;
    const int n0 = blockIdx.x * 128;
    const int wm = wid & 1;
    const int wn = wid >> 1;

    const uint32_t sb = s2u(smem);

    auto load_stage = [&](int kc, int buf) {
        const f16* srcs[4] = {Ahi + (size_t)m0 * K + kc * 64,
                              Alo + (size_t)m0 * K + kc * 64,
                              Whi + (size_t)n0 * K + kc * 64,
                              Wlo + (size_t)n0 * K + kc * 64};
        const uint32_t bufo = buf * 65536;
#pragma unroll
        for (int t = 0; t < 4; t++) {
#pragma unroll
            for (int it = 0; it < 4; it++) {
                const int idx = tid + it * 256;
                const int row = idx >> 3;
                const int u = idx & 7;
                const uint32_t dst = sb + bufo + t * 16384 + SWZ(idx * 16);
                CP16(dst, srcs[t] + (size_t)row * K + u * 8);
            }
        }
    };

    float acc[4][4][4];
#pragma unroll
    for (int a = 0; a < 4; a++)
#pragma unroll
        for (int b = 0; b < 4; b++)
#pragma unroll
            for (int c = 0; c < 4; c++) acc[a][b][c] = 0.f;

    load_stage(0, 0); CP_COMMIT();
    load_stage(1, 1); CP_COMMIT();
    load_stage(2, 2); CP_COMMIT();

    for (int kc = 0; kc < 16; kc++) {
        CP_WAIT2();
        __syncthreads();
        const int bi = kc % 3;
        const uint32_t bufo = sb + bi * 65536;

#pragma unroll
        for (int ks = 0; ks < 4; ks++) {
            uint32_t ah[4][4], al[4][4];
#pragma unroll
            for (int mf = 0; mf < 4; mf++) {
                const int row = wm * 64 + mf * 16 + (lid & 15);
                const int u = ks * 2 + (lid >> 4);
                const uint32_t off = SWZ(row * 128 + u * 16);
                ldsm4(ah[mf], bufo + off);
                ldsm4(al[mf], bufo + 16384 + off);
            }
#pragma unroll
            for (int nf2 = 0; nf2 < 2; nf2++) {
                const int row = wn * 32 + nf2 * 16 + ((lid >> 4) << 3) + (lid & 7);
                const int u = ks * 2 + ((lid >> 3) & 1);
                const uint32_t off = SWZ(row * 128 + u * 16);
                uint32_t bh[4], bl[4];
                ldsm4(bh, bufo + 32768 + off);
                ldsm4(bl, bufo + 49152 + off);
#pragma unroll
                for (int mf = 0; mf < 4; mf++) {
                    mma16816(acc[mf][nf2 * 2],     ah[mf], bh);
                    mma16816(acc[mf][nf2 * 2],     ah[mf], bl);
                    mma16816(acc[mf][nf2 * 2],     al[mf], bh);
                    mma16816(acc[mf][nf2 * 2 + 1], ah[mf], bh + 2);
                    mma16816(acc[mf][nf2 * 2 + 1], ah[mf], bl + 2);
                    mma16816(acc[mf][nf2 * 2 + 1], al[mf], bh + 2);
                }
            }
        }
        __syncthreads();
        if (kc + 3 < 16) load_stage(kc + 3, bi);
        CP_COMMIT();
    }

#pragma unroll
    for (int mf = 0; mf < 4; mf++) {
#pragma unroll
        for (int nf = 0; nf < 4; nf++) {
            const int n = n0 + wn * 32 + nf * 8 + (lid & 3) * 2;
            const int r0 = m0 + wm * 64 + mf * 16 + (lid >> 2);
            const int r1 = r0 + 8;
            const float b0 = bias[n], b1 = bias[n + 1];
            *(float2*)(Cf + (size_t)r0 * 1024 + n) =
                make_float2(acc[mf][nf][0] + b0, acc[mf][nf][1] + b1);
            *(float2*)(Cf + (size_t)r1 * 1024 + n) =
                make_float2(acc[mf][nf][2] + b0, acc[mf][nf][3] + b1);
        }
    }
}

// ---------------------------------------------------------------------------
// Flash attention, fp16 mma. Single-fp16 Q/K/V/P: 1-pass QK, 1-pass PV.
// cp.async double-buffered, log2 softmax, precomputed float mask addend,
// rescale skipped when max unchanged. AO written as hi/lo.
// ---------------------------------------------------------------------------
// Per-buffer layout: K(16K) V(16K) maskf(512B) = 33280 B
static const int ATTN_BUF  = 33280;
static const int ATTN_SMEM = 2 * ATTN_BUF;

__global__ __launch_bounds__(256)
void attn_mma(const f16* __restrict__ Qg,
              const f16* __restrict__ Kg,  const f16* __restrict__ Vg,
              const float* __restrict__ maskf,
              f16* __restrict__ AOhi, f16* __restrict__ AOlo)
{
    extern __shared__ __align__(1024) char smem[];
    const uint32_t sb = s2u(smem);

    const int tid = threadIdx.x;
    const int wid = tid >> 5;
    const int lid = tid & 31;
    const int bh = blockIdx.y;
    const int b = bh >> 4, h = bh & 15;
    const int q0 = blockIdx.x * 128 + wid * 16;

    const size_t bho = (size_t)bh * S_ * DK;

    auto load_chunk = [&](int ch, int buf) {
        const uint32_t bo = sb + buf * ATTN_BUF;
        const char* kh = (const char*)(Kg + bho + (size_t)ch * 128 * DK);
        const char* vh = (const char*)(Vg + bho + (size_t)ch * 128 * DK);
#pragma unroll
        for (int it = 0; it < 4; it++) {
            const int idx = tid + it * 256;
            const uint32_t sw = SWZ(idx * 16);
            CP16(bo + sw,         kh + idx * 16);
            CP16(bo + 16384 + sw, vh + idx * 16);
        }
        if (tid < 128)
            CP4(bo + 32768 + tid * 4, maskf + b * S_ + ch * 128 + tid);
    };

    // Q fragments (pre-scaled by 0.125 via f16x2 multiply: exact)
    uint32_t qh[4][4];
    const uint32_t eighth = 0x30003000u;  // fp16 0.125 x2
#pragma unroll
    for (int ks = 0; ks < 4; ks++) {
        const int c2 = ks * 16 + (lid & 3) * 2;
        const int r0 = q0 + (lid >> 2), r1 = r0 + 8;
        const uint32_t* qp = (const uint32_t*)(Qg + bho);
        uint32_t a0 = qp[(r0 * DK + c2) >> 1];
        uint32_t a1 = qp[(r1 * DK + c2) >> 1];
        uint32_t a2 = qp[(r0 * DK + c2 + 8) >> 1];
        uint32_t a3 = qp[(r1 * DK + c2 + 8) >> 1];
        asm("mul.rn.f16x2 %0, %1, %2;" : "=r"(qh[ks][0]) : "r"(a0), "r"(eighth));
        asm("mul.rn.f16x2 %0, %1, %2;" : "=r"(qh[ks][1]) : "r"(a1), "r"(eighth));
        asm("mul.rn.f16x2 %0, %1, %2;" : "=r"(qh[ks][2]) : "r"(a2), "r"(eighth));
        asm("mul.rn.f16x2 %0, %1, %2;" : "=r"(qh[ks][3]) : "r"(a3), "r"(eighth));
    }

    float o[8][4];
#pragma unroll
    for (int j = 0; j < 8; j++)
#pragma unroll
        for (int c = 0; c < 4; c++) o[j][c] = 0.f;
    float mA = -1e30f, mB = -1e30f, lA = 0.f, lB = 0.f;

    load_chunk(0, 0); CP_COMMIT();
    load_chunk(1, 1); CP_COMMIT();

    for (int ch = 0; ch < 16; ch++) {
        CP_WAIT1();
        __syncthreads();
        const int bi = ch & 1;
        const uint32_t sK  = sb + bi * ATTN_BUF;
        const uint32_t sV  = sK + 16384;
        const float* mskf = (const float*)(smem + bi * ATTN_BUF + 32768);

#pragma unroll
        for (int sub = 0; sub < 2; sub++) {
            float sc[8][4];
#pragma unroll
            for (int nf = 0; nf < 8; nf++)
#pragma unroll
                for (int c = 0; c < 4; c++) sc[nf][c] = 0.f;

            // scores: Q (16xk64) . K^T  (single pass)
#pragma unroll
            for (int nf2 = 0; nf2 < 4; nf2++) {
                const int row = sub * 64 + nf2 * 16 + ((lid >> 4) << 3) + (lid & 7);
#pragma unroll
                for (int ks = 0; ks < 4; ks++) {
                    const int u = ks * 2 + ((lid >> 3) & 1);
                    const uint32_t off = SWZ(row * 128 + u * 16);
                    uint32_t kb[4];
                    ldsm4(kb, sK + off);
                    mma16816(sc[nf2 * 2],     qh[ks], kb);
                    mma16816(sc[nf2 * 2 + 1], qh[ks], kb + 2);
                }
            }

            // mask + convert to log2 domain: s' = s*log2e + maskadd
#pragma unroll
            for (int nf = 0; nf < 8; nf++) {
                const int k0 = sub * 64 + nf * 8 + (lid & 3) * 2;
                const float ma0 = mskf[k0], ma1 = mskf[k0 + 1];
                sc[nf][0] = fmaf(sc[nf][0], LOG2E, ma0);
                sc[nf][1] = fmaf(sc[nf][1], LOG2E, ma1);
                sc[nf][2] = fmaf(sc[nf][2], LOG2E, ma0);
                sc[nf][3] = fmaf(sc[nf][3], LOG2E, ma1);
            }

            // online softmax (log2 domain)
            float mxA = -1e30f, mxB = -1e30f;
#pragma unroll
            for (int nf = 0; nf < 8; nf++) {
                mxA = fmaxf(mxA, fmaxf(sc[nf][0], sc[nf][1]));
                mxB = fmaxf(mxB, fmaxf(sc[nf][2], sc[nf][3]));
            }
            mxA = fmaxf(mxA, __shfl_xor_sync(0xffffffffu, mxA, 1));
            mxA = fmaxf(mxA, __shfl_xor_sync(0xffffffffu, mxA, 2));
            mxB = fmaxf(mxB, __shfl_xor_sync(0xffffffffu, mxB, 1));
            mxB = fmaxf(mxB, __shfl_xor_sync(0xffffffffu, mxB, 2));
            const float mAn = fmaxf(mA, mxA), mBn = fmaxf(mB, mxB);
            if (!__all_sync(0xffffffffu, (mAn == mA) && (mBn == mB))) {
                const float fA = exp2f(mA - mAn), fB = exp2f(mB - mBn);
                lA *= fA; lB *= fB;
#pragma unroll
                for (int j = 0; j < 8; j++) {
                    o[j][0] *= fA; o[j][1] *= fA;
                    o[j][2] *= fB; o[j][3] *= fB;
                }
            }
            mA = mAn; mB = mBn;
#pragma unroll
            for (int nf = 0; nf < 8; nf++) {
                sc[nf][0] = exp2f(sc[nf][0] - mA);
                sc[nf][1] = exp2f(sc[nf][1] - mA);
                sc[nf][2] = exp2f(sc[nf][2] - mB);
                sc[nf][3] = exp2f(sc[nf][3] - mB);
                lA += sc[nf][0] + sc[nf][1];
                lB += sc[nf][2] + sc[nf][3];
            }

            // P·V (P packed single-fp16; single pass)
#pragma unroll
            for (int kk = 0; kk < 4; kk++) {
                uint32_t ph[4];
                ph[0] = pack2h(sc[2 * kk][0],     sc[2 * kk][1]);
                ph[1] = pack2h(sc[2 * kk][2],     sc[2 * kk][3]);
                ph[2] = pack2h(sc[2 * kk + 1][0], sc[2 * kk + 1][1]);
                ph[3] = pack2h(sc[2 * kk + 1][2], sc[2 * kk + 1][3]);
                const int row = sub * 64 + kk * 16 + (((lid >> 3) & 1) << 3) + (lid & 7);
#pragma unroll
                for (int j2 = 0; j2 < 4; j2++) {
                    const int u = 2 * j2 + (lid >> 4);
                    const uint32_t off = SWZ(row * 128 + u * 16);
                    uint32_t vb[4];
                    ldsm4t(vb, sV + off);
                    mma16816(o[j2 * 2],     ph, vb);
                    mma16816(o[j2 * 2 + 1], ph, vb + 2);
                }
            }
        }

        __syncthreads();
        if (ch + 2 < 16) load_chunk(ch + 2, bi);
        CP_COMMIT();
    }

    // final row sums and store
    lA += __shfl_xor_sync(0xffffffffu, lA, 1);
    lA += __shfl_xor_sync(0xffffffffu, lA, 2);
    lB += __shfl_xor_sync(0xffffffffu, lB, 1);
    lB += __shfl_xor_sync(0xffffffffu, lB, 2);
    const float invA = 1.f / lA, invB = 1.f / lB;

    const int s0 = q0 + (lid >> 2), s1 = s0 + 8;
#pragma unroll
    for (int j = 0; j < 8; j++) {
        const int col = h * DK + j * 8 + (lid & 3) * 2;
        const size_t i0 = ((size_t)(b * S_ + s0)) * DM + col;
        const size_t i1 = ((size_t)(b * S_ + s1)) * DM + col;
        uint32_t hv, lv;
        split2(o[j][0] * invA, o[j][1] * invA, hv, lv);
        *(uint32_t*)(AOhi + i0) = hv;
        *(uint32_t*)(AOlo + i0) = lv;
        split2(o[j][2] * invB, o[j][3] * invB, hv, lv);
        *(uint32_t*)(AOhi + i1) = hv;
        *(uint32_t*)(AOlo + i1) = lv;
    }
}

// ---------------------------------------------------------------------------
// Launch
// ---------------------------------------------------------------------------
extern "C" void kernel_launch(void* const* d_in, const int* in_sizes, int n_in,
                              void* d_out, int out_size)
{
    (void)in_sizes; (void)n_in; (void)out_size;
    const float* x    = (const float*)d_in[0];
    const int*   mask = (const int*)  d_in[1];
    const float* Wq   = (const float*)d_in[2];
    const float* bq   = (const float*)d_in[3];
    const float* Wk   = (const float*)d_in[4];
    const float* bk   = (const float*)d_in[5];
    const float* Wv   = (const float*)d_in[6];
    const float* bv   = (const float*)d_in[7];
    const float* Wo   = (const float*)d_in[8];
    const float* bo   = (const float*)d_in[9];
    float* out = (float*)d_out;

    f16 *xhi, *xlo, *whi, *wlo, *qd, *kd, *vd, *aohi, *aolo;
    float* maskf;
    cudaGetSymbolAddress((void**)&xhi,   g_xhi);
    cudaGetSymbolAddress((void**)&xlo,   g_xlo);
    cudaGetSymbolAddress((void**)&whi,   g_whi);
    cudaGetSymbolAddress((void**)&wlo,   g_wlo);
    cudaGetSymbolAddress((void**)&qd,    g_q);
    cudaGetSymbolAddress((void**)&kd,    g_k);
    cudaGetSymbolAddress((void**)&vd,    g_v);
    cudaGetSymbolAddress((void**)&aohi,  g_aohi);
    cudaGetSymbolAddress((void**)&aolo,  g_aolo);
    cudaGetSymbolAddress((void**)&maskf, g_maskf);

    cudaFuncSetAttribute(gemm_qkv, cudaFuncAttributeMaxDynamicSharedMemorySize, GEMM_SMEM);
    cudaFuncSetAttribute(gemm_out, cudaFuncAttributeMaxDynamicSharedMemorySize, GEMM_SMEM);
    cudaFuncSetAttribute(attn_mma, cudaFuncAttributeMaxDynamicSharedMemorySize, ATTN_SMEM);

    cvt_kernel<<<MTOT * DM / 1024, 256>>>(x, xhi, xlo);
    // Only Q/K/V weights' hi parts are used by gemm_qkv; Wo needs hi+lo.
    cvt_kernel<<<DM * DM / 1024, 256>>>(Wq, whi + 0 * DM * DM, wlo + 0 * DM * DM);
    cvt_kernel<<<DM * DM / 1024, 256>>>(Wk, whi + 1 * DM * DM, wlo + 1 * DM * DM);
    cvt_kernel<<<DM * DM / 1024, 256>>>(Wv, whi + 2 * DM * DM, wlo + 2 * DM * DM);
    cvt_kernel<<<DM * DM / 1024, 256>>>(Wo, whi + 3 * DM * DM, wlo + 3 * DM * DM);
    maskcvt_kernel<<<MTOT / 1024, 256>>>(mask, maskf);

    gemm_qkv<<<dim3(24, MTOT / 128), 256, GEMM_SMEM>>>(
        xhi, xlo, whi, bq, bk, bv, qd, kd, vd);

    attn_mma<<<dim3(S_ / 128, B_ * NH), 256, ATTN_SMEM>>>(qd, kd, vd,
                                                          maskf, aohi, aolo);

    gemm_out<<<dim3(DM / 128, MTOT / 128), 256, GEMM_SMEM>>>(
        aohi, aolo, whi + 3 * DM * DM, wlo + 3 * DM * DM, bo, out);
}

// round 13
// speedup vs baseline: 6.6592x; 1.0719x over previous
#include <cuda_runtime.h>
#include <cuda_fp16.h>
#include <cstdint>
#include <math.h>

#define B_   4
#define S_   2048
#define DM   1024
#define NH   16
#define DK   64
#define MTOT (B_ * S_)   // 8192

#define LOG2E 1.4426950408889634f

typedef __half  f16;

// ---------------------------------------------------------------------------
// Scratch
// ---------------------------------------------------------------------------
__device__ f16 g_xhi[MTOT * DM];
__device__ f16 g_xlo[MTOT * DM];
__device__ f16 g_whi[4][DM * DM];
__device__ f16 g_wlo[DM * DM];       // only Wo needs a lo part now
__device__ f16 g_q[MTOT * DM];
__device__ f16 g_k[MTOT * DM];
__device__ f16 g_v[MTOT * DM];
__device__ f16 g_ao[MTOT * DM];
__device__ float g_maskf[MTOT];

// ---------------------------------------------------------------------------
// helpers
// ---------------------------------------------------------------------------
__device__ __forceinline__ uint32_t s2u(const void* p) {
    uint32_t a;
    asm("{ .reg .u64 t; cvta.to.shared.u64 t, %1; cvt.u32.u64 %0, t; }"
        : "=r"(a) : "l"(p));
    return a;
}

#define SWZ(x) ((x) ^ (((x) >> 3) & 0x70))

__device__ __forceinline__ void ldsm4(uint32_t* r, uint32_t addr) {
    asm volatile("ldmatrix.sync.aligned.m8n8.x4.shared.b16 {%0,%1,%2,%3}, [%4];"
        : "=r"(r[0]), "=r"(r[1]), "=r"(r[2]), "=r"(r[3]) : "r"(addr));
}
__device__ __forceinline__ void ldsm4t(uint32_t* r, uint32_t addr) {
    asm volatile("ldmatrix.sync.aligned.m8n8.x4.trans.shared.b16 {%0,%1,%2,%3}, [%4];"
        : "=r"(r[0]), "=r"(r[1]), "=r"(r[2]), "=r"(r[3]) : "r"(addr));
}
__device__ __forceinline__ void mma16816(float* c, const uint32_t* a, const uint32_t* b) {
    asm volatile(
        "mma.sync.aligned.m16n8k16.row.col.f32.f16.f16.f32 "
        "{%0,%1,%2,%3}, {%4,%5,%6,%7}, {%8,%9}, {%0,%1,%2,%3};"
        : "+f"(c[0]), "+f"(c[1]), "+f"(c[2]), "+f"(c[3])
        : "r"(a[0]), "r"(a[1]), "r"(a[2]), "r"(a[3]), "r"(b[0]), "r"(b[1]));
}

// split (v0,v1) into packed fp16 hi and lo parts
__device__ __forceinline__ void split2(float v0, float v1, uint32_t& h, uint32_t& l) {
    f16 h0 = __float2half_rn(v0), h1 = __float2half_rn(v1);
    f16 l0 = __float2half_rn(v0 - __half2float(h0));
    f16 l1 = __float2half_rn(v1 - __half2float(h1));
    __half2 hv = __halves2half2(h0, h1);
    __half2 lv = __halves2half2(l0, l1);
    h = *(uint32_t*)&hv; l = *(uint32_t*)&lv;
}
__device__ __forceinline__ uint32_t pack2h(float v0, float v1) {
    __half2 hv = __floats2half2_rn(v0, v1);
    return *(uint32_t*)&hv;
}

#define CP16(dst, src) \
    asm volatile("cp.async.cg.shared.global [%0], [%1], 16;" :: "r"(dst), "l"(src))
#define CP4(dst, src) \
    asm volatile("cp.async.ca.shared.global [%0], [%1], 4;" :: "r"(dst), "l"(src))
#define CP_COMMIT() asm volatile("cp.async.commit_group;")
#define CP_WAIT1()  asm volatile("cp.async.wait_group 1;")
#define CP_WAIT2()  asm volatile("cp.async.wait_group 2;")

// ---------------------------------------------------------------------------
// fp32 -> fp16 hi/lo split
// ---------------------------------------------------------------------------
__global__ __launch_bounds__(256)
void cvt_kernel(const float* __restrict__ in, f16* __restrict__ hi, f16* __restrict__ lo)
{
    int i = (blockIdx.x * 256 + threadIdx.x) * 4;
    float4 v = *(const float4*)(in + i);
    uint32_t h0, l0, h1, l1;
    split2(v.x, v.y, h0, l0);
    split2(v.z, v.w, h1, l1);
    ((uint32_t*)(hi + i))[0] = h0; ((uint32_t*)(hi + i))[1] = h1;
    ((uint32_t*)(lo + i))[0] = l0; ((uint32_t*)(lo + i))[1] = l1;
}

// fp32 -> fp16 (hi only)
__global__ __launch_bounds__(256)
void cvt_hi_kernel(const float* __restrict__ in, f16* __restrict__ hi)
{
    int i = (blockIdx.x * 256 + threadIdx.x) * 4;
    float4 v = *(const float4*)(in + i);
    ((uint32_t*)(hi + i))[0] = pack2h(v.x, v.y);
    ((uint32_t*)(hi + i))[1] = pack2h(v.z, v.w);
}

// mask(int) -> float addend (0 or -1e9)
__global__ __launch_bounds__(256)
void maskcvt_kernel(const int* __restrict__ mask, float* __restrict__ mf)
{
    int i = (blockIdx.x * 256 + threadIdx.x) * 4;
    int4 m = *(const int4*)(mask + i);
    float4 v;
    v.x = m.x ? 0.f : -1e9f;
    v.y = m.y ? 0.f : -1e9f;
    v.z = m.z ? 0.f : -1e9f;
    v.w = m.w ? 0.f : -1e9f;
    *(float4*)(mf + i) = v;
}

// ---------------------------------------------------------------------------
// Fused QKV projection GEMM. grid (24, 64). Uniform 2-pass (Ahi+Alo)·Wh;
// single-fp16 output scattered to (b,h,s,d).
// ---------------------------------------------------------------------------
static const int QKV_SMEM = 3 * 3 * 16384;  // 3 stages x 48KB

__global__ __launch_bounds__(256)
void gemm_qkv(const f16* __restrict__ Ahi, const f16* __restrict__ Alo,
              const f16* __restrict__ Wh_base,
              const float* __restrict__ bq, const float* __restrict__ bk,
              const float* __restrict__ bv,
              f16* __restrict__ Qd, f16* __restrict__ Kd, f16* __restrict__ Vd)
{
    extern __shared__ __align__(1024) char smem[];
    const int K = 1024;
    const int tid = threadIdx.x;
    const int wid = tid >> 5;
    const int lid = tid & 31;
    const int m0 = blockIdx.y * 128;
    const int wsel = blockIdx.x >> 3;            // 0=Q 1=K 2=V
    const int n0 = (blockIdx.x & 7) * 128;
    const int wm = wid & 1;
    const int wn = wid >> 1;

    const f16* Whi = Wh_base + (size_t)wsel * DM * DM;
    const float* bias = (wsel == 0) ? bq : (wsel == 1) ? bk : bv;

    const uint32_t sb = s2u(smem);

    auto load_stage = [&](int kc, int buf) {
        const f16* srcs[3] = {Ahi + (size_t)m0 * K + kc * 64,
                              Alo + (size_t)m0 * K + kc * 64,
                              Whi + (size_t)n0 * K + kc * 64};
        const uint32_t bufo = buf * 49152;
#pragma unroll
        for (int t = 0; t < 3; t++) {
#pragma unroll
            for (int it = 0; it < 4; it++) {
                const int idx = tid + it * 256;
                const int row = idx >> 3;
                const int u = idx & 7;
                const uint32_t dst = sb + bufo + t * 16384 + SWZ(idx * 16);
                CP16(dst, srcs[t] + (size_t)row * K + u * 8);
            }
        }
    };

    float acc[4][4][4];
#pragma unroll
    for (int a = 0; a < 4; a++)
#pragma unroll
        for (int b = 0; b < 4; b++)
#pragma unroll
            for (int c = 0; c < 4; c++) acc[a][b][c] = 0.f;

    load_stage(0, 0); CP_COMMIT();
    load_stage(1, 1); CP_COMMIT();
    load_stage(2, 2); CP_COMMIT();

    for (int kc = 0; kc < 16; kc++) {
        CP_WAIT2();
        __syncthreads();
        const int bi = kc % 3;
        const uint32_t bufo = sb + bi * 49152;

#pragma unroll
        for (int ks = 0; ks < 4; ks++) {
            uint32_t ah[4][4], al[4][4];
#pragma unroll
            for (int mf = 0; mf < 4; mf++) {
                const int row = wm * 64 + mf * 16 + (lid & 15);
                const int u = ks * 2 + (lid >> 4);
                const uint32_t off = SWZ(row * 128 + u * 16);
                ldsm4(ah[mf], bufo + off);
                ldsm4(al[mf], bufo + 16384 + off);
            }
#pragma unroll
            for (int nf2 = 0; nf2 < 2; nf2++) {
                const int row = wn * 32 + nf2 * 16 + ((lid >> 4) << 3) + (lid & 7);
                const int u = ks * 2 + ((lid >> 3) & 1);
                const uint32_t off = SWZ(row * 128 + u * 16);
                uint32_t bh[4];
                ldsm4(bh, bufo + 32768 + off);
#pragma unroll
                for (int mf = 0; mf < 4; mf++) {
                    mma16816(acc[mf][nf2 * 2],     ah[mf], bh);
                    mma16816(acc[mf][nf2 * 2],     al[mf], bh);
                    mma16816(acc[mf][nf2 * 2 + 1], ah[mf], bh + 2);
                    mma16816(acc[mf][nf2 * 2 + 1], al[mf], bh + 2);
                }
            }
        }
        __syncthreads();
        if (kc + 3 < 16) load_stage(kc + 3, bi);
        CP_COMMIT();
    }

    // epilogue: scatter single fp16 to (b,h,s,d)
    f16* Out = (wsel == 0) ? Qd : (wsel == 1) ? Kd : Vd;
#pragma unroll
    for (int mf = 0; mf < 4; mf++) {
#pragma unroll
        for (int nf = 0; nf < 4; nf++) {
            const int n = n0 + wn * 32 + nf * 8 + (lid & 3) * 2;
            const int r0 = m0 + wm * 64 + mf * 16 + (lid >> 2);
            const float b0 = bias[n], b1 = bias[n + 1];
            const int h = n >> 6, d = n & 63;
#pragma unroll
            for (int rr = 0; rr < 2; rr++) {
                const int r = r0 + rr * 8;
                const int b = r >> 11, s = r & (S_ - 1);
                const size_t idx = ((((size_t)b * NH + h) * S_ + s) * DK) + d;
                *(uint32_t*)(Out + idx) =
                    pack2h(acc[mf][nf][rr * 2] + b0, acc[mf][nf][rr * 2 + 1] + b1);
            }
        }
    }
}

// ---------------------------------------------------------------------------
// Output GEMM: AO (single fp16) x (Whi + Wlo), 2-pass, fp32 row-major out.
// 3 smem tiles/stage (AO, Wh, Wl), 3 stages = 144KB.
// ---------------------------------------------------------------------------
static const int OUT_SMEM = 3 * 3 * 16384;  // 144KB

__global__ __launch_bounds__(256)
void gemm_out(const f16* __restrict__ A,
              const f16* __restrict__ Whi, const f16* __restrict__ Wlo,
              const float* __restrict__ bias, float* __restrict__ Cf)
{
    extern __shared__ __align__(1024) char smem[];
    const int K = 1024;
    const int tid = threadIdx.x;
    const int wid = tid >> 5;
    const int lid = tid & 31;
    const int m0 = blockIdx.y * 128;
    const int n0 = blockIdx.x * 128;
    const int wm = wid & 1;
    const int wn = wid >> 1;

    const uint32_t sb = s2u(smem);

    auto load_stage = [&](int kc, int buf) {
        const f16* srcs[3] = {A   + (size_t)m0 * K + kc * 64,
                              Whi + (size_t)n0 * K + kc * 64,
                              Wlo + (size_t)n0 * K + kc * 64};
        const uint32_t bufo = buf * 49152;
#pragma unroll
        for (int t = 0; t < 3; t++) {
#pragma unroll
            for (int it = 0; it < 4; it++) {
                const int idx = tid + it * 256;
                const int row = idx >> 3;
                const int u = idx & 7;
                const uint32_t dst = sb + bufo + t * 16384 + SWZ(idx * 16);
                CP16(dst, srcs[t] + (size_t)row * K + u * 8);
            }
        }
    };

    float acc[4][4][4];
#pragma unroll
    for (int a = 0; a < 4; a++)
#pragma unroll
        for (int b = 0; b < 4; b++)
#pragma unroll
            for (int c = 0; c < 4; c++) acc[a][b][c] = 0.f;

    load_stage(0, 0); CP_COMMIT();
    load_stage(1, 1); CP_COMMIT();
    load_stage(2, 2); CP_COMMIT();

    for (int kc = 0; kc < 16; kc++) {
        CP_WAIT2();
        __syncthreads();
        const int bi = kc % 3;
        const uint32_t bufo = sb + bi * 49152;

#pragma unroll
        for (int ks = 0; ks < 4; ks++) {
            uint32_t af[4][4];
#pragma unroll
            for (int mf = 0; mf < 4; mf++) {
                const int row = wm * 64 + mf * 16 + (lid & 15);
                const int u = ks * 2 + (lid >> 4);
                const uint32_t off = SWZ(row * 128 + u * 16);
                ldsm4(af[mf], bufo + off);
            }
#pragma unroll
            for (int nf2 = 0; nf2 < 2; nf2++) {
                const int row = wn * 32 + nf2 * 16 + ((lid >> 4) << 3) + (lid & 7);
                const int u = ks * 2 + ((lid >> 3) & 1);
                const uint32_t off = SWZ(row * 128 + u * 16);
                uint32_t bh[4], bl[4];
                ldsm4(bh, bufo + 16384 + off);
                ldsm4(bl, bufo + 32768 + off);
#pragma unroll
                for (int mf = 0; mf < 4; mf++) {
                    mma16816(acc[mf][nf2 * 2],     af[mf], bh);
                    mma16816(acc[mf][nf2 * 2],     af[mf], bl);
                    mma16816(acc[mf][nf2 * 2 + 1], af[mf], bh + 2);
                    mma16816(acc[mf][nf2 * 2 + 1], af[mf], bl + 2);
                }
            }
        }
        __syncthreads();
        if (kc + 3 < 16) load_stage(kc + 3, bi);
        CP_COMMIT();
    }

#pragma unroll
    for (int mf = 0; mf < 4; mf++) {
#pragma unroll
        for (int nf = 0; nf < 4; nf++) {
            const int n = n0 + wn * 32 + nf * 8 + (lid & 3) * 2;
            const int r0 = m0 + wm * 64 + mf * 16 + (lid >> 2);
            const int r1 = r0 + 8;
            const float b0 = bias[n], b1 = bias[n + 1];
            *(float2*)(Cf + (size_t)r0 * 1024 + n) =
                make_float2(acc[mf][nf][0] + b0, acc[mf][nf][1] + b1);
            *(float2*)(Cf + (size_t)r1 * 1024 + n) =
                make_float2(acc[mf][nf][2] + b0, acc[mf][nf][3] + b1);
        }
    }
}

// ---------------------------------------------------------------------------
// Flash attention, fp16 mma. Single-fp16 Q/K/V/P: 1-pass QK, 1-pass PV.
// cp.async double-buffered, log2 softmax, float mask addend, rescale skip.
// AO written as single fp16.
// ---------------------------------------------------------------------------
// Per-buffer layout: K(16K) V(16K) maskf(512B) = 33280 B
static const int ATTN_BUF  = 33280;
static const int ATTN_SMEM = 2 * ATTN_BUF;

__global__ __launch_bounds__(256)
void attn_mma(const f16* __restrict__ Qg,
              const f16* __restrict__ Kg,  const f16* __restrict__ Vg,
              const float* __restrict__ maskf,
              f16* __restrict__ AO)
{
    extern __shared__ __align__(1024) char smem[];
    const uint32_t sb = s2u(smem);

    const int tid = threadIdx.x;
    const int wid = tid >> 5;
    const int lid = tid & 31;
    const int bh = blockIdx.y;
    const int b = bh >> 4, h = bh & 15;
    const int q0 = blockIdx.x * 128 + wid * 16;

    const size_t bho = (size_t)bh * S_ * DK;

    auto load_chunk = [&](int ch, int buf) {
        const uint32_t bo = sb + buf * ATTN_BUF;
        const char* kh = (const char*)(Kg + bho + (size_t)ch * 128 * DK);
        const char* vh = (const char*)(Vg + bho + (size_t)ch * 128 * DK);
#pragma unroll
        for (int it = 0; it < 4; it++) {
            const int idx = tid + it * 256;
            const uint32_t sw = SWZ(idx * 16);
            CP16(bo + sw,         kh + idx * 16);
            CP16(bo + 16384 + sw, vh + idx * 16);
        }
        if (tid < 128)
            CP4(bo + 32768 + tid * 4, maskf + b * S_ + ch * 128 + tid);
    };

    // Q fragments (pre-scaled by 0.125 via f16x2 multiply: exact)
    uint32_t qh[4][4];
    const uint32_t eighth = 0x30003000u;  // fp16 0.125 x2
#pragma unroll
    for (int ks = 0; ks < 4; ks++) {
        const int c2 = ks * 16 + (lid & 3) * 2;
        const int r0 = q0 + (lid >> 2), r1 = r0 + 8;
        const uint32_t* qp = (const uint32_t*)(Qg + bho);
        uint32_t a0 = qp[(r0 * DK + c2) >> 1];
        uint32_t a1 = qp[(r1 * DK + c2) >> 1];
        uint32_t a2 = qp[(r0 * DK + c2 + 8) >> 1];
        uint32_t a3 = qp[(r1 * DK + c2 + 8) >> 1];
        asm("mul.rn.f16x2 %0, %1, %2;" : "=r"(qh[ks][0]) : "r"(a0), "r"(eighth));
        asm("mul.rn.f16x2 %0, %1, %2;" : "=r"(qh[ks][1]) : "r"(a1), "r"(eighth));
        asm("mul.rn.f16x2 %0, %1, %2;" : "=r"(qh[ks][2]) : "r"(a2), "r"(eighth));
        asm("mul.rn.f16x2 %0, %1, %2;" : "=r"(qh[ks][3]) : "r"(a3), "r"(eighth));
    }

    float o[8][4];
#pragma unroll
    for (int j = 0; j < 8; j++)
#pragma unroll
        for (int c = 0; c < 4; c++) o[j][c] = 0.f;
    float mA = -1e30f, mB = -1e30f, lA = 0.f, lB = 0.f;

    load_chunk(0, 0); CP_COMMIT();
    load_chunk(1, 1); CP_COMMIT();

    for (int ch = 0; ch < 16; ch++) {
        CP_WAIT1();
        __syncthreads();
        const int bi = ch & 1;
        const uint32_t sK  = sb + bi * ATTN_BUF;
        const uint32_t sV  = sK + 16384;
        const float* mskf = (const float*)(smem + bi * ATTN_BUF + 32768);

#pragma unroll
        for (int sub = 0; sub < 2; sub++) {
            float sc[8][4];
#pragma unroll
            for (int nf = 0; nf < 8; nf++)
#pragma unroll
                for (int c = 0; c < 4; c++) sc[nf][c] = 0.f;

            // scores: Q (16xk64) . K^T  (single pass)
#pragma unroll
            for (int nf2 = 0; nf2 < 4; nf2++) {
                const int row = sub * 64 + nf2 * 16 + ((lid >> 4) << 3) + (lid & 7);
#pragma unroll
                for (int ks = 0; ks < 4; ks++) {
                    const int u = ks * 2 + ((lid >> 3) & 1);
                    const uint32_t off = SWZ(row * 128 + u * 16);
                    uint32_t kb[4];
                    ldsm4(kb, sK + off);
                    mma16816(sc[nf2 * 2],     qh[ks], kb);
                    mma16816(sc[nf2 * 2 + 1], qh[ks], kb + 2);
                }
            }

            // mask + convert to log2 domain: s' = s*log2e + maskadd
#pragma unroll
            for (int nf = 0; nf < 8; nf++) {
                const int k0 = sub * 64 + nf * 8 + (lid & 3) * 2;
                const float ma0 = mskf[k0], ma1 = mskf[k0 + 1];
                sc[nf][0] = fmaf(sc[nf][0], LOG2E, ma0);
                sc[nf][1] = fmaf(sc[nf][1], LOG2E, ma1);
                sc[nf][2] = fmaf(sc[nf][2], LOG2E, ma0);
                sc[nf][3] = fmaf(sc[nf][3], LOG2E, ma1);
            }

            // online softmax (log2 domain)
            float mxA = -1e30f, mxB = -1e30f;
#pragma unroll
            for (int nf = 0; nf < 8; nf++) {
                mxA = fmaxf(mxA, fmaxf(sc[nf][0], sc[nf][1]));
                mxB = fmaxf(mxB, fmaxf(sc[nf][2], sc[nf][3]));
            }
            mxA = fmaxf(mxA, __shfl_xor_sync(0xffffffffu, mxA, 1));
            mxA = fmaxf(mxA, __shfl_xor_sync(0xffffffffu, mxA, 2));
            mxB = fmaxf(mxB, __shfl_xor_sync(0xffffffffu, mxB, 1));
            mxB = fmaxf(mxB, __shfl_xor_sync(0xffffffffu, mxB, 2));
            const float mAn = fmaxf(mA, mxA), mBn = fmaxf(mB, mxB);
            if (!__all_sync(0xffffffffu, (mAn == mA) && (mBn == mB))) {
                const float fA = exp2f(mA - mAn), fB = exp2f(mB - mBn);
                lA *= fA; lB *= fB;
#pragma unroll
                for (int j = 0; j < 8; j++) {
                    o[j][0] *= fA; o[j][1] *= fA;
                    o[j][2] *= fB; o[j][3] *= fB;
                }
            }
            mA = mAn; mB = mBn;
#pragma unroll
            for (int nf = 0; nf < 8; nf++) {
                sc[nf][0] = exp2f(sc[nf][0] - mA);
                sc[nf][1] = exp2f(sc[nf][1] - mA);
                sc[nf][2] = exp2f(sc[nf][2] - mB);
                sc[nf][3] = exp2f(sc[nf][3] - mB);
                lA += sc[nf][0] + sc[nf][1];
                lB += sc[nf][2] + sc[nf][3];
            }

            // P·V (P packed single-fp16; single pass)
#pragma unroll
            for (int kk = 0; kk < 4; kk++) {
                uint32_t ph[4];
                ph[0] = pack2h(sc[2 * kk][0],     sc[2 * kk][1]);
                ph[1] = pack2h(sc[2 * kk][2],     sc[2 * kk][3]);
                ph[2] = pack2h(sc[2 * kk + 1][0], sc[2 * kk + 1][1]);
                ph[3] = pack2h(sc[2 * kk + 1][2], sc[2 * kk + 1][3]);
                const int row = sub * 64 + kk * 16 + (((lid >> 3) & 1) << 3) + (lid & 7);
#pragma unroll
                for (int j2 = 0; j2 < 4; j2++) {
                    const int u = 2 * j2 + (lid >> 4);
                    const uint32_t off = SWZ(row * 128 + u * 16);
                    uint32_t vb[4];
                    ldsm4t(vb, sV + off);
                    mma16816(o[j2 * 2],     ph, vb);
                    mma16816(o[j2 * 2 + 1], ph, vb + 2);
                }
            }
        }

        __syncthreads();
        if (ch + 2 < 16) load_chunk(ch + 2, bi);
        CP_COMMIT();
    }

    // final row sums and store (single fp16 AO)
    lA += __shfl_xor_sync(0xffffffffu, lA, 1);
    lA += __shfl_xor_sync(0xffffffffu, lA, 2);
    lB += __shfl_xor_sync(0xffffffffu, lB, 1);
    lB += __shfl_xor_sync(0xffffffffu, lB, 2);
    const float invA = 1.f / lA, invB = 1.f / lB;

    const int s0 = q0 + (lid >> 2), s1 = s0 + 8;
#pragma unroll
    for (int j = 0; j < 8; j++) {
        const int col = h * DK + j * 8 + (lid & 3) * 2;
        const size_t i0 = ((size_t)(b * S_ + s0)) * DM + col;
        const size_t i1 = ((size_t)(b * S_ + s1)) * DM + col;
        *(uint32_t*)(AO + i0) = pack2h(o[j][0] * invA, o[j][1] * invA);
        *(uint32_t*)(AO + i1) = pack2h(o[j][2] * invB, o[j][3] * invB);
    }
}

// ---------------------------------------------------------------------------
// Launch
// ---------------------------------------------------------------------------
extern "C" void kernel_launch(void* const* d_in, const int* in_sizes, int n_in,
                              void* d_out, int out_size)
{
    (void)in_sizes; (void)n_in; (void)out_size;
    const float* x    = (const float*)d_in[0];
    const int*   mask = (const int*)  d_in[1];
    const float* Wq   = (const float*)d_in[2];
    const float* bq   = (const float*)d_in[3];
    const float* Wk   = (const float*)d_in[4];
    const float* bk   = (const float*)d_in[5];
    const float* Wv   = (const float*)d_in[6];
    const float* bv   = (const float*)d_in[7];
    const float* Wo   = (const float*)d_in[8];
    const float* bo   = (const float*)d_in[9];
    float* out = (float*)d_out;

    f16 *xhi, *xlo, *whi, *wlo, *qd, *kd, *vd, *ao;
    float* maskf;
    cudaGetSymbolAddress((void**)&xhi,   g_xhi);
    cudaGetSymbolAddress((void**)&xlo,   g_xlo);
    cudaGetSymbolAddress((void**)&whi,   g_whi);
    cudaGetSymbolAddress((void**)&wlo,   g_wlo);
    cudaGetSymbolAddress((void**)&qd,    g_q);
    cudaGetSymbolAddress((void**)&kd,    g_k);
    cudaGetSymbolAddress((void**)&vd,    g_v);
    cudaGetSymbolAddress((void**)&ao,    g_ao);
    cudaGetSymbolAddress((void**)&maskf, g_maskf);

    cudaFuncSetAttribute(gemm_qkv, cudaFuncAttributeMaxDynamicSharedMemorySize, QKV_SMEM);
    cudaFuncSetAttribute(gemm_out, cudaFuncAttributeMaxDynamicSharedMemorySize, OUT_SMEM);
    cudaFuncSetAttribute(attn_mma, cudaFuncAttributeMaxDynamicSharedMemorySize, ATTN_SMEM);

    cvt_kernel<<<MTOT * DM / 1024, 256>>>(x, xhi, xlo);
    cvt_hi_kernel<<<DM * DM / 1024, 256>>>(Wq, whi + 0 * DM * DM);
    cvt_hi_kernel<<<DM * DM / 1024, 256>>>(Wk, whi + 1 * DM * DM);
    cvt_hi_kernel<<<DM * DM / 1024, 256>>>(Wv, whi + 2 * DM * DM);
    cvt_kernel<<<DM * DM / 1024, 256>>>(Wo, whi + 3 * DM * DM, wlo);
    maskcvt_kernel<<<MTOT / 1024, 256>>>(mask, maskf);

    gemm_qkv<<<dim3(24, MTOT / 128), 256, QKV_SMEM>>>(
        xhi, xlo, whi, bq, bk, bv, qd, kd, vd);

    attn_mma<<<dim3(S_ / 128, B_ * NH), 256, ATTN_SMEM>>>(qd, kd, vd, maskf, ao);

    gemm_out<<<dim3(DM / 128, MTOT / 128), 256, OUT_SMEM>>>(
        ao, whi + 3 * DM * DM, wlo, bo, out);
}

// round 16
// speedup vs baseline: 8.4888x; 1.2747x over previous
#include <cuda_runtime.h>
#include <cuda_fp16.h>
#include <cstdint>
#include <math.h>

#define B_   4
#define S_   2048
#define DM   1024
#define NH   16
#define DK   64
#define MTOT (B_ * S_)   // 8192

#define LOG2E 1.4426950408889634f

typedef __half  f16;

// ---------------------------------------------------------------------------
// Scratch
// ---------------------------------------------------------------------------
__device__ f16 g_x[MTOT * DM];
__device__ f16 g_whi[4][DM * DM];
__device__ f16 g_wlo[DM * DM];       // only Wo keeps a lo part
__device__ f16 g_q[MTOT * DM];
__device__ f16 g_k[MTOT * DM];
__device__ f16 g_v[MTOT * DM];
__device__ f16 g_ao[MTOT * DM];
__device__ float g_maskf[MTOT];

// ---------------------------------------------------------------------------
// helpers
// ---------------------------------------------------------------------------
__device__ __forceinline__ uint32_t s2u(const void* p) {
    uint32_t a;
    asm("{ .reg .u64 t; cvta.to.shared.u64 t, %1; cvt.u32.u64 %0, t; }"
        : "=r"(a) : "l"(p));
    return a;
}

#define SWZ(x) ((x) ^ (((x) >> 3) & 0x70))

__device__ __forceinline__ void ldsm4(uint32_t* r, uint32_t addr) {
    asm volatile("ldmatrix.sync.aligned.m8n8.x4.shared.b16 {%0,%1,%2,%3}, [%4];"
        : "=r"(r[0]), "=r"(r[1]), "=r"(r[2]), "=r"(r[3]) : "r"(addr));
}
__device__ __forceinline__ void ldsm4t(uint32_t* r, uint32_t addr) {
    asm volatile("ldmatrix.sync.aligned.m8n8.x4.trans.shared.b16 {%0,%1,%2,%3}, [%4];"
        : "=r"(r[0]), "=r"(r[1]), "=r"(r[2]), "=r"(r[3]) : "r"(addr));
}
__device__ __forceinline__ void mma16816(float* c, const uint32_t* a, const uint32_t* b) {
    asm volatile(
        "mma.sync.aligned.m16n8k16.row.col.f32.f16.f16.f32 "
        "{%0,%1,%2,%3}, {%4,%5,%6,%7}, {%8,%9}, {%0,%1,%2,%3};"
        : "+f"(c[0]), "+f"(c[1]), "+f"(c[2]), "+f"(c[3])
        : "r"(a[0]), "r"(a[1]), "r"(a[2]), "r"(a[3]), "r"(b[0]), "r"(b[1]));
}

// split (v0,v1) into packed fp16 hi and lo parts
__device__ __forceinline__ void split2(float v0, float v1, uint32_t& h, uint32_t& l) {
    f16 h0 = __float2half_rn(v0), h1 = __float2half_rn(v1);
    f16 l0 = __float2half_rn(v0 - __half2float(h0));
    f16 l1 = __float2half_rn(v1 - __half2float(h1));
    __half2 hv = __halves2half2(h0, h1);
    __half2 lv = __halves2half2(l0, l1);
    h = *(uint32_t*)&hv; l = *(uint32_t*)&lv;
}
__device__ __forceinline__ uint32_t pack2h(float v0, float v1) {
    __half2 hv = __floats2half2_rn(v0, v1);
    return *(uint32_t*)&hv;
}

#define CP16(dst, src) \
    asm volatile("cp.async.cg.shared.global [%0], [%1], 16;" :: "r"(dst), "l"(src))
#define CP4(dst, src) \
    asm volatile("cp.async.ca.shared.global [%0], [%1], 4;" :: "r"(dst), "l"(src))
#define CP_COMMIT() asm volatile("cp.async.commit_group;")
#define CP_WAIT1()  asm volatile("cp.async.wait_group 1;")
#define CP_WAIT2()  asm volatile("cp.async.wait_group 2;")

// ---------------------------------------------------------------------------
// fp32 -> fp16 (hi only), 4 independent float4 loads per thread (MLP=4).
// One block handles 4096 consecutive floats.
// ---------------------------------------------------------------------------
__global__ __launch_bounds__(256)
void cvt_hi4_kernel(const float* __restrict__ in, f16* __restrict__ hi)
{
    const int base = blockIdx.x * 4096 + threadIdx.x * 4;
    float4 v0 = *(const float4*)(in + base);
    float4 v1 = *(const float4*)(in + base + 1024);
    float4 v2 = *(const float4*)(in + base + 2048);
    float4 v3 = *(const float4*)(in + base + 3072);
    ((uint32_t*)(hi + base))[0] = pack2h(v0.x, v0.y);
    ((uint32_t*)(hi + base))[1] = pack2h(v0.z, v0.w);
    ((uint32_t*)(hi + base + 1024))[0] = pack2h(v1.x, v1.y);
    ((uint32_t*)(hi + base + 1024))[1] = pack2h(v1.z, v1.w);
    ((uint32_t*)(hi + base + 2048))[0] = pack2h(v2.x, v2.y);
    ((uint32_t*)(hi + base + 2048))[1] = pack2h(v2.z, v2.w);
    ((uint32_t*)(hi + base + 3072))[0] = pack2h(v3.x, v3.y);
    ((uint32_t*)(hi + base + 3072))[1] = pack2h(v3.z, v3.w);
}

// fp32 -> fp16 hi/lo split, same ILP pattern (for Wo only)
__global__ __launch_bounds__(256)
void cvt_split4_kernel(const float* __restrict__ in,
                       f16* __restrict__ hi, f16* __restrict__ lo)
{
    const int base = blockIdx.x * 4096 + threadIdx.x * 4;
#pragma unroll
    for (int it = 0; it < 4; it++) {
        const int i = base + it * 1024;
        float4 v = *(const float4*)(in + i);
        uint32_t h0, l0, h1, l1;
        split2(v.x, v.y, h0, l0);
        split2(v.z, v.w, h1, l1);
        ((uint32_t*)(hi + i))[0] = h0; ((uint32_t*)(hi + i))[1] = h1;
        ((uint32_t*)(lo + i))[0] = l0; ((uint32_t*)(lo + i))[1] = l1;
    }
}

// mask(int) -> float addend (0 or -1e9)
__global__ __launch_bounds__(256)
void maskcvt_kernel(const int* __restrict__ mask, float* __restrict__ mf)
{
    int i = (blockIdx.x * 256 + threadIdx.x) * 4;
    int4 m = *(const int4*)(mask + i);
    float4 v;
    v.x = m.x ? 0.f : -1e9f;
    v.y = m.y ? 0.f : -1e9f;
    v.z = m.z ? 0.f : -1e9f;
    v.w = m.w ? 0.f : -1e9f;
    *(float4*)(mf + i) = v;
}

// ---------------------------------------------------------------------------
// Fused QKV projection GEMM. grid (24, 64). Single-pass fp16 A x fp16 W;
// fp32 accum; single-fp16 output scattered to (b,h,s,d).
// ---------------------------------------------------------------------------
static const int QKV_SMEM = 3 * 2 * 16384;  // 3 stages x 32KB

__global__ __launch_bounds__(256)
void gemm_qkv(const f16* __restrict__ A, const f16* __restrict__ Wh_base,
              const float* __restrict__ bq, const float* __restrict__ bk,
              const float* __restrict__ bv,
              f16* __restrict__ Qd, f16* __restrict__ Kd, f16* __restrict__ Vd)
{
    extern __shared__ __align__(1024) char smem[];
    const int K = 1024;
    const int tid = threadIdx.x;
    const int wid = tid >> 5;
    const int lid = tid & 31;
    const int m0 = blockIdx.y * 128;
    const int wsel = blockIdx.x >> 3;            // 0=Q 1=K 2=V
    const int n0 = (blockIdx.x & 7) * 128;
    const int wm = wid & 1;
    const int wn = wid >> 1;

    const f16* Whi = Wh_base + (size_t)wsel * DM * DM;
    const float* bias = (wsel == 0) ? bq : (wsel == 1) ? bk : bv;

    const uint32_t sb = s2u(smem);

    auto load_stage = [&](int kc, int buf) {
        const f16* srcs[2] = {A   + (size_t)m0 * K + kc * 64,
                              Whi + (size_t)n0 * K + kc * 64};
        const uint32_t bufo = buf * 32768;
#pragma unroll
        for (int t = 0; t < 2; t++) {
#pragma unroll
            for (int it = 0; it < 4; it++) {
                const int idx = tid + it * 256;
                const int row = idx >> 3;
                const int u = idx & 7;
                const uint32_t dst = sb + bufo + t * 16384 + SWZ(idx * 16);
                CP16(dst, srcs[t] + (size_t)row * K + u * 8);
            }
        }
    };

    float acc[4][4][4];
#pragma unroll
    for (int a = 0; a < 4; a++)
#pragma unroll
        for (int b = 0; b < 4; b++)
#pragma unroll
            for (int c = 0; c < 4; c++) acc[a][b][c] = 0.f;

    load_stage(0, 0); CP_COMMIT();
    load_stage(1, 1); CP_COMMIT();
    load_stage(2, 2); CP_COMMIT();

    for (int kc = 0; kc < 16; kc++) {
        CP_WAIT2();
        __syncthreads();
        const int bi = kc % 3;
        const uint32_t bufo = sb + bi * 32768;

#pragma unroll
        for (int ks = 0; ks < 4; ks++) {
            uint32_t af[4][4];
#pragma unroll
            for (int mf = 0; mf < 4; mf++) {
                const int row = wm * 64 + mf * 16 + (lid & 15);
                const int u = ks * 2 + (lid >> 4);
                const uint32_t off = SWZ(row * 128 + u * 16);
                ldsm4(af[mf], bufo + off);
            }
#pragma unroll
            for (int nf2 = 0; nf2 < 2; nf2++) {
                const int row = wn * 32 + nf2 * 16 + ((lid >> 4) << 3) + (lid & 7);
                const int u = ks * 2 + ((lid >> 3) & 1);
                const uint32_t off = SWZ(row * 128 + u * 16);
                uint32_t bh[4];
                ldsm4(bh, bufo + 16384 + off);
#pragma unroll
                for (int mf = 0; mf < 4; mf++) {
                    mma16816(acc[mf][nf2 * 2],     af[mf], bh);
                    mma16816(acc[mf][nf2 * 2 + 1], af[mf], bh + 2);
                }
            }
        }
        __syncthreads();
        if (kc + 3 < 16) load_stage(kc + 3, bi);
        CP_COMMIT();
    }

    // epilogue: scatter single fp16 to (b,h,s,d)
    f16* Out = (wsel == 0) ? Qd : (wsel == 1) ? Kd : Vd;
#pragma unroll
    for (int mf = 0; mf < 4; mf++) {
#pragma unroll
        for (int nf = 0; nf < 4; nf++) {
            const int n = n0 + wn * 32 + nf * 8 + (lid & 3) * 2;
            const int r0 = m0 + wm * 64 + mf * 16 + (lid >> 2);
            const float b0 = bias[n], b1 = bias[n + 1];
            const int h = n >> 6, d = n & 63;
#pragma unroll
            for (int rr = 0; rr < 2; rr++) {
                const int r = r0 + rr * 8;
                const int b = r >> 11, s = r & (S_ - 1);
                const size_t idx = ((((size_t)b * NH + h) * S_ + s) * DK) + d;
                *(uint32_t*)(Out + idx) =
                    pack2h(acc[mf][nf][rr * 2] + b0, acc[mf][nf][rr * 2 + 1] + b1);
            }
        }
    }
}

// ---------------------------------------------------------------------------
// Output GEMM: AO (single fp16) x (Whi + Wlo), 2-pass, fp32 row-major out.
// ---------------------------------------------------------------------------
static const int OUT_SMEM = 3 * 3 * 16384;  // 144KB

__global__ __launch_bounds__(256)
void gemm_out(const f16* __restrict__ A,
              const f16* __restrict__ Whi, const f16* __restrict__ Wlo,
              const float* __restrict__ bias, float* __restrict__ Cf)
{
    extern __shared__ __align__(1024) char smem[];
    const int K = 1024;
    const int tid = threadIdx.x;
    const int wid = tid >> 5;
    const int lid = tid & 31;
    const int m0 = blockIdx.y * 128;
    const int n0 = blockIdx.x * 128;
    const int wm = wid & 1;
    const int wn = wid >> 1;

    const uint32_t sb = s2u(smem);

    auto load_stage = [&](int kc, int buf) {
        const f16* srcs[3] = {A   + (size_t)m0 * K + kc * 64,
                              Whi + (size_t)n0 * K + kc * 64,
                              Wlo + (size_t)n0 * K + kc * 64};
        const uint32_t bufo = buf * 49152;
#pragma unroll
        for (int t = 0; t < 3; t++) {
#pragma unroll
            for (int it = 0; it < 4; it++) {
                const int idx = tid + it * 256;
                const int row = idx >> 3;
                const int u = idx & 7;
                const uint32_t dst = sb + bufo + t * 16384 + SWZ(idx * 16);
                CP16(dst, srcs[t] + (size_t)row * K + u * 8);
            }
        }
    };

    float acc[4][4][4];
#pragma unroll
    for (int a = 0; a < 4; a++)
#pragma unroll
        for (int b = 0; b < 4; b++)
#pragma unroll
            for (int c = 0; c < 4; c++) acc[a][b][c] = 0.f;

    load_stage(0, 0); CP_COMMIT();
    load_stage(1, 1); CP_COMMIT();
    load_stage(2, 2); CP_COMMIT();

    for (int kc = 0; kc < 16; kc++) {
        CP_WAIT2();
        __syncthreads();
        const int bi = kc % 3;
        const uint32_t bufo = sb + bi * 49152;

#pragma unroll
        for (int ks = 0; ks < 4; ks++) {
            uint32_t af[4][4];
#pragma unroll
            for (int mf = 0; mf < 4; mf++) {
                const int row = wm * 64 + mf * 16 + (lid & 15);
                const int u = ks * 2 + (lid >> 4);
                const uint32_t off = SWZ(row * 128 + u * 16);
                ldsm4(af[mf], bufo + off);
            }
#pragma unroll
            for (int nf2 = 0; nf2 < 2; nf2++) {
                const int row = wn * 32 + nf2 * 16 + ((lid >> 4) << 3) + (lid & 7);
                const int u = ks * 2 + ((lid >> 3) & 1);
                const uint32_t off = SWZ(row * 128 + u * 16);
                uint32_t bh[4], bl[4];
                ldsm4(bh, bufo + 16384 + off);
                ldsm4(bl, bufo + 32768 + off);
#pragma unroll
                for (int mf = 0; mf < 4; mf++) {
                    mma16816(acc[mf][nf2 * 2],     af[mf], bh);
                    mma16816(acc[mf][nf2 * 2],     af[mf], bl);
                    mma16816(acc[mf][nf2 * 2 + 1], af[mf], bh + 2);
                    mma16816(acc[mf][nf2 * 2 + 1], af[mf], bl + 2);
                }
            }
        }
        __syncthreads();
        if (kc + 3 < 16) load_stage(kc + 3, bi);
        CP_COMMIT();
    }

#pragma unroll
    for (int mf = 0; mf < 4; mf++) {
#pragma unroll
        for (int nf = 0; nf < 4; nf++) {
            const int n = n0 + wn * 32 + nf * 8 + (lid & 3) * 2;
            const int r0 = m0 + wm * 64 + mf * 16 + (lid >> 2);
            const int r1 = r0 + 8;
            const float b0 = bias[n], b1 = bias[n + 1];
            *(float2*)(Cf + (size_t)r0 * 1024 + n) =
                make_float2(acc[mf][nf][0] + b0, acc[mf][nf][1] + b1);
            *(float2*)(Cf + (size_t)r1 * 1024 + n) =
                make_float2(acc[mf][nf][2] + b0, acc[mf][nf][3] + b1);
        }
    }
}

// ---------------------------------------------------------------------------
// Flash attention, fp16 mma. Single-fp16 Q/K/V/P: 1-pass QK, 1-pass PV.
// cp.async double-buffered, log2 softmax, float mask addend, rescale skip.
// AO written as single fp16.
// ---------------------------------------------------------------------------
static const int ATTN_BUF  = 33280;
static const int ATTN_SMEM = 2 * ATTN_BUF;

__global__ __launch_bounds__(256)
void attn_mma(const f16* __restrict__ Qg,
              const f16* __restrict__ Kg,  const f16* __restrict__ Vg,
              const float* __restrict__ maskf,
              f16* __restrict__ AO)
{
    extern __shared__ __align__(1024) char smem[];
    const uint32_t sb = s2u(smem);

    const int tid = threadIdx.x;
    const int wid = tid >> 5;
    const int lid = tid & 31;
    const int bh = blockIdx.y;
    const int b = bh >> 4, h = bh & 15;
    const int q0 = blockIdx.x * 128 + wid * 16;

    const size_t bho = (size_t)bh * S_ * DK;

    auto load_chunk = [&](int ch, int buf) {
        const uint32_t bo = sb + buf * ATTN_BUF;
        const char* kh = (const char*)(Kg + bho + (size_t)ch * 128 * DK);
        const char* vh = (const char*)(Vg + bho + (size_t)ch * 128 * DK);
#pragma unroll
        for (int it = 0; it < 4; it++) {
            const int idx = tid + it * 256;
            const uint32_t sw = SWZ(idx * 16);
            CP16(bo + sw,         kh + idx * 16);
            CP16(bo + 16384 + sw, vh + idx * 16);
        }
        if (tid < 128)
            CP4(bo + 32768 + tid * 4, maskf + b * S_ + ch * 128 + tid);
    };

    // Q fragments (pre-scaled by 0.125 via f16x2 multiply: exact)
    uint32_t qh[4][4];
    const uint32_t eighth = 0x30003000u;  // fp16 0.125 x2
#pragma unroll
    for (int ks = 0; ks < 4; ks++) {
        const int c2 = ks * 16 + (lid & 3) * 2;
        const int r0 = q0 + (lid >> 2), r1 = r0 + 8;
        const uint32_t* qp = (const uint32_t*)(Qg + bho);
        uint32_t a0 = qp[(r0 * DK + c2) >> 1];
        uint32_t a1 = qp[(r1 * DK + c2) >> 1];
        uint32_t a2 = qp[(r0 * DK + c2 + 8) >> 1];
        uint32_t a3 = qp[(r1 * DK + c2 + 8) >> 1];
        asm("mul.rn.f16x2 %0, %1, %2;" : "=r"(qh[ks][0]) : "r"(a0), "r"(eighth));
        asm("mul.rn.f16x2 %0, %1, %2;" : "=r"(qh[ks][1]) : "r"(a1), "r"(eighth));
        asm("mul.rn.f16x2 %0, %1, %2;" : "=r"(qh[ks][2]) : "r"(a2), "r"(eighth));
        asm("mul.rn.f16x2 %0, %1, %2;" : "=r"(qh[ks][3]) : "r"(a3), "r"(eighth));
    }

    float o[8][4];
#pragma unroll
    for (int j = 0; j < 8; j++)
#pragma unroll
        for (int c = 0; c < 4; c++) o[j][c] = 0.f;
    float mA = -1e30f, mB = -1e30f, lA = 0.f, lB = 0.f;

    load_chunk(0, 0); CP_COMMIT();
    load_chunk(1, 1); CP_COMMIT();

    for (int ch = 0; ch < 16; ch++) {
        CP_WAIT1();
        __syncthreads();
        const int bi = ch & 1;
        const uint32_t sK  = sb + bi * ATTN_BUF;
        const uint32_t sV  = sK + 16384;
        const float* mskf = (const float*)(smem + bi * ATTN_BUF + 32768);

#pragma unroll
        for (int sub = 0; sub < 2; sub++) {
            float sc[8][4];
#pragma unroll
            for (int nf = 0; nf < 8; nf++)
#pragma unroll
                for (int c = 0; c < 4; c++) sc[nf][c] = 0.f;

            // scores: Q (16xk64) . K^T  (single pass)
#pragma unroll
            for (int nf2 = 0; nf2 < 4; nf2++) {
                const int row = sub * 64 + nf2 * 16 + ((lid >> 4) << 3) + (lid & 7);
#pragma unroll
                for (int ks = 0; ks < 4; ks++) {
                    const int u = ks * 2 + ((lid >> 3) & 1);
                    const uint32_t off = SWZ(row * 128 + u * 16);
                    uint32_t kb[4];
                    ldsm4(kb, sK + off);
                    mma16816(sc[nf2 * 2],     qh[ks], kb);
                    mma16816(sc[nf2 * 2 + 1], qh[ks], kb + 2);
                }
            }

            // mask + convert to log2 domain
#pragma unroll
            for (int nf = 0; nf < 8; nf++) {
                const int k0 = sub * 64 + nf * 8 + (lid & 3) * 2;
                const float ma0 = mskf[k0], ma1 = mskf[k0 + 1];
                sc[nf][0] = fmaf(sc[nf][0], LOG2E, ma0);
                sc[nf][1] = fmaf(sc[nf][1], LOG2E, ma1);
                sc[nf][2] = fmaf(sc[nf][2], LOG2E, ma0);
                sc[nf][3] = fmaf(sc[nf][3], LOG2E, ma1);
            }

            // online softmax (log2 domain)
            float mxA = -1e30f, mxB = -1e30f;
#pragma unroll
            for (int nf = 0; nf < 8; nf++) {
                mxA = fmaxf(mxA, fmaxf(sc[nf][0], sc[nf][1]));
                mxB = fmaxf(mxB, fmaxf(sc[nf][2], sc[nf][3]));
            }
            mxA = fmaxf(mxA, __shfl_xor_sync(0xffffffffu, mxA, 1));
            mxA = fmaxf(mxA, __shfl_xor_sync(0xffffffffu, mxA, 2));
            mxB = fmaxf(mxB, __shfl_xor_sync(0xffffffffu, mxB, 1));
            mxB = fmaxf(mxB, __shfl_xor_sync(0xffffffffu, mxB, 2));
            const float mAn = fmaxf(mA, mxA), mBn = fmaxf(mB, mxB);
            if (!__all_sync(0xffffffffu, (mAn == mA) && (mBn == mB))) {
                const float fA = exp2f(mA - mAn), fB = exp2f(mB - mBn);
                lA *= fA; lB *= fB;
#pragma unroll
                for (int j = 0; j < 8; j++) {
                    o[j][0] *= fA; o[j][1] *= fA;
                    o[j][2] *= fB; o[j][3] *= fB;
                }
            }
            mA = mAn; mB = mBn;
#pragma unroll
            for (int nf = 0; nf < 8; nf++) {
                sc[nf][0] = exp2f(sc[nf][0] - mA);
                sc[nf][1] = exp2f(sc[nf][1] - mA);
                sc[nf][2] = exp2f(sc[nf][2] - mB);
                sc[nf][3] = exp2f(sc[nf][3] - mB);
                lA += sc[nf][0] + sc[nf][1];
                lB += sc[nf][2] + sc[nf][3];
            }

            // P·V (P packed single-fp16; single pass)
#pragma unroll
            for (int kk = 0; kk < 4; kk++) {
                uint32_t ph[4];
                ph[0] = pack2h(sc[2 * kk][0],     sc[2 * kk][1]);
                ph[1] = pack2h(sc[2 * kk][2],     sc[2 * kk][3]);
                ph[2] = pack2h(sc[2 * kk + 1][0], sc[2 * kk + 1][1]);
                ph[3] = pack2h(sc[2 * kk + 1][2], sc[2 * kk + 1][3]);
                const int row = sub * 64 + kk * 16 + (((lid >> 3) & 1) << 3) + (lid & 7);
#pragma unroll
                for (int j2 = 0; j2 < 4; j2++) {
                    const int u = 2 * j2 + (lid >> 4);
                    const uint32_t off = SWZ(row * 128 + u * 16);
                    uint32_t vb[4];
                    ldsm4t(vb, sV + off);
                    mma16816(o[j2 * 2],     ph, vb);
                    mma16816(o[j2 * 2 + 1], ph, vb + 2);
                }
            }
        }

        __syncthreads();
        if (ch + 2 < 16) load_chunk(ch + 2, bi);
        CP_COMMIT();
    }

    // final row sums and store (single fp16 AO)
    lA += __shfl_xor_sync(0xffffffffu, lA, 1);
    lA += __shfl_xor_sync(0xffffffffu, lA, 2);
    lB += __shfl_xor_sync(0xffffffffu, lB, 1);
    lB += __shfl_xor_sync(0xffffffffu, lB, 2);
    const float invA = 1.f / lA, invB = 1.f / lB;

    const int s0 = q0 + (lid >> 2), s1 = s0 + 8;
#pragma unroll
    for (int j = 0; j < 8; j++) {
        const int col = h * DK + j * 8 + (lid & 3) * 2;
        const size_t i0 = ((size_t)(b * S_ + s0)) * DM + col;
        const size_t i1 = ((size_t)(b * S_ + s1)) * DM + col;
        *(uint32_t*)(AO + i0) = pack2h(o[j][0] * invA, o[j][1] * invA);
        *(uint32_t*)(AO + i1) = pack2h(o[j][2] * invB, o[j][3] * invB);
    }
}

// ---------------------------------------------------------------------------
// Launch
// ---------------------------------------------------------------------------
extern "C" void kernel_launch(void* const* d_in, const int* in_sizes, int n_in,
                              void* d_out, int out_size)
{
    (void)in_sizes; (void)n_in; (void)out_size;
    const float* x    = (const float*)d_in[0];
    const int*   mask = (const int*)  d_in[1];
    const float* Wq   = (const float*)d_in[2];
    const float* bq   = (const float*)d_in[3];
    const float* Wk   = (const float*)d_in[4];
    const float* bk   = (const float*)d_in[5];
    const float* Wv   = (const float*)d_in[6];
    const float* bv   = (const float*)d_in[7];
    const float* Wo   = (const float*)d_in[8];
    const float* bo   = (const float*)d_in[9];
    float* out = (float*)d_out;

    f16 *xd, *whi, *wlo, *qd, *kd, *vd, *ao;
    float* maskf;
    cudaGetSymbolAddress((void**)&xd,    g_x);
    cudaGetSymbolAddress((void**)&whi,   g_whi);
    cudaGetSymbolAddress((void**)&wlo,   g_wlo);
    cudaGetSymbolAddress((void**)&qd,    g_q);
    cudaGetSymbolAddress((void**)&kd,    g_k);
    cudaGetSymbolAddress((void**)&vd,    g_v);
    cudaGetSymbolAddress((void**)&ao,    g_ao);
    cudaGetSymbolAddress((void**)&maskf, g_maskf);

    cudaFuncSetAttribute(gemm_qkv, cudaFuncAttributeMaxDynamicSharedMemorySize, QKV_SMEM);
    cudaFuncSetAttribute(gemm_out, cudaFuncAttributeMaxDynamicSharedMemorySize, OUT_SMEM);
    cudaFuncSetAttribute(attn_mma, cudaFuncAttributeMaxDynamicSharedMemorySize, ATTN_SMEM);

    cvt_hi4_kernel<<<MTOT * DM / 4096, 256>>>(x, xd);
    cvt_hi4_kernel<<<DM * DM / 4096, 256>>>(Wq, whi + 0 * DM * DM);
    cvt_hi4_kernel<<<DM * DM / 4096, 256>>>(Wk, whi + 1 * DM * DM);
    cvt_hi4_kernel<<<DM * DM / 4096, 256>>>(Wv, whi + 2 * DM * DM);
    cvt_split4_kernel<<<DM * DM / 4096, 256>>>(Wo, whi + 3 * DM * DM, wlo);
    maskcvt_kernel<<<MTOT / 1024, 256>>>(mask, maskf);

    gemm_qkv<<<dim3(24, MTOT / 128), 256, QKV_SMEM>>>(
        xd, whi, bq, bk, bv, qd, kd, vd);

    attn_mma<<<dim3(S_ / 128, B_ * NH), 256, ATTN_SMEM>>>(qd, kd, vd, maskf, ao);

    gemm_out<<<dim3(DM / 128, MTOT / 128), 256, OUT_SMEM>>>(
        ao, whi + 3 * DM * DM, wlo, bo, out);
}

// round 17
// speedup vs baseline: 9.4647x; 1.1150x over previous
#include <cuda_runtime.h>
#include <cuda_fp16.h>
#include <cstdint>
#include <math.h>

#define B_   4
#define S_   2048
#define DM   1024
#define NH   16
#define DK   64
#define MTOT (B_ * S_)   // 8192

#define LOG2E 1.4426950408889634f

typedef __half  f16;

// ---------------------------------------------------------------------------
// Scratch
// ---------------------------------------------------------------------------
__device__ f16 g_x[MTOT * DM];
__device__ f16 g_w[4][DM * DM];
__device__ f16 g_q[MTOT * DM];
__device__ f16 g_k[MTOT * DM];
__device__ f16 g_v[MTOT * DM];
__device__ f16 g_ao[MTOT * DM];
__device__ float g_maskf[MTOT];

// ---------------------------------------------------------------------------
// helpers
// ---------------------------------------------------------------------------
__device__ __forceinline__ uint32_t s2u(const void* p) {
    uint32_t a;
    asm("{ .reg .u64 t; cvta.to.shared.u64 t, %1; cvt.u32.u64 %0, t; }"
        : "=r"(a) : "l"(p));
    return a;
}

#define SWZ(x) ((x) ^ (((x) >> 3) & 0x70))

__device__ __forceinline__ void ldsm4(uint32_t* r, uint32_t addr) {
    asm volatile("ldmatrix.sync.aligned.m8n8.x4.shared.b16 {%0,%1,%2,%3}, [%4];"
        : "=r"(r[0]), "=r"(r[1]), "=r"(r[2]), "=r"(r[3]) : "r"(addr));
}
__device__ __forceinline__ void ldsm4t(uint32_t* r, uint32_t addr) {
    asm volatile("ldmatrix.sync.aligned.m8n8.x4.trans.shared.b16 {%0,%1,%2,%3}, [%4];"
        : "=r"(r[0]), "=r"(r[1]), "=r"(r[2]), "=r"(r[3]) : "r"(addr));
}
__device__ __forceinline__ void mma16816(float* c, const uint32_t* a, const uint32_t* b) {
    asm volatile(
        "mma.sync.aligned.m16n8k16.row.col.f32.f16.f16.f32 "
        "{%0,%1,%2,%3}, {%4,%5,%6,%7}, {%8,%9}, {%0,%1,%2,%3};"
        : "+f"(c[0]), "+f"(c[1]), "+f"(c[2]), "+f"(c[3])
        : "r"(a[0]), "r"(a[1]), "r"(a[2]), "r"(a[3]), "r"(b[0]), "r"(b[1]));
}

__device__ __forceinline__ uint32_t pack2h(float v0, float v1) {
    __half2 hv = __floats2half2_rn(v0, v1);
    return *(uint32_t*)&hv;
}

#define CP16(dst, src) \
    asm volatile("cp.async.cg.shared.global [%0], [%1], 16;" :: "r"(dst), "l"(src))
#define CP4(dst, src) \
    asm volatile("cp.async.ca.shared.global [%0], [%1], 4;" :: "r"(dst), "l"(src))
#define CP_COMMIT() asm volatile("cp.async.commit_group;")
#define CP_WAIT1()  asm volatile("cp.async.wait_group 1;")
#define CP_WAIT2()  asm volatile("cp.async.wait_group 2;")

// ---------------------------------------------------------------------------
// fp32 -> fp16, 4 independent float4 loads per thread (MLP=4).
// One block handles 4096 consecutive floats.
// ---------------------------------------------------------------------------
__global__ __launch_bounds__(256)
void cvt_hi4_kernel(const float* __restrict__ in, f16* __restrict__ hi)
{
    const int base = blockIdx.x * 4096 + threadIdx.x * 4;
    float4 v0 = *(const float4*)(in + base);
    float4 v1 = *(const float4*)(in + base + 1024);
    float4 v2 = *(const float4*)(in + base + 2048);
    float4 v3 = *(const float4*)(in + base + 3072);
    ((uint32_t*)(hi + base))[0] = pack2h(v0.x, v0.y);
    ((uint32_t*)(hi + base))[1] = pack2h(v0.z, v0.w);
    ((uint32_t*)(hi + base + 1024))[0] = pack2h(v1.x, v1.y);
    ((uint32_t*)(hi + base + 1024))[1] = pack2h(v1.z, v1.w);
    ((uint32_t*)(hi + base + 2048))[0] = pack2h(v2.x, v2.y);
    ((uint32_t*)(hi + base + 2048))[1] = pack2h(v2.z, v2.w);
    ((uint32_t*)(hi + base + 3072))[0] = pack2h(v3.x, v3.y);
    ((uint32_t*)(hi + base + 3072))[1] = pack2h(v3.z, v3.w);
}

// Fused 4-weight fp32 -> fp16 conversion. grid.x = 4 * 256; block 256.
// blockIdx.x >> 8 selects the weight; low bits select the 4096-elem slab.
__global__ __launch_bounds__(256)
void cvt_w4_kernel(const float* __restrict__ w0, const float* __restrict__ w1,
                   const float* __restrict__ w2, const float* __restrict__ w3,
                   f16* __restrict__ out)
{
    const int wsel = blockIdx.x >> 8;
    const int slab = blockIdx.x & 255;
    const float* in = (wsel == 0) ? w0 : (wsel == 1) ? w1 : (wsel == 2) ? w2 : w3;
    f16* hi = out + (size_t)wsel * DM * DM;
    const int base = slab * 4096 + threadIdx.x * 4;
    float4 v0 = *(const float4*)(in + base);
    float4 v1 = *(const float4*)(in + base + 1024);
    float4 v2 = *(const float4*)(in + base + 2048);
    float4 v3 = *(const float4*)(in + base + 3072);
    ((uint32_t*)(hi + base))[0] = pack2h(v0.x, v0.y);
    ((uint32_t*)(hi + base))[1] = pack2h(v0.z, v0.w);
    ((uint32_t*)(hi + base + 1024))[0] = pack2h(v1.x, v1.y);
    ((uint32_t*)(hi + base + 1024))[1] = pack2h(v1.z, v1.w);
    ((uint32_t*)(hi + base + 2048))[0] = pack2h(v2.x, v2.y);
    ((uint32_t*)(hi + base + 2048))[1] = pack2h(v2.z, v2.w);
    ((uint32_t*)(hi + base + 3072))[0] = pack2h(v3.x, v3.y);
    ((uint32_t*)(hi + base + 3072))[1] = pack2h(v3.z, v3.w);
}

// mask(int) -> float addend (0 or -1e9)
__global__ __launch_bounds__(256)
void maskcvt_kernel(const int* __restrict__ mask, float* __restrict__ mf)
{
    int i = (blockIdx.x * 256 + threadIdx.x) * 4;
    int4 m = *(const int4*)(mask + i);
    float4 v;
    v.x = m.x ? 0.f : -1e9f;
    v.y = m.y ? 0.f : -1e9f;
    v.z = m.z ? 0.f : -1e9f;
    v.w = m.w ? 0.f : -1e9f;
    *(float4*)(mf + i) = v;
}

// ---------------------------------------------------------------------------
// Single-pass fp16 GEMM core: C = A[128,K] x W[128,K]^T with fp32 accum.
// 3-stage cp.async, 2 tiles/stage (32KB), warp 64x32 (8 warps as 2x4).
// ---------------------------------------------------------------------------
static const int GEMM_SMEM = 3 * 2 * 16384;  // 96KB

// Fused QKV projection. grid (24, 64): blockIdx.x>>3 selects weight.
__global__ __launch_bounds__(256)
void gemm_qkv(const f16* __restrict__ A, const f16* __restrict__ Wbase,
              const float* __restrict__ bq, const float* __restrict__ bk,
              const float* __restrict__ bv,
              f16* __restrict__ Qd, f16* __restrict__ Kd, f16* __restrict__ Vd)
{
    extern __shared__ __align__(1024) char smem[];
    const int K = 1024;
    const int tid = threadIdx.x;
    const int wid = tid >> 5;
    const int lid = tid & 31;
    const int m0 = blockIdx.y * 128;
    const int wsel = blockIdx.x >> 3;            // 0=Q 1=K 2=V
    const int n0 = (blockIdx.x & 7) * 128;
    const int wm = wid & 1;
    const int wn = wid >> 1;

    const f16* W = Wbase + (size_t)wsel * DM * DM;
    const float* bias = (wsel == 0) ? bq : (wsel == 1) ? bk : bv;

    const uint32_t sb = s2u(smem);

    auto load_stage = [&](int kc, int buf) {
        const f16* srcs[2] = {A + (size_t)m0 * K + kc * 64,
                              W + (size_t)n0 * K + kc * 64};
        const uint32_t bufo = buf * 32768;
#pragma unroll
        for (int t = 0; t < 2; t++) {
#pragma unroll
            for (int it = 0; it < 4; it++) {
                const int idx = tid + it * 256;
                const int row = idx >> 3;
                const int u = idx & 7;
                const uint32_t dst = sb + bufo + t * 16384 + SWZ(idx * 16);
                CP16(dst, srcs[t] + (size_t)row * K + u * 8);
            }
        }
    };

    float acc[4][4][4];
#pragma unroll
    for (int a = 0; a < 4; a++)
#pragma unroll
        for (int b = 0; b < 4; b++)
#pragma unroll
            for (int c = 0; c < 4; c++) acc[a][b][c] = 0.f;

    load_stage(0, 0); CP_COMMIT();
    load_stage(1, 1); CP_COMMIT();
    load_stage(2, 2); CP_COMMIT();

    for (int kc = 0; kc < 16; kc++) {
        CP_WAIT2();
        __syncthreads();
        const int bi = kc % 3;
        const uint32_t bufo = sb + bi * 32768;

#pragma unroll
        for (int ks = 0; ks < 4; ks++) {
            uint32_t af[4][4];
#pragma unroll
            for (int mf = 0; mf < 4; mf++) {
                const int row = wm * 64 + mf * 16 + (lid & 15);
                const int u = ks * 2 + (lid >> 4);
                const uint32_t off = SWZ(row * 128 + u * 16);
                ldsm4(af[mf], bufo + off);
            }
#pragma unroll
            for (int nf2 = 0; nf2 < 2; nf2++) {
                const int row = wn * 32 + nf2 * 16 + ((lid >> 4) << 3) + (lid & 7);
                const int u = ks * 2 + ((lid >> 3) & 1);
                const uint32_t off = SWZ(row * 128 + u * 16);
                uint32_t bh[4];
                ldsm4(bh, bufo + 16384 + off);
#pragma unroll
                for (int mf = 0; mf < 4; mf++) {
                    mma16816(acc[mf][nf2 * 2],     af[mf], bh);
                    mma16816(acc[mf][nf2 * 2 + 1], af[mf], bh + 2);
                }
            }
        }
        __syncthreads();
        if (kc + 3 < 16) load_stage(kc + 3, bi);
        CP_COMMIT();
    }

    // epilogue: scatter single fp16 to (b,h,s,d)
    f16* Out = (wsel == 0) ? Qd : (wsel == 1) ? Kd : Vd;
#pragma unroll
    for (int mf = 0; mf < 4; mf++) {
#pragma unroll
        for (int nf = 0; nf < 4; nf++) {
            const int n = n0 + wn * 32 + nf * 8 + (lid & 3) * 2;
            const int r0 = m0 + wm * 64 + mf * 16 + (lid >> 2);
            const float b0 = bias[n], b1 = bias[n + 1];
            const int h = n >> 6, d = n & 63;
#pragma unroll
            for (int rr = 0; rr < 2; rr++) {
                const int r = r0 + rr * 8;
                const int b = r >> 11, s = r & (S_ - 1);
                const size_t idx = ((((size_t)b * NH + h) * S_ + s) * DK) + d;
                *(uint32_t*)(Out + idx) =
                    pack2h(acc[mf][nf][rr * 2] + b0, acc[mf][nf][rr * 2 + 1] + b1);
            }
        }
    }
}

// Output GEMM: AO x Wo (both single fp16), 1-pass, fp32 row-major out.
__global__ __launch_bounds__(256)
void gemm_out(const f16* __restrict__ A, const f16* __restrict__ W,
              const float* __restrict__ bias, float* __restrict__ Cf)
{
    extern __shared__ __align__(1024) char smem[];
    const int K = 1024;
    const int tid = threadIdx.x;
    const int wid = tid >> 5;
    const int lid = tid & 31;
    const int m0 = blockIdx.y * 128;
    const int n0 = blockIdx.x * 128;
    const int wm = wid & 1;
    const int wn = wid >> 1;

    const uint32_t sb = s2u(smem);

    auto load_stage = [&](int kc, int buf) {
        const f16* srcs[2] = {A + (size_t)m0 * K + kc * 64,
                              W + (size_t)n0 * K + kc * 64};
        const uint32_t bufo = buf * 32768;
#pragma unroll
        for (int t = 0; t < 2; t++) {
#pragma unroll
            for (int it = 0; it < 4; it++) {
                const int idx = tid + it * 256;
                const int row = idx >> 3;
                const int u = idx & 7;
                const uint32_t dst = sb + bufo + t * 16384 + SWZ(idx * 16);
                CP16(dst, srcs[t] + (size_t)row * K + u * 8);
            }
        }
    };

    float acc[4][4][4];
#pragma unroll
    for (int a = 0; a < 4; a++)
#pragma unroll
        for (int b = 0; b < 4; b++)
#pragma unroll
            for (int c = 0; c < 4; c++) acc[a][b][c] = 0.f;

    load_stage(0, 0); CP_COMMIT();
    load_stage(1, 1); CP_COMMIT();
    load_stage(2, 2); CP_COMMIT();

    for (int kc = 0; kc < 16; kc++) {
        CP_WAIT2();
        __syncthreads();
        const int bi = kc % 3;
        const uint32_t bufo = sb + bi * 32768;

#pragma unroll
        for (int ks = 0; ks < 4; ks++) {
            uint32_t af[4][4];
#pragma unroll
            for (int mf = 0; mf < 4; mf++) {
                const int row = wm * 64 + mf * 16 + (lid & 15);
                const int u = ks * 2 + (lid >> 4);
                const uint32_t off = SWZ(row * 128 + u * 16);
                ldsm4(af[mf], bufo + off);
            }
#pragma unroll
            for (int nf2 = 0; nf2 < 2; nf2++) {
                const int row = wn * 32 + nf2 * 16 + ((lid >> 4) << 3) + (lid & 7);
                const int u = ks * 2 + ((lid >> 3) & 1);
                const uint32_t off = SWZ(row * 128 + u * 16);
                uint32_t bh[4];
                ldsm4(bh, bufo + 16384 + off);
#pragma unroll
                for (int mf = 0; mf < 4; mf++) {
                    mma16816(acc[mf][nf2 * 2],     af[mf], bh);
                    mma16816(acc[mf][nf2 * 2 + 1], af[mf], bh + 2);
                }
            }
        }
        __syncthreads();
        if (kc + 3 < 16) load_stage(kc + 3, bi);
        CP_COMMIT();
    }

#pragma unroll
    for (int mf = 0; mf < 4; mf++) {
#pragma unroll
        for (int nf = 0; nf < 4; nf++) {
            const int n = n0 + wn * 32 + nf * 8 + (lid & 3) * 2;
            const int r0 = m0 + wm * 64 + mf * 16 + (lid >> 2);
            const int r1 = r0 + 8;
            const float b0 = bias[n], b1 = bias[n + 1];
            *(float2*)(Cf + (size_t)r0 * 1024 + n) =
                make_float2(acc[mf][nf][0] + b0, acc[mf][nf][1] + b1);
            *(float2*)(Cf + (size_t)r1 * 1024 + n) =
                make_float2(acc[mf][nf][2] + b0, acc[mf][nf][3] + b1);
        }
    }
}

// ---------------------------------------------------------------------------
// Flash attention, fp16 mma. Single-fp16 Q/K/V/P: 1-pass QK, 1-pass PV.
// cp.async double-buffered, log2 softmax, float mask addend, rescale skip.
// AO written as single fp16.
// ---------------------------------------------------------------------------
static const int ATTN_BUF  = 33280;
static const int ATTN_SMEM = 2 * ATTN_BUF;

__global__ __launch_bounds__(256)
void attn_mma(const f16* __restrict__ Qg,
              const f16* __restrict__ Kg,  const f16* __restrict__ Vg,
              const float* __restrict__ maskf,
              f16* __restrict__ AO)
{
    extern __shared__ __align__(1024) char smem[];
    const uint32_t sb = s2u(smem);

    const int tid = threadIdx.x;
    const int wid = tid >> 5;
    const int lid = tid & 31;
    const int bh = blockIdx.y;
    const int b = bh >> 4, h = bh & 15;
    const int q0 = blockIdx.x * 128 + wid * 16;

    const size_t bho = (size_t)bh * S_ * DK;

    auto load_chunk = [&](int ch, int buf) {
        const uint32_t bo = sb + buf * ATTN_BUF;
        const char* kh = (const char*)(Kg + bho + (size_t)ch * 128 * DK);
        const char* vh = (const char*)(Vg + bho + (size_t)ch * 128 * DK);
#pragma unroll
        for (int it = 0; it < 4; it++) {
            const int idx = tid + it * 256;
            const uint32_t sw = SWZ(idx * 16);
            CP16(bo + sw,         kh + idx * 16);
            CP16(bo + 16384 + sw, vh + idx * 16);
        }
        if (tid < 128)
            CP4(bo + 32768 + tid * 4, maskf + b * S_ + ch * 128 + tid);
    };

    // Q fragments (pre-scaled by 0.125 via f16x2 multiply: exact)
    uint32_t qh[4][4];
    const uint32_t eighth = 0x30003000u;  // fp16 0.125 x2
#pragma unroll
    for (int ks = 0; ks < 4; ks++) {
        const int c2 = ks * 16 + (lid & 3) * 2;
        const int r0 = q0 + (lid >> 2), r1 = r0 + 8;
        const uint32_t* qp = (const uint32_t*)(Qg + bho);
        uint32_t a0 = qp[(r0 * DK + c2) >> 1];
        uint32_t a1 = qp[(r1 * DK + c2) >> 1];
        uint32_t a2 = qp[(r0 * DK + c2 + 8) >> 1];
        uint32_t a3 = qp[(r1 * DK + c2 + 8) >> 1];
        asm("mul.rn.f16x2 %0, %1, %2;" : "=r"(qh[ks][0]) : "r"(a0), "r"(eighth));
        asm("mul.rn.f16x2 %0, %1, %2;" : "=r"(qh[ks][1]) : "r"(a1), "r"(eighth));
        asm("mul.rn.f16x2 %0, %1, %2;" : "=r"(qh[ks][2]) : "r"(a2), "r"(eighth));
        asm("mul.rn.f16x2 %0, %1, %2;" : "=r"(qh[ks][3]) : "r"(a3), "r"(eighth));
    }

    float o[8][4];
#pragma unroll
    for (int j = 0; j < 8; j++)
#pragma unroll
        for (int c = 0; c < 4; c++) o[j][c] = 0.f;
    float mA = -1e30f, mB = -1e30f, lA = 0.f, lB = 0.f;

    load_chunk(0, 0); CP_COMMIT();
    load_chunk(1, 1); CP_COMMIT();

    for (int ch = 0; ch < 16; ch++) {
        CP_WAIT1();
        __syncthreads();
        const int bi = ch & 1;
        const uint32_t sK  = sb + bi * ATTN_BUF;
        const uint32_t sV  = sK + 16384;
        const float* mskf = (const float*)(smem + bi * ATTN_BUF + 32768);

#pragma unroll
        for (int sub = 0; sub < 2; sub++) {
            float sc[8][4];
#pragma unroll
            for (int nf = 0; nf < 8; nf++)
#pragma unroll
                for (int c = 0; c < 4; c++) sc[nf][c] = 0.f;

            // scores: Q (16xk64) . K^T  (single pass)
#pragma unroll
            for (int nf2 = 0; nf2 < 4; nf2++) {
                const int row = sub * 64 + nf2 * 16 + ((lid >> 4) << 3) + (lid & 7);
#pragma unroll
                for (int ks = 0; ks < 4; ks++) {
                    const int u = ks * 2 + ((lid >> 3) & 1);
                    const uint32_t off = SWZ(row * 128 + u * 16);
                    uint32_t kb[4];
                    ldsm4(kb, sK + off);
                    mma16816(sc[nf2 * 2],     qh[ks], kb);
                    mma16816(sc[nf2 * 2 + 1], qh[ks], kb + 2);
                }
            }

            // mask + convert to log2 domain
#pragma unroll
            for (int nf = 0; nf < 8; nf++) {
                const int k0 = sub * 64 + nf * 8 + (lid & 3) * 2;
                const float ma0 = mskf[k0], ma1 = mskf[k0 + 1];
                sc[nf][0] = fmaf(sc[nf][0], LOG2E, ma0);
                sc[nf][1] = fmaf(sc[nf][1], LOG2E, ma1);
                sc[nf][2] = fmaf(sc[nf][2], LOG2E, ma0);
                sc[nf][3] = fmaf(sc[nf][3], LOG2E, ma1);
            }

            // online softmax (log2 domain)
            float mxA = -1e30f, mxB = -1e30f;
#pragma unroll
            for (int nf = 0; nf < 8; nf++) {
                mxA = fmaxf(mxA, fmaxf(sc[nf][0], sc[nf][1]));
                mxB = fmaxf(mxB, fmaxf(sc[nf][2], sc[nf][3]));
            }
            mxA = fmaxf(mxA, __shfl_xor_sync(0xffffffffu, mxA, 1));
            mxA = fmaxf(mxA, __shfl_xor_sync(0xffffffffu, mxA, 2));
            mxB = fmaxf(mxB, __shfl_xor_sync(0xffffffffu, mxB, 1));
            mxB = fmaxf(mxB, __shfl_xor_sync(0xffffffffu, mxB, 2));
            const float mAn = fmaxf(mA, mxA), mBn = fmaxf(mB, mxB);
            if (!__all_sync(0xffffffffu, (mAn == mA) && (mBn == mB))) {
                const float fA = exp2f(mA - mAn), fB = exp2f(mB - mBn);
                lA *= fA; lB *= fB;
#pragma unroll
                for (int j = 0; j < 8; j++) {
                    o[j][0] *= fA; o[j][1] *= fA;
                    o[j][2] *= fB; o[j][3] *= fB;
                }
            }
            mA = mAn; mB = mBn;
#pragma unroll
            for (int nf = 0; nf < 8; nf++) {
                sc[nf][0] = exp2f(sc[nf][0] - mA);
                sc[nf][1] = exp2f(sc[nf][1] - mA);
                sc[nf][2] = exp2f(sc[nf][2] - mB);
                sc[nf][3] = exp2f(sc[nf][3] - mB);
                lA += sc[nf][0] + sc[nf][1];
                lB += sc[nf][2] + sc[nf][3];
            }

            // P·V (P packed single-fp16; single pass)
#pragma unroll
            for (int kk = 0; kk < 4; kk++) {
                uint32_t ph[4];
                ph[0] = pack2h(sc[2 * kk][0],     sc[2 * kk][1]);
                ph[1] = pack2h(sc[2 * kk][2],     sc[2 * kk][3]);
                ph[2] = pack2h(sc[2 * kk + 1][0], sc[2 * kk + 1][1]);
                ph[3] = pack2h(sc[2 * kk + 1][2], sc[2 * kk + 1][3]);
                const int row = sub * 64 + kk * 16 + (((lid >> 3) & 1) << 3) + (lid & 7);
#pragma unroll
                for (int j2 = 0; j2 < 4; j2++) {
                    const int u = 2 * j2 + (lid >> 4);
                    const uint32_t off = SWZ(row * 128 + u * 16);
                    uint32_t vb[4];
                    ldsm4t(vb, sV + off);
                    mma16816(o[j2 * 2],     ph, vb);
                    mma16816(o[j2 * 2 + 1], ph, vb + 2);
                }
            }
        }

        __syncthreads();
        if (ch + 2 < 16) load_chunk(ch + 2, bi);
        CP_COMMIT();
    }

    // final row sums and store (single fp16 AO)
    lA += __shfl_xor_sync(0xffffffffu, lA, 1);
    lA += __shfl_xor_sync(0xffffffffu, lA, 2);
    lB += __shfl_xor_sync(0xffffffffu, lB, 1);
    lB += __shfl_xor_sync(0xffffffffu, lB, 2);
    const float invA = 1.f / lA, invB = 1.f / lB;

    const int s0 = q0 + (lid >> 2), s1 = s0 + 8;
#pragma unroll
    for (int j = 0; j < 8; j++) {
        const int col = h * DK + j * 8 + (lid & 3) * 2;
        const size_t i0 = ((size_t)(b * S_ + s0)) * DM + col;
        const size_t i1 = ((size_t)(b * S_ + s1)) * DM + col;
        *(uint32_t*)(AO + i0) = pack2h(o[j][0] * invA, o[j][1] * invA);
        *(uint32_t*)(AO + i1) = pack2h(o[j][2] * invB, o[j][3] * invB);
    }
}

// ---------------------------------------------------------------------------
// Launch
// ---------------------------------------------------------------------------
extern "C" void kernel_launch(void* const* d_in, const int* in_sizes, int n_in,
                              void* d_out, int out_size)
{
    (void)in_sizes; (void)n_in; (void)out_size;
    const float* x    = (const float*)d_in[0];
    const int*   mask = (const int*)  d_in[1];
    const float* Wq   = (const float*)d_in[2];
    const float* bq   = (const float*)d_in[3];
    const float* Wk   = (const float*)d_in[4];
    const float* bk   = (const float*)d_in[5];
    const float* Wv   = (const float*)d_in[6];
    const float* bv   = (const float*)d_in[7];
    const float* Wo   = (const float*)d_in[8];
    const float* bo   = (const float*)d_in[9];
    float* out = (float*)d_out;

    f16 *xd, *wd, *qd, *kd, *vd, *ao;
    float* maskf;
    cudaGetSymbolAddress((void**)&xd,    g_x);
    cudaGetSymbolAddress((void**)&wd,    g_w);
    cudaGetSymbolAddress((void**)&qd,    g_q);
    cudaGetSymbolAddress((void**)&kd,    g_k);
    cudaGetSymbolAddress((void**)&vd,    g_v);
    cudaGetSymbolAddress((void**)&ao,    g_ao);
    cudaGetSymbolAddress((void**)&maskf, g_maskf);

    cudaFuncSetAttribute(gemm_qkv, cudaFuncAttributeMaxDynamicSharedMemorySize, GEMM_SMEM);
    cudaFuncSetAttribute(gemm_out, cudaFuncAttributeMaxDynamicSharedMemorySize, GEMM_SMEM);
    cudaFuncSetAttribute(attn_mma, cudaFuncAttributeMaxDynamicSharedMemorySize, ATTN_SMEM);

    cvt_hi4_kernel<<<MTOT * DM / 4096, 256>>>(x, xd);
    cvt_w4_kernel<<<4 * DM * DM / 4096, 256>>>(Wq, Wk, Wv, Wo, wd);
    maskcvt_kernel<<<MTOT / 1024, 256>>>(mask, maskf);

    gemm_qkv<<<dim3(24, MTOT / 128), 256, GEMM_SMEM>>>(
        xd, wd, bq, bk, bv, qd, kd, vd);

    attn_mma<<<dim3(S_ / 128, B_ * NH), 256, ATTN_SMEM>>>(qd, kd, vd, maskf, ao);

    gemm_out<<<dim3(DM / 128, MTOT / 128), 256, GEMM_SMEM>>>(
        ao, wd + 3 * (size_t)DM * DM, bo, out);
}